// round 6
// baseline (speedup 1.0000x reference)
#include <cuda_runtime.h>
#include <math.h>

typedef unsigned long long ull;
#define HW 65536
#define NCHUNK 64

// pool: 2*SZ2 + 6*SZ + 16384 + 294912 + 147456
__device__ float g_pool[168230912];

__device__ __forceinline__ float gelu_f(float v) {
    return 0.5f * v * (1.0f + erff(v * 0.70710678118654752f));
}
__device__ __forceinline__ ull pack2(float lo, float hi) {
    ull d; asm("mov.b64 %0,{%1,%2};" : "=l"(d) : "f"(lo), "f"(hi)); return d;
}
__device__ __forceinline__ void unpack2(ull v, float& lo, float& hi) {
    asm("mov.b64 {%0,%1},%2;" : "=f"(lo), "=f"(hi) : "l"(v));
}
__device__ __forceinline__ ull ffma2(ull a, ull b, ull c) {
    ull d; asm("fma.rn.f32x2 %0,%1,%2,%3;" : "=l"(d) : "l"(a), "l"(b), "l"(c)); return d;
}
__device__ __forceinline__ unsigned smaddr(const void* p) {
    unsigned a;
    asm("{.reg .u64 t; cvta.to.shared.u64 t, %1; cvt.u32.u64 %0, t;}" : "=r"(a) : "l"(p));
    return a;
}
__device__ __forceinline__ void cpa4(unsigned s, const void* g, bool pred) {
    int sz = pred ? 4 : 0;
    asm volatile("cp.async.ca.shared.global [%0], [%1], 4, %2;" :: "r"(s), "l"(g), "r"(sz));
}
__device__ __forceinline__ void cpa16(unsigned s, const void* g) {
    asm volatile("cp.async.cg.shared.global [%0], [%1], 16;" :: "r"(s), "l"(g));
}
__device__ __forceinline__ void cpa_commit() { asm volatile("cp.async.commit_group;"); }
__device__ __forceinline__ void cpa_wait1() { asm volatile("cp.async.wait_group 1;"); }
__device__ __forceinline__ void cpa_wait0() { asm volatile("cp.async.wait_group 0;"); }

// ---------------- weight transpose: [oc][ic][9] -> [(ic*9+t)*64+oc] ----------------
__global__ void wtrans_kernel(const float* __restrict__ w, float* __restrict__ wT)
{
    int o = blockIdx.x * 256 + threadIdx.x;   // 0..36863
    int oc = o & 63;
    int s = o >> 6;
    int t = s % 9;
    int ic = s / 9;
    wT[o] = w[(oc * 64 + ic) * 9 + t];
}

// ---------------- LayerNorm over channel dim (per pixel) ----------------
__global__ void ln_kernel(const float* __restrict__ in, const float* __restrict__ w,
                          const float* __restrict__ bb, float* __restrict__ out)
{
    int p = blockIdx.x * blockDim.x + threadIdx.x;
    int b = p >> 16;
    int pix = p & 65535;
    const float* ip = in + (long)b * (64 * HW) + pix;
    float s = 0.f, ss = 0.f;
#pragma unroll 8
    for (int c = 0; c < 64; ++c) {
        float v = ip[(long)c * HW];
        s += v; ss += v * v;
    }
    float mu = s * (1.0f / 64);
    float var = ss * (1.0f / 64) - mu * mu;
    float r = rsqrtf(var + 1e-5f);
    float* op = out + (long)b * (64 * HW) + pix;
#pragma unroll 8
    for (int c = 0; c < 64; ++c) {
        float v = ip[(long)c * HW];
        op[(long)c * HW] = (v - mu) * r * w[c] + bb[c];
    }
}

// ---------------- 1x1 conv (optionally with fused channel-LN on input) ----------------
template<int OC, bool LNORM, bool PBW, bool RES>
__global__ void conv1x1_kernel(const float* __restrict__ in, const float* __restrict__ w,
                               const float* __restrict__ lnw, const float* __restrict__ lnb,
                               const float* __restrict__ res, float* __restrict__ out,
                               int in_bstride, int ic_off)
{
    constexpr int OCG = OC / 8;
    constexpr int PG  = 128 / OCG;
    constexpr int PXT = PG * 8;
    __shared__ float sW[64 * OC];
    __shared__ float sIn[64 * PXT];
    int b = blockIdx.y;
    int pix0 = blockIdx.x * PXT;
    int tid = threadIdx.x;
    const float* wb = PBW ? (w + b * 64 * OC) : w;
    for (int idx = tid; idx < 64 * OC; idx += 128) {
        int oc = idx % OC, ic = idx / OC;
        sW[idx] = wb[oc * 64 + ic];
    }
    const float* inb = in + (long)b * in_bstride + (long)ic_off * HW + pix0;
    for (int idx = tid; idx < 64 * PXT; idx += 128) {
        int px = idx % PXT, ic = idx / PXT;
        sIn[idx] = inb[(long)ic * HW + px];
    }
    __syncthreads();
    if (LNORM) {
        if (tid < PXT) {
            float s = 0.f, ss = 0.f;
#pragma unroll 8
            for (int c = 0; c < 64; ++c) {
                float v = sIn[c * PXT + tid];
                s += v; ss += v * v;
            }
            float mu = s * (1.0f / 64);
            float var = ss * (1.0f / 64) - mu * mu;
            float r = rsqrtf(var + 1e-5f);
#pragma unroll 8
            for (int c = 0; c < 64; ++c) {
                sIn[c * PXT + tid] = (sIn[c * PXT + tid] - mu) * r * lnw[c] + lnb[c];
            }
        }
        __syncthreads();
    }
    int og = tid % OCG, pg = tid / OCG;
    int oc0 = og * 8, px0 = pg * 8;
    ull acc[8][4];
#pragma unroll
    for (int j = 0; j < 8; ++j)
#pragma unroll
        for (int k = 0; k < 4; ++k) acc[j][k] = 0ull;
#pragma unroll 2
    for (int ic = 0; ic < 64; ++ic) {
        const float4* wv4 = (const float4*)&sW[ic * OC + oc0];
        float4 wa = wv4[0], wbb = wv4[1];
        ull wp[8];
        wp[0] = pack2(wa.x, wa.x); wp[1] = pack2(wa.y, wa.y);
        wp[2] = pack2(wa.z, wa.z); wp[3] = pack2(wa.w, wa.w);
        wp[4] = pack2(wbb.x, wbb.x); wp[5] = pack2(wbb.y, wbb.y);
        wp[6] = pack2(wbb.z, wbb.z); wp[7] = pack2(wbb.w, wbb.w);
        const ull* xv = (const ull*)&sIn[ic * PXT + px0];
        ull x0 = xv[0], x1 = xv[1], x2 = xv[2], x3 = xv[3];
#pragma unroll
        for (int j = 0; j < 8; ++j) {
            acc[j][0] = ffma2(wp[j], x0, acc[j][0]);
            acc[j][1] = ffma2(wp[j], x1, acc[j][1]);
            acc[j][2] = ffma2(wp[j], x2, acc[j][2]);
            acc[j][3] = ffma2(wp[j], x3, acc[j][3]);
        }
    }
#pragma unroll
    for (int j = 0; j < 8; ++j) {
        long o = (long)(b * OC + oc0 + j) * HW + pix0 + px0;
        float v[8];
#pragma unroll
        for (int k = 0; k < 4; ++k) unpack2(acc[j][k], v[2 * k], v[2 * k + 1]);
        float4 a0 = make_float4(v[0], v[1], v[2], v[3]);
        float4 a1 = make_float4(v[4], v[5], v[6], v[7]);
        if (RES) {
            float4 r0 = *(const float4*)&res[o];
            float4 r1 = *(const float4*)&res[o + 4];
            a0.x += r0.x; a0.y += r0.y; a0.z += r0.z; a0.w += r0.w;
            a1.x += r1.x; a1.y += r1.y; a1.z += r1.z; a1.w += r1.w;
        }
        *(float4*)&out[o] = a0;
        *(float4*)&out[o + 4] = a1;
    }
}

// ---------------- depthwise 3x3 v2: 8 px per thread, vector fast path ----------------
template<int CH>
__global__ void dw3x3_kernel(const float* __restrict__ in, const float* __restrict__ w,
                             float* __restrict__ out)
{
    int p = blockIdx.x * 256 + threadIdx.x;
    int xg = p & 31;
    int y = (p >> 5) & 255;
    int g = p >> 13;              // b*CH + c
    int c = g & (CH - 1);
    int x0 = xg * 8;
    const float* wp = w + c * 9;
    float wr[9];
#pragma unroll
    for (int t = 0; t < 9; ++t) wr[t] = wp[t];
    const float* ip = in + (long)g * HW;
    float r[3][10];
    bool interior = (y > 0) && (y < 255) && (xg > 0) && (xg < 31);
    if (interior) {
#pragma unroll
        for (int rr = 0; rr < 3; ++rr) {
            const float* base = ip + (y - 1 + rr) * 256 + x0;
            float4 a = *(const float4*)base;
            float4 bq = *(const float4*)(base + 4);
            r[rr][0] = base[-1];
            r[rr][1] = a.x; r[rr][2] = a.y; r[rr][3] = a.z; r[rr][4] = a.w;
            r[rr][5] = bq.x; r[rr][6] = bq.y; r[rr][7] = bq.z; r[rr][8] = bq.w;
            r[rr][9] = base[8];
        }
    } else {
#pragma unroll
        for (int rr = 0; rr < 3; ++rr) {
            int iy = y - 1 + rr;
#pragma unroll
            for (int j = 0; j < 10; ++j) {
                int ix = x0 - 1 + j;
                r[rr][j] = (iy >= 0 && iy < 256 && ix >= 0 && ix < 256) ? ip[iy * 256 + ix] : 0.f;
            }
        }
    }
    float acc[8];
#pragma unroll
    for (int q = 0; q < 8; ++q) acc[q] = 0.f;
#pragma unroll
    for (int ky = 0; ky < 3; ++ky)
#pragma unroll
        for (int kx = 0; kx < 3; ++kx) {
            float wv = wr[ky * 3 + kx];
#pragma unroll
            for (int q = 0; q < 8; ++q) acc[q] += wv * r[ky][q + kx];
        }
    float* op = out + (long)g * HW + y * 256 + x0;
    *(float4*)op = make_float4(acc[0], acc[1], acc[2], acc[3]);
    *(float4*)(op + 4) = make_float4(acc[4], acc[5], acc[6], acc[7]);
}

// ---------------- attention stats ----------------
__global__ void attn_stats_kernel(const float* __restrict__ q, const float* __restrict__ k,
                                  float* __restrict__ part)
{
    __shared__ float sQ[16 * 129];
    __shared__ float sK[16 * 129];
    int g = blockIdx.y;
    int b = g >> 2, h = g & 3;
    const float* qb = q + (long)b * 64 * HW + (long)h * 16 * HW;
    const float* kb = k + (long)b * 128 * HW + (long)h * 16 * HW;
    int tid = threadIdx.x;
    int c = tid >> 4, d = tid & 15;
    float accG = 0.f, accQ = 0.f, accK = 0.f;
    int nbase = blockIdx.x * (HW / NCHUNK);
    for (int sub = 0; sub < (HW / NCHUNK) / 128; ++sub) {
        int n0 = nbase + sub * 128;
#pragma unroll
        for (int i = 0; i < 8; ++i) {
            int lin = tid + i * 256;
            int cc = lin >> 7, nn = lin & 127;
            sQ[cc * 129 + nn] = qb[(long)cc * HW + n0 + nn];
            sK[cc * 129 + nn] = kb[(long)cc * HW + n0 + nn];
        }
        __syncthreads();
        const float* qr = sQ + c * 129;
        const float* kr = sK + d * 129;
#pragma unroll 8
        for (int nn = 0; nn < 128; ++nn) accG += qr[nn] * kr[nn];
        if (d == 0) {
#pragma unroll 8
            for (int nn = 0; nn < 128; ++nn) accQ += qr[nn] * qr[nn];
        }
        if (c == 0) {
#pragma unroll 8
            for (int nn = 0; nn < 128; ++nn) accK += kr[nn] * kr[nn];
        }
        __syncthreads();
    }
    float* pp = part + ((long)g * NCHUNK + blockIdx.x) * 288;
    pp[tid] = accG;
    if (d == 0) pp[256 + c] = accQ;
    if (c == 0) pp[272 + d] = accK;
}

// ---------------- finish: softmax + fold W_proj -> M[b][64][64] ----------------
__global__ void attn_finish_kernel(const float* __restrict__ part, const float* __restrict__ wproj,
                                   const float* __restrict__ temp, float* __restrict__ Mout)
{
    int b = blockIdx.x, tid = threadIdx.x;
    __shared__ float sG[4][256];
    __shared__ float sq[4][16], sk[4][16];
    __shared__ float sA[4][16][16];
    for (int h = 0; h < 4; ++h) {
        const float* pp = part + ((long)(b * 4 + h)) * NCHUNK * 288;
        float s = 0.f;
        for (int ch = 0; ch < NCHUNK; ++ch) s += pp[ch * 288 + tid];
        sG[h][tid] = s;
        if (tid < 32) {
            float s2 = 0.f;
            for (int ch = 0; ch < NCHUNK; ++ch) s2 += pp[ch * 288 + 256 + tid];
            if (tid < 16) sq[h][tid] = s2; else sk[h][tid - 16] = s2;
        }
    }
    __syncthreads();
    if (tid < 64) {
        int h = tid >> 4, c = tid & 15;
        float qn = fmaxf(sqrtf(sq[h][c]), 1e-12f);
        float tp = temp[h];
        float lg[16];
        float mx = -1e30f;
#pragma unroll
        for (int d = 0; d < 16; ++d) {
            float kn = fmaxf(sqrtf(sk[h][d]), 1e-12f);
            lg[d] = tp * sG[h][c * 16 + d] / (qn * kn);
            mx = fmaxf(mx, lg[d]);
        }
        float ssum = 0.f;
#pragma unroll
        for (int d = 0; d < 16; ++d) { lg[d] = expf(lg[d] - mx); ssum += lg[d]; }
        float inv = 1.f / ssum;
#pragma unroll
        for (int d = 0; d < 16; ++d) sA[h][c][d] = lg[d] * inv;
    }
    __syncthreads();
    for (int e = tid; e < 4096; e += 256) {
        int oc = e >> 6, j = e & 63, h = j >> 4, d = j & 15;
        float s = 0.f;
#pragma unroll
        for (int r = 0; r < 16; ++r) s += wproj[oc * 64 + h * 16 + r] * sA[h][r][d];
        Mout[b * 4096 + e] = s;
    }
}

// ---------------- dense 3x3 conv v2: oc-paired f32x2, cp.async double-buffered ----------------
// Block: 256 thr, output 64 oc x (4 rows x 64 cols). Thread: 8 oc x 8 px.
// Weights pre-transposed to [(ic*9+t)*64 + oc].
// EPI: 0 none, 1 gelu, 2 mix out=aux1*sigmoid(acc)+aux2, 3 acc+aux1
template<int EPI>
__global__ void __launch_bounds__(256, 2)
conv3x3_kernel(const float* __restrict__ in, const float* __restrict__ wT,
               const float* __restrict__ aux1, const float* __restrict__ aux2,
               float* __restrict__ out)
{
    __shared__ float sx[2][4][6][68];
    __shared__ float4 sw4[2][576];      // [ic_l][tap][oc] as float4

    int tid = threadIdx.x;
    int bx = blockIdx.x;
    int b = blockIdx.y;
    int tx = bx & 3, ty = bx >> 2;
    int x0 = tx * 64, y0 = ty * 4;
    int ocg = tid >> 5;
    int pxg = tid & 31;
    int row = pxg >> 3;
    int colg = pxg & 7;
    int oc0 = ocg * 8;

    const float* inb = in + (long)b * (64 * HW);

    // ---- staging lambda-ish (macro by hand) ----
    // input chunk icb covers ic = icb*4 .. +3
#define STAGE(ICB, BUF) do { \
        int icBase = (ICB) * 4; \
        for (int idx = tid; idx < 1632; idx += 256) { \
            int ic_l = idx / 408; \
            int rem = idx - ic_l * 408; \
            int ry = rem / 68; \
            int cx = rem - ry * 68; \
            int gy = y0 - 1 + ry; \
            int gx = x0 - 2 + cx; \
            bool ok = (gy >= 0) && (gy < 256) && (gx >= 0) && (gx < 256); \
            const float* gsrc = ok ? (inb + (long)(icBase + ic_l) * HW + gy * 256 + gx) : inb; \
            cpa4(smaddr(&sx[BUF][ic_l][ry][cx]), gsrc, ok); \
        } \
        const float4* wsrc = (const float4*)(wT + (long)icBase * 576); \
        for (int idx = tid; idx < 576; idx += 256) { \
            cpa16(smaddr(&sw4[BUF][idx]), wsrc + idx); \
        } \
    } while (0)

    ull acc[4][8];
#pragma unroll
    for (int j = 0; j < 4; ++j)
#pragma unroll
        for (int p2 = 0; p2 < 8; ++p2) acc[j][p2] = 0ull;

    STAGE(0, 0);
    cpa_commit();

    for (int icb = 0; icb < 16; ++icb) {
        int buf = icb & 1;
        if (icb < 15) {
            STAGE(icb + 1, (icb + 1) & 1);
            cpa_commit();
            cpa_wait1();
        } else {
            cpa_wait0();
        }
        __syncthreads();
        const float* swf = (const float*)sw4[buf];
#pragma unroll
        for (int ic_l = 0; ic_l < 4; ++ic_l) {
#pragma unroll
            for (int ky = 0; ky < 3; ++ky) {
                const float* xs = &sx[buf][ic_l][row + ky][colg * 8 + 1];
                ull xp[10];
#pragma unroll
                for (int j = 0; j < 10; ++j) {
                    float xv = xs[j];
                    xp[j] = pack2(xv, xv);
                }
#pragma unroll
                for (int kx = 0; kx < 3; ++kx) {
                    const ull* wp = (const ull*)&swf[(ic_l * 9 + ky * 3 + kx) * 64 + oc0];
                    ull w0 = wp[0], w1 = wp[1], w2 = wp[2], w3 = wp[3];
#pragma unroll
                    for (int p2 = 0; p2 < 8; ++p2) {
                        ull xv = xp[p2 + kx];
                        acc[0][p2] = ffma2(w0, xv, acc[0][p2]);
                        acc[1][p2] = ffma2(w1, xv, acc[1][p2]);
                        acc[2][p2] = ffma2(w2, xv, acc[2][p2]);
                        acc[3][p2] = ffma2(w3, xv, acc[3][p2]);
                    }
                }
            }
        }
        __syncthreads();
    }
#undef STAGE

    // ---- epilogue ----
    float v[8][8];
#pragma unroll
    for (int j = 0; j < 4; ++j)
#pragma unroll
        for (int p2 = 0; p2 < 8; ++p2)
            unpack2(acc[j][p2], v[2 * j][p2], v[2 * j + 1][p2]);

    long base = (long)(b * 64 + oc0) * HW + (y0 + row) * 256 + x0 + colg * 8;
#pragma unroll
    for (int ol = 0; ol < 8; ++ol) {
        long o = base + (long)ol * HW;
        float* vv = v[ol];
        if (EPI == 1) {
#pragma unroll
            for (int k = 0; k < 8; ++k) vv[k] = gelu_f(vv[k]);
        } else if (EPI == 2) {
            float4 y0v = *(const float4*)&aux1[o];
            float4 y1v = *(const float4*)&aux1[o + 4];
            float4 a0v = *(const float4*)&aux2[o];
            float4 a1v = *(const float4*)&aux2[o + 4];
            float ya[8] = {y0v.x, y0v.y, y0v.z, y0v.w, y1v.x, y1v.y, y1v.z, y1v.w};
            float aa[8] = {a0v.x, a0v.y, a0v.z, a0v.w, a1v.x, a1v.y, a1v.z, a1v.w};
#pragma unroll
            for (int k = 0; k < 8; ++k) {
                float s = 1.f / (1.f + expf(-vv[k]));
                vv[k] = ya[k] * s + aa[k];
            }
        } else if (EPI == 3) {
            float4 r0 = *(const float4*)&aux1[o];
            float4 r1 = *(const float4*)&aux1[o + 4];
            vv[0] += r0.x; vv[1] += r0.y; vv[2] += r0.z; vv[3] += r0.w;
            vv[4] += r1.x; vv[5] += r1.y; vv[6] += r1.z; vv[7] += r1.w;
        }
        *(float4*)&out[o] = make_float4(vv[0], vv[1], vv[2], vv[3]);
        *(float4*)&out[o + 4] = make_float4(vv[4], vv[5], vv[6], vv[7]);
    }
}

extern "C" void kernel_launch(void* const* d_in, const int* in_sizes, int n_in,
                              void* d_out, int out_size)
{
    const float* x       = (const float*)d_in[0];
    const float* ref     = (const float*)d_in[1];
    const float* ln1w    = (const float*)d_in[2];
    const float* ln1b    = (const float*)d_in[3];
    const float* ln2w    = (const float*)d_in[4];
    const float* ln2b    = (const float*)d_in[5];
    const float* ln3w    = (const float*)d_in[6];
    const float* ln3b    = (const float*)d_in[7];
    const float* w_kv    = (const float*)d_in[8];
    const float* w_kv_dw = (const float*)d_in[9];
    const float* w_q     = (const float*)d_in[10];
    const float* w_q_dw  = (const float*)d_in[11];
    const float* w_proj  = (const float*)d_in[12];
    const float* temp    = (const float*)d_in[13];
    const float* w_add1  = (const float*)d_in[14];
    const float* w_add2  = (const float*)d_in[15];
    const float* w_mul1  = (const float*)d_in[16];
    const float* w_fuse  = (const float*)d_in[17];
    float* out = (float*)d_out;

    float* pool = nullptr;
    cudaGetSymbolAddress((void**)&pool, g_pool);
    const long SZ = 16777216L, SZ2 = 33554432L;
    float* kv0  = pool;
    float* kv1  = pool + SZ2;
    float* bufA = pool + 2 * SZ2;
    float* bufB = bufA + SZ;
    float* bufC = bufB + SZ;
    float* bufD = bufC + SZ;
    float* bufE = bufD + SZ;
    float* x1   = bufE + SZ;
    float* Mb   = x1 + SZ;
    float* part = Mb + 16384;
    float* wTa1 = part + 294912;
    float* wTa2 = wTa1 + 36864;
    float* wTm  = wTa2 + 36864;
    float* wTf  = wTm + 36864;

    // weight transposes (tiny, run first)
    wtrans_kernel<<<144, 256>>>(w_add1, wTa1);
    wtrans_kernel<<<144, 256>>>(w_add2, wTa2);
    wtrans_kernel<<<144, 256>>>(w_mul1, wTm);
    wtrans_kernel<<<144, 256>>>(w_fuse, wTf);

    // ---- Attention branch ----
    conv1x1_kernel<128, true, false, false><<<dim3(1024, 4), 128>>>(ref, w_kv, ln1w, ln1b, nullptr, kv0, 64 * HW, 0);
    conv1x1_kernel<64,  true, false, false><<<dim3(512, 4), 128>>>(x, w_q, ln3w, ln3b, nullptr, bufC, 64 * HW, 0);
    dw3x3_kernel<128><<<16384, 256>>>(kv0,  w_kv_dw, kv1);
    dw3x3_kernel<64><<<8192, 256>>>(bufC, w_q_dw, bufD);
    attn_stats_kernel<<<dim3(NCHUNK, 16), 256>>>(bufD, kv1, part);
    attn_finish_kernel<<<4, 256>>>(part, w_proj, temp, Mb);
    conv1x1_kernel<64, false, true, true><<<dim3(512, 4), 128>>>(kv1, Mb, nullptr, nullptr, x, x1, 128 * HW, 64);

    // ---- SFM branch ----
    ln_kernel<<<1024, 256>>>(x1, ln2w, ln2b, bufA);                                     // y
    conv3x3_kernel<1><<<dim3(256, 4), 256>>>(bufA, wTa1, nullptr, nullptr, bufB);       // ga1
    conv3x3_kernel<0><<<dim3(256, 4), 256>>>(bufB, wTa2, nullptr, nullptr, bufC);       // x_add
    conv3x3_kernel<1><<<dim3(256, 4), 256>>>(bufA, wTm, nullptr, nullptr, bufD);        // gm1
    conv3x3_kernel<2><<<dim3(256, 4), 256>>>(bufD, wTm, bufA, bufC, bufE);              // z
    conv3x3_kernel<3><<<dim3(256, 4), 256>>>(bufE, wTf, x1, nullptr, out);              // out
}

// round 8
// speedup vs baseline: 1.1045x; 1.1045x over previous
#include <cuda_runtime.h>
#include <math.h>
#include <stdint.h>

typedef unsigned long long ull;
#define HW 65536
#define NCHUNK 64
#define CSM 178176

__device__ float g_pool[168378368];

__device__ __forceinline__ float gelu_f(float v) {
    return 0.5f * v * (1.0f + erff(v * 0.70710678118654752f));
}
__device__ __forceinline__ ull pack2(float lo, float hi) {
    ull d; asm("mov.b64 %0,{%1,%2};" : "=l"(d) : "f"(lo), "f"(hi)); return d;
}
__device__ __forceinline__ void unpack2(ull v, float& lo, float& hi) {
    asm("mov.b64 {%0,%1},%2;" : "=f"(lo), "=f"(hi) : "l"(v));
}
__device__ __forceinline__ ull ffma2(ull a, ull b, ull c) {
    ull d; asm("fma.rn.f32x2 %0,%1,%2,%3;" : "=l"(d) : "l"(a), "l"(b), "l"(c)); return d;
}
__device__ __forceinline__ uint32_t smaddr(const void* p) {
    uint32_t a;
    asm("{.reg .u64 t; cvta.to.shared.u64 t, %1; cvt.u32.u64 %0, t;}" : "=r"(a) : "l"(p));
    return a;
}
__device__ __forceinline__ float tf32r(float f) {
    uint32_t r; asm("cvt.rna.tf32.f32 %0, %1;" : "=r"(r) : "f"(f));
    return __uint_as_float(r);
}
__device__ __forceinline__ void cpa16(uint32_t s, const void* g) {
    asm volatile("cp.async.cg.shared.global [%0], [%1], 16;" :: "r"(s), "l"(g));
}
__device__ __forceinline__ void cpa16z(uint32_t s, const void* g, bool ok) {
    int sz = ok ? 16 : 0;
    asm volatile("cp.async.cg.shared.global [%0], [%1], 16, %2;" :: "r"(s), "l"(g), "r"(sz));
}
__device__ __forceinline__ void cpa_commit() { asm volatile("cp.async.commit_group;"); }
__device__ __forceinline__ void cpa_wait1() { asm volatile("cp.async.wait_group 1;"); }
__device__ __forceinline__ void cpa_wait0() { asm volatile("cp.async.wait_group 0;"); }
__device__ __forceinline__ void mma_tf32(float* d, const uint32_t* a, const uint32_t* b) {
    asm volatile("mma.sync.aligned.m16n8k8.row.col.f32.tf32.tf32.f32 "
        "{%0,%1,%2,%3}, {%4,%5,%6,%7}, {%8,%9}, {%0,%1,%2,%3};"
        : "+f"(d[0]), "+f"(d[1]), "+f"(d[2]), "+f"(d[3])
        : "r"(a[0]), "r"(a[1]), "r"(a[2]), "r"(a[3]), "r"(b[0]), "r"(b[1]));
}

// ---- weight prep: [(chunk8*9+tap)*128 + m]*8 + k ; m<64 hi / m>=64 lo ----
__global__ void wprep_kernel(const float* __restrict__ w, float* __restrict__ img)
{
    int e = blockIdx.x * 256 + threadIdx.x;   // < 73728
    int k = e & 7;
    int m = (e >> 3) & 127;
    int j = e >> 10;                          // 0..71
    int tap = j % 9, c = j / 9;
    int oc = m & 63, ic = c * 8 + k;
    float wv = w[(oc * 64 + ic) * 9 + tap];
    float hi = tf32r(wv);
    img[e] = (m < 64) ? hi : (wv - hi);
}

// ---- LayerNorm over channels (tf32-rounded: feeds mma convs) ----
__global__ void ln_kernel(const float* __restrict__ in, const float* __restrict__ w,
                          const float* __restrict__ bb, float* __restrict__ out)
{
    int p = blockIdx.x * blockDim.x + threadIdx.x;
    int b = p >> 16, pix = p & 65535;
    const float* ip = in + (long)b * (64 * HW) + pix;
    float s = 0.f, ss = 0.f;
#pragma unroll 8
    for (int c = 0; c < 64; ++c) { float v = ip[(long)c * HW]; s += v; ss += v * v; }
    float mu = s * (1.0f / 64);
    float var = ss * (1.0f / 64) - mu * mu;
    float r = rsqrtf(var + 1e-5f);
    float* op = out + (long)b * (64 * HW) + pix;
#pragma unroll 8
    for (int c = 0; c < 64; ++c) {
        float v = ip[(long)c * HW];
        op[(long)c * HW] = tf32r((v - mu) * r * w[c] + bb[c]);
    }
}

// ---- 1x1 conv, optional fused LN ----
template<int OC, bool LNORM, bool PBW, bool RES>
__global__ void conv1x1_kernel(const float* __restrict__ in, const float* __restrict__ w,
                               const float* __restrict__ lnw, const float* __restrict__ lnb,
                               const float* __restrict__ res, float* __restrict__ out,
                               int in_bstride, int ic_off)
{
    constexpr int OCG = OC / 8;
    constexpr int PXT = (128 / OCG) * 8;
    __shared__ float sW[64 * OC];
    __shared__ float sIn[64 * PXT];
    int b = blockIdx.y, pix0 = blockIdx.x * PXT, tid = threadIdx.x;
    const float* wb = PBW ? (w + b * 64 * OC) : w;
    for (int idx = tid; idx < 64 * OC; idx += 128) {
        int oc = idx % OC, ic = idx / OC;
        sW[idx] = wb[oc * 64 + ic];
    }
    const float* inb = in + (long)b * in_bstride + (long)ic_off * HW + pix0;
    for (int idx = tid; idx < 64 * PXT; idx += 128) {
        int px = idx % PXT, ic = idx / PXT;
        sIn[idx] = inb[(long)ic * HW + px];
    }
    __syncthreads();
    if (LNORM) {
        if (tid < PXT) {
            float s = 0.f, ss = 0.f;
#pragma unroll 8
            for (int c = 0; c < 64; ++c) { float v = sIn[c * PXT + tid]; s += v; ss += v * v; }
            float mu = s * (1.0f / 64);
            float var = ss * (1.0f / 64) - mu * mu;
            float r = rsqrtf(var + 1e-5f);
#pragma unroll 8
            for (int c = 0; c < 64; ++c)
                sIn[c * PXT + tid] = (sIn[c * PXT + tid] - mu) * r * lnw[c] + lnb[c];
        }
        __syncthreads();
    }
    int og = tid % OCG, pg = tid / OCG;
    int oc0 = og * 8, px0 = pg * 8;
    ull acc[8][4];
#pragma unroll
    for (int j = 0; j < 8; ++j)
#pragma unroll
        for (int k = 0; k < 4; ++k) acc[j][k] = 0ull;
#pragma unroll 2
    for (int ic = 0; ic < 64; ++ic) {
        const float4* wv4 = (const float4*)&sW[ic * OC + oc0];
        float4 wa = wv4[0], wbb = wv4[1];
        ull wp[8];
        wp[0] = pack2(wa.x, wa.x); wp[1] = pack2(wa.y, wa.y);
        wp[2] = pack2(wa.z, wa.z); wp[3] = pack2(wa.w, wa.w);
        wp[4] = pack2(wbb.x, wbb.x); wp[5] = pack2(wbb.y, wbb.y);
        wp[6] = pack2(wbb.z, wbb.z); wp[7] = pack2(wbb.w, wbb.w);
        const ull* xv = (const ull*)&sIn[ic * PXT + px0];
        ull x0 = xv[0], x1 = xv[1], x2 = xv[2], x3 = xv[3];
#pragma unroll
        for (int j = 0; j < 8; ++j) {
            acc[j][0] = ffma2(wp[j], x0, acc[j][0]);
            acc[j][1] = ffma2(wp[j], x1, acc[j][1]);
            acc[j][2] = ffma2(wp[j], x2, acc[j][2]);
            acc[j][3] = ffma2(wp[j], x3, acc[j][3]);
        }
    }
#pragma unroll
    for (int j = 0; j < 8; ++j) {
        long o = (long)(b * OC + oc0 + j) * HW + pix0 + px0;
        float v[8];
#pragma unroll
        for (int k = 0; k < 4; ++k) unpack2(acc[j][k], v[2 * k], v[2 * k + 1]);
        float4 a0 = make_float4(v[0], v[1], v[2], v[3]);
        float4 a1 = make_float4(v[4], v[5], v[6], v[7]);
        if (RES) {
            float4 r0 = *(const float4*)&res[o];
            float4 r1 = *(const float4*)&res[o + 4];
            a0.x += r0.x; a0.y += r0.y; a0.z += r0.z; a0.w += r0.w;
            a1.x += r1.x; a1.y += r1.y; a1.z += r1.z; a1.w += r1.w;
        }
        *(float4*)&out[o] = a0;
        *(float4*)&out[o + 4] = a1;
    }
}

// ---- depthwise 3x3 ----
template<int CH>
__global__ void dw3x3_kernel(const float* __restrict__ in, const float* __restrict__ w,
                             float* __restrict__ out)
{
    int p = blockIdx.x * 256 + threadIdx.x;
    int xg = p & 31, y = (p >> 5) & 255, g = p >> 13;
    int c = g & (CH - 1);
    int x0 = xg * 8;
    const float* wp = w + c * 9;
    float wr[9];
#pragma unroll
    for (int t = 0; t < 9; ++t) wr[t] = wp[t];
    const float* ip = in + (long)g * HW;
    float r[3][10];
    bool interior = (y > 0) && (y < 255) && (xg > 0) && (xg < 31);
    if (interior) {
#pragma unroll
        for (int rr = 0; rr < 3; ++rr) {
            const float* base = ip + (y - 1 + rr) * 256 + x0;
            float4 a = *(const float4*)base;
            float4 bq = *(const float4*)(base + 4);
            r[rr][0] = base[-1];
            r[rr][1] = a.x; r[rr][2] = a.y; r[rr][3] = a.z; r[rr][4] = a.w;
            r[rr][5] = bq.x; r[rr][6] = bq.y; r[rr][7] = bq.z; r[rr][8] = bq.w;
            r[rr][9] = base[8];
        }
    } else {
#pragma unroll
        for (int rr = 0; rr < 3; ++rr) {
            int iy = y - 1 + rr;
#pragma unroll
            for (int j = 0; j < 10; ++j) {
                int ix = x0 - 1 + j;
                r[rr][j] = (iy >= 0 && iy < 256 && ix >= 0 && ix < 256) ? ip[iy * 256 + ix] : 0.f;
            }
        }
    }
    float acc[8];
#pragma unroll
    for (int q = 0; q < 8; ++q) acc[q] = 0.f;
#pragma unroll
    for (int ky = 0; ky < 3; ++ky)
#pragma unroll
        for (int kx = 0; kx < 3; ++kx) {
            float wv = wr[ky * 3 + kx];
#pragma unroll
            for (int q = 0; q < 8; ++q) acc[q] += wv * r[ky][q + kx];
        }
    float* op = out + (long)g * HW + y * 256 + x0;
    *(float4*)op = make_float4(acc[0], acc[1], acc[2], acc[3]);
    *(float4*)(op + 4) = make_float4(acc[4], acc[5], acc[6], acc[7]);
}

// ---- attention stats ----
__global__ void attn_stats_kernel(const float* __restrict__ q, const float* __restrict__ k,
                                  float* __restrict__ part)
{
    __shared__ float sQ[16 * 129];
    __shared__ float sK[16 * 129];
    int g = blockIdx.y;
    int b = g >> 2, h = g & 3;
    const float* qb = q + (long)b * 64 * HW + (long)h * 16 * HW;
    const float* kb = k + (long)b * 128 * HW + (long)h * 16 * HW;
    int tid = threadIdx.x;
    int c = tid >> 4, d = tid & 15;
    float accG = 0.f, accQ = 0.f, accK = 0.f;
    int nbase = blockIdx.x * (HW / NCHUNK);
    for (int sub = 0; sub < (HW / NCHUNK) / 128; ++sub) {
        int n0 = nbase + sub * 128;
#pragma unroll
        for (int i = 0; i < 8; ++i) {
            int lin = tid + i * 256;
            int cc = lin >> 7, nn = lin & 127;
            sQ[cc * 129 + nn] = qb[(long)cc * HW + n0 + nn];
            sK[cc * 129 + nn] = kb[(long)cc * HW + n0 + nn];
        }
        __syncthreads();
        const float* qr = sQ + c * 129;
        const float* kr = sK + d * 129;
#pragma unroll 8
        for (int nn = 0; nn < 128; ++nn) accG += qr[nn] * kr[nn];
        if (d == 0) {
#pragma unroll 8
            for (int nn = 0; nn < 128; ++nn) accQ += qr[nn] * qr[nn];
        }
        if (c == 0) {
#pragma unroll 8
            for (int nn = 0; nn < 128; ++nn) accK += kr[nn] * kr[nn];
        }
        __syncthreads();
    }
    float* pp = part + ((long)g * NCHUNK + blockIdx.x) * 288;
    pp[tid] = accG;
    if (d == 0) pp[256 + c] = accQ;
    if (c == 0) pp[272 + d] = accK;
}

// ---- softmax + fold W_proj -> M[b][64][64] ----
__global__ void attn_finish_kernel(const float* __restrict__ part, const float* __restrict__ wproj,
                                   const float* __restrict__ temp, float* __restrict__ Mout)
{
    int b = blockIdx.x, tid = threadIdx.x;
    __shared__ float sG[4][256];
    __shared__ float sq[4][16], sk[4][16];
    __shared__ float sA[4][16][16];
    for (int h = 0; h < 4; ++h) {
        const float* pp = part + ((long)(b * 4 + h)) * NCHUNK * 288;
        float s = 0.f;
        for (int ch = 0; ch < NCHUNK; ++ch) s += pp[ch * 288 + tid];
        sG[h][tid] = s;
        if (tid < 32) {
            float s2 = 0.f;
            for (int ch = 0; ch < NCHUNK; ++ch) s2 += pp[ch * 288 + 256 + tid];
            if (tid < 16) sq[h][tid] = s2; else sk[h][tid - 16] = s2;
        }
    }
    __syncthreads();
    if (tid < 64) {
        int h = tid >> 4, c = tid & 15;
        float qn = fmaxf(sqrtf(sq[h][c]), 1e-12f);
        float tp = temp[h];
        float lg[16];
        float mx = -1e30f;
#pragma unroll
        for (int d = 0; d < 16; ++d) {
            float kn = fmaxf(sqrtf(sk[h][d]), 1e-12f);
            lg[d] = tp * sG[h][c * 16 + d] / (qn * kn);
            mx = fmaxf(mx, lg[d]);
        }
        float ssum = 0.f;
#pragma unroll
        for (int d = 0; d < 16; ++d) { lg[d] = expf(lg[d] - mx); ssum += lg[d]; }
        float inv = 1.f / ssum;
#pragma unroll
        for (int d = 0; d < 16; ++d) sA[h][c][d] = lg[d] * inv;
    }
    __syncthreads();
    for (int e = tid; e < 4096; e += 256) {
        int oc = e >> 6, j = e & 63, h = j >> 4, d = j & 15;
        float s = 0.f;
#pragma unroll
        for (int r = 0; r < 16; ++r) s += wproj[oc * 64 + h * 16 + r] * sA[h][r][d];
        Mout[b * 4096 + e] = s;
    }
}

// ---- dense 3x3 conv via mma.sync tf32 ----
// CTA: 256 thr / 8 warps. Tile: M=128 (64 hi oc + 64 lo oc) x N=128 px (half row).
// X resident: [3 rows][64 ic][136 px] (halo px = x0-4+c). W streamed in 8 ic-chunks.
// EPI: 0 none, 1 gelu+rnd, 2 mix out=tf32r(aux1*sig(acc)+aux2), 3 acc+aux1 fp32
template<int EPI>
__global__ void __launch_bounds__(256, 1)
conv3x3_mma(const float* __restrict__ in, const float* __restrict__ wimg,
            const float* __restrict__ aux1, const float* __restrict__ aux2,
            float* __restrict__ out)
{
    extern __shared__ float smem[];
    float* Wb = smem;               // 2 x 9216
    float* Xb = smem + 18432;       // 3*64*136 = 26112
    float* Db = smem + 18432;       // overlay: 128*132 = 16896
    uint32_t sbW = smaddr(Wb), sbX = smaddr(Xb);

    int tid = threadIdx.x, wid = tid >> 5, lane = tid & 31;
    int gr = lane >> 2, tk = lane & 3;
    int half = blockIdx.x & 1, y = blockIdx.x >> 1, b = blockIdx.y;
    int x0 = half * 128;
    const float* inb = in + (long)b * (64 * HW);

    // stage X (group 0 includes W chunk 0)
    for (int idx = tid; idx < 6528; idx += 256) {
        int c4 = idx % 34;
        int ic = (idx / 34) & 63;
        int row = idx / (34 * 64);
        int gx = x0 - 4 + c4 * 4;
        int gy = y + row - 1;
        bool ok = (gx >= 0) && (gx <= 252) && (gy >= 0) && (gy < 256);
        const float* g = inb + (long)ic * HW + gy * 256 + gx;
        cpa16z(sbX + ((row * 64 + ic) * 136 + c4 * 4) * 4, ok ? g : inb, ok);
    }
#define STAGEW(C, BUF) do { \
        const float4* s_ = (const float4*)(wimg + (long)(C) * 9216); \
        uint32_t d_ = sbW + (BUF) * 36864; \
        for (int t_ = tid; t_ < 2304; t_ += 256) cpa16(d_ + t_ * 16, s_ + t_); \
    } while (0)
    STAGEW(0, 0);
    cpa_commit();
    STAGEW(1, 1);
    cpa_commit();

    int mw = wid & 1, nw = wid >> 1;
    int m0 = mw * 64, n0 = nw * 32;
    float d[4][4][4];
#pragma unroll
    for (int mt = 0; mt < 4; ++mt)
#pragma unroll
        for (int nt = 0; nt < 4; ++nt)
#pragma unroll
            for (int q = 0; q < 4; ++q) d[mt][nt][q] = 0.f;

    for (int cc = 0; cc < 8; ++cc) {
        if (cc < 7) cpa_wait1(); else cpa_wait0();
        __syncthreads();
        const float* wb = Wb + (cc & 1) * 9216;
#pragma unroll
        for (int tap = 0; tap < 9; ++tap) {
            int ky = tap / 3, kx = tap - ky * 3;
            const float* xr = Xb + ((ky * 64 + cc * 8 + tk) * 136) + n0 + gr + kx + 3;
            uint32_t bf[4][2];
#pragma unroll
            for (int nt = 0; nt < 4; ++nt) {
                bf[nt][0] = __float_as_uint(xr[nt * 8]);
                bf[nt][1] = __float_as_uint(xr[nt * 8 + 4 * 136]);
            }
#pragma unroll
            for (int mt = 0; mt < 4; ++mt) {
                const float* wp = wb + (tap * 128 + m0 + mt * 16) * 8;
                uint32_t af[4];
                af[0] = __float_as_uint(wp[gr * 8 + tk]);
                af[1] = __float_as_uint(wp[(gr + 8) * 8 + tk]);
                af[2] = __float_as_uint(wp[gr * 8 + tk + 4]);
                af[3] = __float_as_uint(wp[(gr + 8) * 8 + tk + 4]);
#pragma unroll
                for (int nt = 0; nt < 4; ++nt)
                    mma_tf32(d[mt][nt], af, bf[nt]);
            }
        }
        __syncthreads();
        if (cc + 2 < 8) { STAGEW(cc + 2, cc & 1); cpa_commit(); }
    }
#undef STAGEW

    // store fragments to smem D[128][132]
#pragma unroll
    for (int mt = 0; mt < 4; ++mt) {
        int mr = m0 + mt * 16 + gr;
#pragma unroll
        for (int nt = 0; nt < 4; ++nt) {
            int nc = n0 + nt * 8 + tk * 2;
            *(float2*)&Db[mr * 132 + nc] = make_float2(d[mt][nt][0], d[mt][nt][1]);
            *(float2*)&Db[(mr + 8) * 132 + nc] = make_float2(d[mt][nt][2], d[mt][nt][3]);
        }
    }
    __syncthreads();

    long obase = (long)(b * 64) * HW + y * 256 + x0;
    for (int it = 0; it < 32; ++it) {
        int e = it * 256 + tid;
        int px = e & 127, oc = e >> 7;
        float v = Db[oc * 132 + px] + Db[(oc + 64) * 132 + px];
        long o = obase + (long)oc * HW + px;
        if (EPI == 1) v = tf32r(gelu_f(v));
        else if (EPI == 2) {
            float s = 1.f / (1.f + expf(-v));
            v = tf32r(aux1[o] * s + aux2[o]);
        } else if (EPI == 3) v += aux1[o];
        out[o] = v;
    }
}

extern "C" void kernel_launch(void* const* d_in, const int* in_sizes, int n_in,
                              void* d_out, int out_size)
{
    const float* x       = (const float*)d_in[0];
    const float* ref     = (const float*)d_in[1];
    const float* ln1w    = (const float*)d_in[2];
    const float* ln1b    = (const float*)d_in[3];
    const float* ln2w    = (const float*)d_in[4];
    const float* ln2b    = (const float*)d_in[5];
    const float* ln3w    = (const float*)d_in[6];
    const float* ln3b    = (const float*)d_in[7];
    const float* w_kv    = (const float*)d_in[8];
    const float* w_kv_dw = (const float*)d_in[9];
    const float* w_q     = (const float*)d_in[10];
    const float* w_q_dw  = (const float*)d_in[11];
    const float* w_proj  = (const float*)d_in[12];
    const float* temp    = (const float*)d_in[13];
    const float* w_add1  = (const float*)d_in[14];
    const float* w_add2  = (const float*)d_in[15];
    const float* w_mul1  = (const float*)d_in[16];
    const float* w_fuse  = (const float*)d_in[17];
    float* out = (float*)d_out;

    float* pool = nullptr;
    cudaGetSymbolAddress((void**)&pool, g_pool);
    const long SZ = 16777216L, SZ2 = 33554432L;
    float* kv0  = pool;
    float* kv1  = pool + SZ2;
    float* bufA = pool + 2 * SZ2;
    float* bufB = bufA + SZ;
    float* bufC = bufB + SZ;
    float* bufD = bufC + SZ;
    float* bufE = bufD + SZ;
    float* x1   = bufE + SZ;
    float* Mb   = x1 + SZ;
    float* part = Mb + 16384;
    float* wIa1 = part + 294912;
    float* wIa2 = wIa1 + 73728;
    float* wIm  = wIa2 + 73728;
    float* wIf  = wIm + 73728;

    cudaFuncSetAttribute(conv3x3_mma<0>, cudaFuncAttributeMaxDynamicSharedMemorySize, CSM);
    cudaFuncSetAttribute(conv3x3_mma<1>, cudaFuncAttributeMaxDynamicSharedMemorySize, CSM);
    cudaFuncSetAttribute(conv3x3_mma<2>, cudaFuncAttributeMaxDynamicSharedMemorySize, CSM);
    cudaFuncSetAttribute(conv3x3_mma<3>, cudaFuncAttributeMaxDynamicSharedMemorySize, CSM);

    wprep_kernel<<<288, 256>>>(w_add1, wIa1);
    wprep_kernel<<<288, 256>>>(w_add2, wIa2);
    wprep_kernel<<<288, 256>>>(w_mul1, wIm);
    wprep_kernel<<<288, 256>>>(w_fuse, wIf);

    // ---- Attention branch ----
    conv1x1_kernel<128, true, false, false><<<dim3(1024, 4), 128>>>(ref, w_kv, ln1w, ln1b, nullptr, kv0, 64 * HW, 0);
    conv1x1_kernel<64,  true, false, false><<<dim3(512, 4), 128>>>(x, w_q, ln3w, ln3b, nullptr, bufC, 64 * HW, 0);
    dw3x3_kernel<128><<<16384, 256>>>(kv0,  w_kv_dw, kv1);
    dw3x3_kernel<64><<<8192, 256>>>(bufC, w_q_dw, bufD);
    attn_stats_kernel<<<dim3(NCHUNK, 16), 256>>>(bufD, kv1, part);
    attn_finish_kernel<<<4, 256>>>(part, w_proj, temp, Mb);
    conv1x1_kernel<64, false, true, true><<<dim3(512, 4), 128>>>(kv1, Mb, nullptr, nullptr, x, x1, 128 * HW, 64);

    // ---- SFM branch (mma convs) ----
    ln_kernel<<<1024, 256>>>(x1, ln2w, ln2b, bufA);                                     // y (tf32)
    conv3x3_mma<1><<<dim3(512, 4), 256, CSM>>>(bufA, wIa1, nullptr, nullptr, bufB);     // ga1
    conv3x3_mma<0><<<dim3(512, 4), 256, CSM>>>(bufB, wIa2, nullptr, nullptr, bufC);     // x_add
    conv3x3_mma<1><<<dim3(512, 4), 256, CSM>>>(bufA, wIm, nullptr, nullptr, bufD);      // gm1
    conv3x3_mma<2><<<dim3(512, 4), 256, CSM>>>(bufD, wIm, bufA, bufC, bufE);            // z
    conv3x3_mma<3><<<dim3(512, 4), 256, CSM>>>(bufE, wIf, x1, nullptr, out);            // out
}

// round 10
// speedup vs baseline: 1.3654x; 1.2362x over previous
#include <cuda_runtime.h>
#include <math.h>
#include <stdint.h>

typedef unsigned long long ull;
#define HW 65536
#define NCHUNK 64
#define CSM 99840

__device__ float g_pool[168378368];

__device__ __forceinline__ float gelu_f(float v) {
    return 0.5f * v * (1.0f + erff(v * 0.70710678118654752f));
}
__device__ __forceinline__ ull pack2(float lo, float hi) {
    ull d; asm("mov.b64 %0,{%1,%2};" : "=l"(d) : "f"(lo), "f"(hi)); return d;
}
__device__ __forceinline__ void unpack2(ull v, float& lo, float& hi) {
    asm("mov.b64 {%0,%1},%2;" : "=f"(lo), "=f"(hi) : "l"(v));
}
__device__ __forceinline__ ull ffma2(ull a, ull b, ull c) {
    ull d; asm("fma.rn.f32x2 %0,%1,%2,%3;" : "=l"(d) : "l"(a), "l"(b), "l"(c)); return d;
}
__device__ __forceinline__ uint32_t smaddr(const void* p) {
    uint32_t a;
    asm("{.reg .u64 t; cvta.to.shared.u64 t, %1; cvt.u32.u64 %0, t;}" : "=r"(a) : "l"(p));
    return a;
}
__device__ __forceinline__ float tf32r(float f) {
    uint32_t r; asm("cvt.rna.tf32.f32 %0, %1;" : "=r"(r) : "f"(f));
    return __uint_as_float(r);
}
__device__ __forceinline__ void cpa16(uint32_t s, const void* g) {
    asm volatile("cp.async.cg.shared.global [%0], [%1], 16;" :: "r"(s), "l"(g));
}
__device__ __forceinline__ void cpa16z(uint32_t s, const void* g, bool ok) {
    int sz = ok ? 16 : 0;
    asm volatile("cp.async.cg.shared.global [%0], [%1], 16, %2;" :: "r"(s), "l"(g), "r"(sz));
}
__device__ __forceinline__ void cpa_commit() { asm volatile("cp.async.commit_group;"); }
__device__ __forceinline__ void cpa_wait1() { asm volatile("cp.async.wait_group 1;"); }
__device__ __forceinline__ void cpa_wait0() { asm volatile("cp.async.wait_group 0;"); }
__device__ __forceinline__ void mma_tf32(float* d, const uint32_t* a, const uint32_t* b) {
    asm volatile("mma.sync.aligned.m16n8k8.row.col.f32.tf32.tf32.f32 "
        "{%0,%1,%2,%3}, {%4,%5,%6,%7}, {%8,%9}, {%0,%1,%2,%3};"
        : "+f"(d[0]), "+f"(d[1]), "+f"(d[2]), "+f"(d[3])
        : "r"(a[0]), "r"(a[1]), "r"(a[2]), "r"(a[3]), "r"(b[0]), "r"(b[1]));
}

// ---- weight prep: [(chunk8*9+tap)*128 + m]*8 + k' ; k' pairs (k,k+4) adjacent; m<64 hi / m>=64 lo ----
__global__ void wprep_kernel(const float* __restrict__ w, float* __restrict__ img)
{
    int e = blockIdx.x * 256 + threadIdx.x;   // < 73728
    int kp = e & 7;
    int m = (e >> 3) & 127;
    int j = e >> 10;                          // 0..71
    int tap = j % 9, c = j / 9;
    int k = (kp >> 1) + ((kp & 1) << 2);
    int oc = m & 63, ic = c * 8 + k;
    float wv = w[(oc * 64 + ic) * 9 + tap];
    float hi = tf32r(wv);
    img[e] = (m < 64) ? hi : (wv - hi);
}

// ---- LayerNorm over channels (tf32-rounded: feeds mma convs) ----
__global__ void ln_kernel(const float* __restrict__ in, const float* __restrict__ w,
                          const float* __restrict__ bb, float* __restrict__ out)
{
    int p = blockIdx.x * blockDim.x + threadIdx.x;
    int b = p >> 16, pix = p & 65535;
    const float* ip = in + (long)b * (64 * HW) + pix;
    float s = 0.f, ss = 0.f;
#pragma unroll 8
    for (int c = 0; c < 64; ++c) { float v = ip[(long)c * HW]; s += v; ss += v * v; }
    float mu = s * (1.0f / 64);
    float var = ss * (1.0f / 64) - mu * mu;
    float r = rsqrtf(var + 1e-5f);
    float* op = out + (long)b * (64 * HW) + pix;
#pragma unroll 8
    for (int c = 0; c < 64; ++c) {
        float v = ip[(long)c * HW];
        op[(long)c * HW] = tf32r((v - mu) * r * w[c] + bb[c]);
    }
}

// ---- 1x1 conv, optional fused LN ----
template<int OC, bool LNORM, bool PBW, bool RES>
__global__ void conv1x1_kernel(const float* __restrict__ in, const float* __restrict__ w,
                               const float* __restrict__ lnw, const float* __restrict__ lnb,
                               const float* __restrict__ res, float* __restrict__ out,
                               int in_bstride, int ic_off)
{
    constexpr int OCG = OC / 8;
    constexpr int PXT = (128 / OCG) * 8;
    __shared__ float sW[64 * OC];
    __shared__ float sIn[64 * PXT];
    int b = blockIdx.y, pix0 = blockIdx.x * PXT, tid = threadIdx.x;
    const float* wb = PBW ? (w + b * 64 * OC) : w;
    for (int idx = tid; idx < 64 * OC; idx += 128) {
        int oc = idx % OC, ic = idx / OC;
        sW[idx] = wb[oc * 64 + ic];
    }
    const float* inb = in + (long)b * in_bstride + (long)ic_off * HW + pix0;
    for (int idx = tid; idx < 64 * PXT; idx += 128) {
        int px = idx % PXT, ic = idx / PXT;
        sIn[idx] = inb[(long)ic * HW + px];
    }
    __syncthreads();
    if (LNORM) {
        if (tid < PXT) {
            float s = 0.f, ss = 0.f;
#pragma unroll 8
            for (int c = 0; c < 64; ++c) { float v = sIn[c * PXT + tid]; s += v; ss += v * v; }
            float mu = s * (1.0f / 64);
            float var = ss * (1.0f / 64) - mu * mu;
            float r = rsqrtf(var + 1e-5f);
#pragma unroll 8
            for (int c = 0; c < 64; ++c)
                sIn[c * PXT + tid] = (sIn[c * PXT + tid] - mu) * r * lnw[c] + lnb[c];
        }
        __syncthreads();
    }
    int og = tid % OCG, pg = tid / OCG;
    int oc0 = og * 8, px0 = pg * 8;
    ull acc[8][4];
#pragma unroll
    for (int j = 0; j < 8; ++j)
#pragma unroll
        for (int k = 0; k < 4; ++k) acc[j][k] = 0ull;
#pragma unroll 2
    for (int ic = 0; ic < 64; ++ic) {
        const float4* wv4 = (const float4*)&sW[ic * OC + oc0];
        float4 wa = wv4[0], wbb = wv4[1];
        ull wp[8];
        wp[0] = pack2(wa.x, wa.x); wp[1] = pack2(wa.y, wa.y);
        wp[2] = pack2(wa.z, wa.z); wp[3] = pack2(wa.w, wa.w);
        wp[4] = pack2(wbb.x, wbb.x); wp[5] = pack2(wbb.y, wbb.y);
        wp[6] = pack2(wbb.z, wbb.z); wp[7] = pack2(wbb.w, wbb.w);
        const ull* xv = (const ull*)&sIn[ic * PXT + px0];
        ull x0 = xv[0], x1 = xv[1], x2 = xv[2], x3 = xv[3];
#pragma unroll
        for (int j = 0; j < 8; ++j) {
            acc[j][0] = ffma2(wp[j], x0, acc[j][0]);
            acc[j][1] = ffma2(wp[j], x1, acc[j][1]);
            acc[j][2] = ffma2(wp[j], x2, acc[j][2]);
            acc[j][3] = ffma2(wp[j], x3, acc[j][3]);
        }
    }
#pragma unroll
    for (int j = 0; j < 8; ++j) {
        long o = (long)(b * OC + oc0 + j) * HW + pix0 + px0;
        float v[8];
#pragma unroll
        for (int k = 0; k < 4; ++k) unpack2(acc[j][k], v[2 * k], v[2 * k + 1]);
        float4 a0 = make_float4(v[0], v[1], v[2], v[3]);
        float4 a1 = make_float4(v[4], v[5], v[6], v[7]);
        if (RES) {
            float4 r0 = *(const float4*)&res[o];
            float4 r1 = *(const float4*)&res[o + 4];
            a0.x += r0.x; a0.y += r0.y; a0.z += r0.z; a0.w += r0.w;
            a1.x += r1.x; a1.y += r1.y; a1.z += r1.z; a1.w += r1.w;
        }
        *(float4*)&out[o] = a0;
        *(float4*)&out[o + 4] = a1;
    }
}

// ---- depthwise 3x3 ----
template<int CH>
__global__ void dw3x3_kernel(const float* __restrict__ in, const float* __restrict__ w,
                             float* __restrict__ out)
{
    int p = blockIdx.x * 256 + threadIdx.x;
    int xg = p & 31, y = (p >> 5) & 255, g = p >> 13;
    int c = g & (CH - 1);
    int x0 = xg * 8;
    const float* wp = w + c * 9;
    float wr[9];
#pragma unroll
    for (int t = 0; t < 9; ++t) wr[t] = wp[t];
    const float* ip = in + (long)g * HW;
    float r[3][10];
    bool interior = (y > 0) && (y < 255) && (xg > 0) && (xg < 31);
    if (interior) {
#pragma unroll
        for (int rr = 0; rr < 3; ++rr) {
            const float* base = ip + (y - 1 + rr) * 256 + x0;
            float4 a = *(const float4*)base;
            float4 bq = *(const float4*)(base + 4);
            r[rr][0] = base[-1];
            r[rr][1] = a.x; r[rr][2] = a.y; r[rr][3] = a.z; r[rr][4] = a.w;
            r[rr][5] = bq.x; r[rr][6] = bq.y; r[rr][7] = bq.z; r[rr][8] = bq.w;
            r[rr][9] = base[8];
        }
    } else {
#pragma unroll
        for (int rr = 0; rr < 3; ++rr) {
            int iy = y - 1 + rr;
#pragma unroll
            for (int j = 0; j < 10; ++j) {
                int ix = x0 - 1 + j;
                r[rr][j] = (iy >= 0 && iy < 256 && ix >= 0 && ix < 256) ? ip[iy * 256 + ix] : 0.f;
            }
        }
    }
    float acc[8];
#pragma unroll
    for (int q = 0; q < 8; ++q) acc[q] = 0.f;
#pragma unroll
    for (int ky = 0; ky < 3; ++ky)
#pragma unroll
        for (int kx = 0; kx < 3; ++kx) {
            float wv = wr[ky * 3 + kx];
#pragma unroll
            for (int q = 0; q < 8; ++q) acc[q] += wv * r[ky][q + kx];
        }
    float* op = out + (long)g * HW + y * 256 + x0;
    *(float4*)op = make_float4(acc[0], acc[1], acc[2], acc[3]);
    *(float4*)(op + 4) = make_float4(acc[4], acc[5], acc[6], acc[7]);
}

// ---- attention stats ----
__global__ void attn_stats_kernel(const float* __restrict__ q, const float* __restrict__ k,
                                  float* __restrict__ part)
{
    __shared__ float sQ[16 * 129];
    __shared__ float sK[16 * 129];
    int g = blockIdx.y;
    int b = g >> 2, h = g & 3;
    const float* qb = q + (long)b * 64 * HW + (long)h * 16 * HW;
    const float* kb = k + (long)b * 128 * HW + (long)h * 16 * HW;
    int tid = threadIdx.x;
    int c = tid >> 4, d = tid & 15;
    float accG = 0.f, accQ = 0.f, accK = 0.f;
    int nbase = blockIdx.x * (HW / NCHUNK);
    for (int sub = 0; sub < (HW / NCHUNK) / 128; ++sub) {
        int n0 = nbase + sub * 128;
#pragma unroll
        for (int i = 0; i < 8; ++i) {
            int lin = tid + i * 256;
            int cc = lin >> 7, nn = lin & 127;
            sQ[cc * 129 + nn] = qb[(long)cc * HW + n0 + nn];
            sK[cc * 129 + nn] = kb[(long)cc * HW + n0 + nn];
        }
        __syncthreads();
        const float* qr = sQ + c * 129;
        const float* kr = sK + d * 129;
#pragma unroll 8
        for (int nn = 0; nn < 128; ++nn) accG += qr[nn] * kr[nn];
        if (d == 0) {
#pragma unroll 8
            for (int nn = 0; nn < 128; ++nn) accQ += qr[nn] * qr[nn];
        }
        if (c == 0) {
#pragma unroll 8
            for (int nn = 0; nn < 128; ++nn) accK += kr[nn] * kr[nn];
        }
        __syncthreads();
    }
    float* pp = part + ((long)g * NCHUNK + blockIdx.x) * 288;
    pp[tid] = accG;
    if (d == 0) pp[256 + c] = accQ;
    if (c == 0) pp[272 + d] = accK;
}

// ---- softmax + fold W_proj -> M[b][64][64] ----
__global__ void attn_finish_kernel(const float* __restrict__ part, const float* __restrict__ wproj,
                                   const float* __restrict__ temp, float* __restrict__ Mout)
{
    int b = blockIdx.x, tid = threadIdx.x;
    __shared__ float sG[4][256];
    __shared__ float sq[4][16], sk[4][16];
    __shared__ float sA[4][16][16];
    for (int h = 0; h < 4; ++h) {
        const float* pp = part + ((long)(b * 4 + h)) * NCHUNK * 288;
        float s = 0.f;
        for (int ch = 0; ch < NCHUNK; ++ch) s += pp[ch * 288 + tid];
        sG[h][tid] = s;
        if (tid < 32) {
            float s2 = 0.f;
            for (int ch = 0; ch < NCHUNK; ++ch) s2 += pp[ch * 288 + 256 + tid];
            if (tid < 16) sq[h][tid] = s2; else sk[h][tid - 16] = s2;
        }
    }
    __syncthreads();
    if (tid < 64) {
        int h = tid >> 4, c = tid & 15;
        float qn = fmaxf(sqrtf(sq[h][c]), 1e-12f);
        float tp = temp[h];
        float lg[16];
        float mx = -1e30f;
#pragma unroll
        for (int d = 0; d < 16; ++d) {
            float kn = fmaxf(sqrtf(sk[h][d]), 1e-12f);
            lg[d] = tp * sG[h][c * 16 + d] / (qn * kn);
            mx = fmaxf(mx, lg[d]);
        }
        float ssum = 0.f;
#pragma unroll
        for (int d = 0; d < 16; ++d) { lg[d] = expf(lg[d] - mx); ssum += lg[d]; }
        float inv = 1.f / ssum;
#pragma unroll
        for (int d = 0; d < 16; ++d) sA[h][c][d] = lg[d] * inv;
    }
    __syncthreads();
    for (int e = tid; e < 4096; e += 256) {
        int oc = e >> 6, j = e & 63, h = j >> 4, d = j & 15;
        float s = 0.f;
#pragma unroll
        for (int r = 0; r < 16; ++r) s += wproj[oc * 64 + h * 16 + r] * sA[h][r][d];
        Mout[b * 4096 + e] = s;
    }
}

// ---- dense 3x3 conv via mma.sync tf32, streamed X+W chunks, 2 CTAs/SM ----
// CTA: 256 thr / 8 warps. Tile: M=128 (64 hi oc + 64 lo oc) x N=128 px (half row).
// Per ic-chunk(8): X = [3 rows][8 ic][136 px], W = [9 taps][128 m][8 k'] ; both double-buffered.
// EPI: 0 none, 1 gelu+rnd, 2 mix out=tf32r(aux1*sig(acc)+aux2), 3 acc+aux1 fp32
template<int EPI>
__global__ void __launch_bounds__(256, 2)
conv3x3_mma(const float* __restrict__ in, const float* __restrict__ wimg,
            const float* __restrict__ aux1, const float* __restrict__ aux2,
            float* __restrict__ out)
{
    extern __shared__ float smem[];
    float* Wb = smem;               // 2 x 9216
    float* Xb = smem + 18432;       // 2 x 3264
    float* Db = smem;               // overlay after compute: 128*132
    uint32_t sbW = smaddr(Wb), sbX = smaddr(Xb);

    int tid = threadIdx.x, wid = tid >> 5, lane = tid & 31;
    int gr = lane >> 2, tk = lane & 3;
    int half = blockIdx.x & 1, y = blockIdx.x >> 1, b = blockIdx.y;
    int x0 = half * 128;
    const float* inb = in + (long)b * (64 * HW);

#define STAGE(C, BUF) do { \
        for (int idx = tid; idx < 816; idx += 256) { \
            int c4 = idx % 34; \
            int ri = idx / 34; \
            int ic = ri & 7, row = ri >> 3; \
            int gx = x0 - 4 + c4 * 4; \
            int gy = y + row - 1; \
            bool ok = (gx >= 0) && (gx <= 252) && (gy >= 0) && (gy < 256); \
            const float* g_ = inb + (long)((C) * 8 + ic) * HW + gy * 256 + gx; \
            cpa16z(sbX + ((BUF) * 3264 + ri * 136 + c4 * 4) * 4, ok ? g_ : inb, ok); \
        } \
        const float4* s_ = (const float4*)(wimg + (long)(C) * 9216); \
        uint32_t d_ = sbW + (BUF) * 36864; \
        for (int t_ = tid; t_ < 2304; t_ += 256) cpa16(d_ + t_ * 16, s_ + t_); \
    } while (0)

    STAGE(0, 0);
    cpa_commit();
    STAGE(1, 1);
    cpa_commit();

    int mw = wid & 1, nw = wid >> 1;
    int m0 = mw * 64, n0 = nw * 32;
    float d[4][4][4];
#pragma unroll
    for (int mt = 0; mt < 4; ++mt)
#pragma unroll
        for (int nt = 0; nt < 4; ++nt)
#pragma unroll
            for (int q = 0; q < 4; ++q) d[mt][nt][q] = 0.f;

    for (int cc = 0; cc < 8; ++cc) {
        if (cc < 7) cpa_wait1(); else cpa_wait0();
        __syncthreads();
        const float* wb = Wb + (cc & 1) * 9216;
        const float* xb = Xb + (cc & 1) * 3264;
#pragma unroll
        for (int tap = 0; tap < 9; ++tap) {
            int ky = tap / 3, kx = tap - ky * 3;
            const float* xr = xb + (ky * 8 + tk) * 136 + n0 + gr + kx + 3;
            uint32_t bf[4][2];
#pragma unroll
            for (int nt = 0; nt < 4; ++nt) {
                bf[nt][0] = __float_as_uint(xr[nt * 8]);
                bf[nt][1] = __float_as_uint(xr[nt * 8 + 4 * 136]);
            }
#pragma unroll
            for (int mt = 0; mt < 4; ++mt) {
                const float* wp = wb + (tap * 128 + m0 + mt * 16) * 8;
                float2 aA = *(const float2*)(wp + gr * 8 + tk * 2);
                float2 aB = *(const float2*)(wp + (gr + 8) * 8 + tk * 2);
                uint32_t af[4];
                af[0] = __float_as_uint(aA.x);
                af[1] = __float_as_uint(aB.x);
                af[2] = __float_as_uint(aA.y);
                af[3] = __float_as_uint(aB.y);
#pragma unroll
                for (int nt = 0; nt < 4; ++nt)
                    mma_tf32(d[mt][nt], af, bf[nt]);
            }
        }
        __syncthreads();
        if (cc + 2 < 8) { STAGE(cc + 2, cc & 1); cpa_commit(); }
    }
#undef STAGE

    // store fragments to smem D[128][132]
#pragma unroll
    for (int mt = 0; mt < 4; ++mt) {
        int mr = m0 + mt * 16 + gr;
#pragma unroll
        for (int nt = 0; nt < 4; ++nt) {
            int nc = n0 + nt * 8 + tk * 2;
            *(float2*)&Db[mr * 132 + nc] = make_float2(d[mt][nt][0], d[mt][nt][1]);
            *(float2*)&Db[(mr + 8) * 132 + nc] = make_float2(d[mt][nt][2], d[mt][nt][3]);
        }
    }
    __syncthreads();

    long obase = (long)(b * 64) * HW + y * 256 + x0;
    for (int it = 0; it < 32; ++it) {
        int e = it * 256 + tid;
        int px = e & 127, oc = e >> 7;
        float v = Db[oc * 132 + px] + Db[(oc + 64) * 132 + px];
        long o = obase + (long)oc * HW + px;
        if (EPI == 1) v = tf32r(gelu_f(v));
        else if (EPI == 2) {
            float s = 1.f / (1.f + expf(-v));
            v = tf32r(aux1[o] * s + aux2[o]);
        } else if (EPI == 3) v += aux1[o];
        out[o] = v;
    }
}

extern "C" void kernel_launch(void* const* d_in, const int* in_sizes, int n_in,
                              void* d_out, int out_size)
{
    const float* x       = (const float*)d_in[0];
    const float* ref     = (const float*)d_in[1];
    const float* ln1w    = (const float*)d_in[2];
    const float* ln1b    = (const float*)d_in[3];
    const float* ln2w    = (const float*)d_in[4];
    const float* ln2b    = (const float*)d_in[5];
    const float* ln3w    = (const float*)d_in[6];
    const float* ln3b    = (const float*)d_in[7];
    const float* w_kv    = (const float*)d_in[8];
    const float* w_kv_dw = (const float*)d_in[9];
    const float* w_q     = (const float*)d_in[10];
    const float* w_q_dw  = (const float*)d_in[11];
    const float* w_proj  = (const float*)d_in[12];
    const float* temp    = (const float*)d_in[13];
    const float* w_add1  = (const float*)d_in[14];
    const float* w_add2  = (const float*)d_in[15];
    const float* w_mul1  = (const float*)d_in[16];
    const float* w_fuse  = (const float*)d_in[17];
    float* out = (float*)d_out;

    float* pool = nullptr;
    cudaGetSymbolAddress((void**)&pool, g_pool);
    const long SZ = 16777216L, SZ2 = 33554432L;
    float* kv0  = pool;
    float* kv1  = pool + SZ2;
    float* bufA = pool + 2 * SZ2;
    float* bufB = bufA + SZ;
    float* bufC = bufB + SZ;
    float* bufD = bufC + SZ;
    float* bufE = bufD + SZ;
    float* x1   = bufE + SZ;
    float* Mb   = x1 + SZ;
    float* part = Mb + 16384;
    float* wIa1 = part + 294912;
    float* wIa2 = wIa1 + 73728;
    float* wIm  = wIa2 + 73728;
    float* wIf  = wIm + 73728;

    cudaFuncSetAttribute(conv3x3_mma<0>, cudaFuncAttributeMaxDynamicSharedMemorySize, CSM);
    cudaFuncSetAttribute(conv3x3_mma<1>, cudaFuncAttributeMaxDynamicSharedMemorySize, CSM);
    cudaFuncSetAttribute(conv3x3_mma<2>, cudaFuncAttributeMaxDynamicSharedMemorySize, CSM);
    cudaFuncSetAttribute(conv3x3_mma<3>, cudaFuncAttributeMaxDynamicSharedMemorySize, CSM);

    wprep_kernel<<<288, 256>>>(w_add1, wIa1);
    wprep_kernel<<<288, 256>>>(w_add2, wIa2);
    wprep_kernel<<<288, 256>>>(w_mul1, wIm);
    wprep_kernel<<<288, 256>>>(w_fuse, wIf);

    // ---- Attention branch ----
    conv1x1_kernel<128, true, false, false><<<dim3(1024, 4), 128>>>(ref, w_kv, ln1w, ln1b, nullptr, kv0, 64 * HW, 0);
    conv1x1_kernel<64,  true, false, false><<<dim3(512, 4), 128>>>(x, w_q, ln3w, ln3b, nullptr, bufC, 64 * HW, 0);
    dw3x3_kernel<128><<<16384, 256>>>(kv0,  w_kv_dw, kv1);
    dw3x3_kernel<64><<<8192, 256>>>(bufC, w_q_dw, bufD);
    attn_stats_kernel<<<dim3(NCHUNK, 16), 256>>>(bufD, kv1, part);
    attn_finish_kernel<<<4, 256>>>(part, w_proj, temp, Mb);
    conv1x1_kernel<64, false, true, true><<<dim3(512, 4), 128>>>(kv1, Mb, nullptr, nullptr, x, x1, 128 * HW, 64);

    // ---- SFM branch (mma convs) ----
    ln_kernel<<<1024, 256>>>(x1, ln2w, ln2b, bufA);                                     // y (tf32)
    conv3x3_mma<1><<<dim3(512, 4), 256, CSM>>>(bufA, wIa1, nullptr, nullptr, bufB);     // ga1
    conv3x3_mma<0><<<dim3(512, 4), 256, CSM>>>(bufB, wIa2, nullptr, nullptr, bufC);     // x_add
    conv3x3_mma<1><<<dim3(512, 4), 256, CSM>>>(bufA, wIm, nullptr, nullptr, bufD);      // gm1
    conv3x3_mma<2><<<dim3(512, 4), 256, CSM>>>(bufD, wIm, bufA, bufC, bufE);            // z
    conv3x3_mma<3><<<dim3(512, 4), 256, CSM>>>(bufE, wIf, x1, nullptr, out);            // out
}

// round 11
// speedup vs baseline: 1.7868x; 1.3086x over previous
#include <cuda_runtime.h>
#include <math.h>
#include <stdint.h>

typedef unsigned long long ull;
#define HW 65536
#define NCHUNK 64
#define CSM 62976

__device__ float g_pool[168378368];

__device__ __forceinline__ float gelu_f(float v) {
    return 0.5f * v * (1.0f + erff(v * 0.70710678118654752f));
}
__device__ __forceinline__ ull pack2(float lo, float hi) {
    ull d; asm("mov.b64 %0,{%1,%2};" : "=l"(d) : "f"(lo), "f"(hi)); return d;
}
__device__ __forceinline__ void unpack2(ull v, float& lo, float& hi) {
    asm("mov.b64 {%0,%1},%2;" : "=f"(lo), "=f"(hi) : "l"(v));
}
__device__ __forceinline__ ull ffma2(ull a, ull b, ull c) {
    ull d; asm("fma.rn.f32x2 %0,%1,%2,%3;" : "=l"(d) : "l"(a), "l"(b), "l"(c)); return d;
}
__device__ __forceinline__ uint32_t smaddr(const void* p) {
    uint32_t a;
    asm("{.reg .u64 t; cvta.to.shared.u64 t, %1; cvt.u32.u64 %0, t;}" : "=r"(a) : "l"(p));
    return a;
}
__device__ __forceinline__ float tf32r(float f) {
    uint32_t r; asm("cvt.rna.tf32.f32 %0, %1;" : "=r"(r) : "f"(f));
    return __uint_as_float(r);
}
__device__ __forceinline__ void cpa16(uint32_t s, const void* g) {
    asm volatile("cp.async.cg.shared.global [%0], [%1], 16;" :: "r"(s), "l"(g));
}
__device__ __forceinline__ void cpa16z(uint32_t s, const void* g, bool ok) {
    int sz = ok ? 16 : 0;
    asm volatile("cp.async.cg.shared.global [%0], [%1], 16, %2;" :: "r"(s), "l"(g), "r"(sz));
}
__device__ __forceinline__ void cpa_commit() { asm volatile("cp.async.commit_group;"); }
__device__ __forceinline__ void cpa_wait1() { asm volatile("cp.async.wait_group 1;"); }
__device__ __forceinline__ void cpa_wait0() { asm volatile("cp.async.wait_group 0;"); }
__device__ __forceinline__ void mma_tf32(float* d, const uint32_t* a, const uint32_t* b) {
    asm volatile("mma.sync.aligned.m16n8k8.row.col.f32.tf32.tf32.f32 "
        "{%0,%1,%2,%3}, {%4,%5,%6,%7}, {%8,%9}, {%0,%1,%2,%3};"
        : "+f"(d[0]), "+f"(d[1]), "+f"(d[2]), "+f"(d[3])
        : "r"(a[0]), "r"(a[1]), "r"(a[2]), "r"(a[3]), "r"(b[0]), "r"(b[1]));
}

// ---- weight prep: [(chunk8*9+tap)*64 + oc]*8 + k' ; k' pairs (k,k+4) adjacent; tf32-rounded ----
__global__ void wprep_kernel(const float* __restrict__ w, float* __restrict__ img)
{
    int e = blockIdx.x * 256 + threadIdx.x;   // < 36864
    int kp = e & 7;
    int m = (e >> 3) & 63;
    int j = e >> 9;                           // 0..71
    int tap = j % 9, c = j / 9;
    int k = (kp >> 1) + ((kp & 1) << 2);
    int ic = c * 8 + k;
    img[e] = tf32r(w[(m * 64 + ic) * 9 + tap]);
}

// ---- LayerNorm over channels (tf32-rounded: feeds mma convs) ----
__global__ void ln_kernel(const float* __restrict__ in, const float* __restrict__ w,
                          const float* __restrict__ bb, float* __restrict__ out)
{
    int p = blockIdx.x * blockDim.x + threadIdx.x;
    int b = p >> 16, pix = p & 65535;
    const float* ip = in + (long)b * (64 * HW) + pix;
    float s = 0.f, ss = 0.f;
#pragma unroll 8
    for (int c = 0; c < 64; ++c) { float v = ip[(long)c * HW]; s += v; ss += v * v; }
    float mu = s * (1.0f / 64);
    float var = ss * (1.0f / 64) - mu * mu;
    float r = rsqrtf(var + 1e-5f);
    float* op = out + (long)b * (64 * HW) + pix;
#pragma unroll 8
    for (int c = 0; c < 64; ++c) {
        float v = ip[(long)c * HW];
        op[(long)c * HW] = tf32r((v - mu) * r * w[c] + bb[c]);
    }
}

// ---- 1x1 conv, optional fused LN ----
template<int OC, bool LNORM, bool PBW, bool RES>
__global__ void conv1x1_kernel(const float* __restrict__ in, const float* __restrict__ w,
                               const float* __restrict__ lnw, const float* __restrict__ lnb,
                               const float* __restrict__ res, float* __restrict__ out,
                               int in_bstride, int ic_off)
{
    constexpr int OCG = OC / 8;
    constexpr int PXT = (128 / OCG) * 8;
    __shared__ float sW[64 * OC];
    __shared__ float sIn[64 * PXT];
    int b = blockIdx.y, pix0 = blockIdx.x * PXT, tid = threadIdx.x;
    const float* wb = PBW ? (w + b * 64 * OC) : w;
    for (int idx = tid; idx < 64 * OC; idx += 128) {
        int oc = idx % OC, ic = idx / OC;
        sW[idx] = wb[oc * 64 + ic];
    }
    const float* inb = in + (long)b * in_bstride + (long)ic_off * HW + pix0;
    for (int idx = tid; idx < 64 * PXT; idx += 128) {
        int px = idx % PXT, ic = idx / PXT;
        sIn[idx] = inb[(long)ic * HW + px];
    }
    __syncthreads();
    if (LNORM) {
        if (tid < PXT) {
            float s = 0.f, ss = 0.f;
#pragma unroll 8
            for (int c = 0; c < 64; ++c) { float v = sIn[c * PXT + tid]; s += v; ss += v * v; }
            float mu = s * (1.0f / 64);
            float var = ss * (1.0f / 64) - mu * mu;
            float r = rsqrtf(var + 1e-5f);
#pragma unroll 8
            for (int c = 0; c < 64; ++c)
                sIn[c * PXT + tid] = (sIn[c * PXT + tid] - mu) * r * lnw[c] + lnb[c];
        }
        __syncthreads();
    }
    int og = tid % OCG, pg = tid / OCG;
    int oc0 = og * 8, px0 = pg * 8;
    ull acc[8][4];
#pragma unroll
    for (int j = 0; j < 8; ++j)
#pragma unroll
        for (int k = 0; k < 4; ++k) acc[j][k] = 0ull;
#pragma unroll 2
    for (int ic = 0; ic < 64; ++ic) {
        const float4* wv4 = (const float4*)&sW[ic * OC + oc0];
        float4 wa = wv4[0], wbb = wv4[1];
        ull wp[8];
        wp[0] = pack2(wa.x, wa.x); wp[1] = pack2(wa.y, wa.y);
        wp[2] = pack2(wa.z, wa.z); wp[3] = pack2(wa.w, wa.w);
        wp[4] = pack2(wbb.x, wbb.x); wp[5] = pack2(wbb.y, wbb.y);
        wp[6] = pack2(wbb.z, wbb.z); wp[7] = pack2(wbb.w, wbb.w);
        const ull* xv = (const ull*)&sIn[ic * PXT + px0];
        ull x0 = xv[0], x1 = xv[1], x2 = xv[2], x3 = xv[3];
#pragma unroll
        for (int j = 0; j < 8; ++j) {
            acc[j][0] = ffma2(wp[j], x0, acc[j][0]);
            acc[j][1] = ffma2(wp[j], x1, acc[j][1]);
            acc[j][2] = ffma2(wp[j], x2, acc[j][2]);
            acc[j][3] = ffma2(wp[j], x3, acc[j][3]);
        }
    }
#pragma unroll
    for (int j = 0; j < 8; ++j) {
        long o = (long)(b * OC + oc0 + j) * HW + pix0 + px0;
        float v[8];
#pragma unroll
        for (int k = 0; k < 4; ++k) unpack2(acc[j][k], v[2 * k], v[2 * k + 1]);
        float4 a0 = make_float4(v[0], v[1], v[2], v[3]);
        float4 a1 = make_float4(v[4], v[5], v[6], v[7]);
        if (RES) {
            float4 r0 = *(const float4*)&res[o];
            float4 r1 = *(const float4*)&res[o + 4];
            a0.x += r0.x; a0.y += r0.y; a0.z += r0.z; a0.w += r0.w;
            a1.x += r1.x; a1.y += r1.y; a1.z += r1.z; a1.w += r1.w;
        }
        *(float4*)&out[o] = a0;
        *(float4*)&out[o + 4] = a1;
    }
}

// ---- depthwise 3x3 ----
template<int CH>
__global__ void dw3x3_kernel(const float* __restrict__ in, const float* __restrict__ w,
                             float* __restrict__ out)
{
    int p = blockIdx.x * 256 + threadIdx.x;
    int xg = p & 31, y = (p >> 5) & 255, g = p >> 13;
    int c = g & (CH - 1);
    int x0 = xg * 8;
    const float* wp = w + c * 9;
    float wr[9];
#pragma unroll
    for (int t = 0; t < 9; ++t) wr[t] = wp[t];
    const float* ip = in + (long)g * HW;
    float r[3][10];
    bool interior = (y > 0) && (y < 255) && (xg > 0) && (xg < 31);
    if (interior) {
#pragma unroll
        for (int rr = 0; rr < 3; ++rr) {
            const float* base = ip + (y - 1 + rr) * 256 + x0;
            float4 a = *(const float4*)base;
            float4 bq = *(const float4*)(base + 4);
            r[rr][0] = base[-1];
            r[rr][1] = a.x; r[rr][2] = a.y; r[rr][3] = a.z; r[rr][4] = a.w;
            r[rr][5] = bq.x; r[rr][6] = bq.y; r[rr][7] = bq.z; r[rr][8] = bq.w;
            r[rr][9] = base[8];
        }
    } else {
#pragma unroll
        for (int rr = 0; rr < 3; ++rr) {
            int iy = y - 1 + rr;
#pragma unroll
            for (int j = 0; j < 10; ++j) {
                int ix = x0 - 1 + j;
                r[rr][j] = (iy >= 0 && iy < 256 && ix >= 0 && ix < 256) ? ip[iy * 256 + ix] : 0.f;
            }
        }
    }
    float acc[8];
#pragma unroll
    for (int q = 0; q < 8; ++q) acc[q] = 0.f;
#pragma unroll
    for (int ky = 0; ky < 3; ++ky)
#pragma unroll
        for (int kx = 0; kx < 3; ++kx) {
            float wv = wr[ky * 3 + kx];
#pragma unroll
            for (int q = 0; q < 8; ++q) acc[q] += wv * r[ky][q + kx];
        }
    float* op = out + (long)g * HW + y * 256 + x0;
    *(float4*)op = make_float4(acc[0], acc[1], acc[2], acc[3]);
    *(float4*)(op + 4) = make_float4(acc[4], acc[5], acc[6], acc[7]);
}

// ---- attention stats ----
__global__ void attn_stats_kernel(const float* __restrict__ q, const float* __restrict__ k,
                                  float* __restrict__ part)
{
    __shared__ float sQ[16 * 129];
    __shared__ float sK[16 * 129];
    int g = blockIdx.y;
    int b = g >> 2, h = g & 3;
    const float* qb = q + (long)b * 64 * HW + (long)h * 16 * HW;
    const float* kb = k + (long)b * 128 * HW + (long)h * 16 * HW;
    int tid = threadIdx.x;
    int c = tid >> 4, d = tid & 15;
    float accG = 0.f, accQ = 0.f, accK = 0.f;
    int nbase = blockIdx.x * (HW / NCHUNK);
    for (int sub = 0; sub < (HW / NCHUNK) / 128; ++sub) {
        int n0 = nbase + sub * 128;
#pragma unroll
        for (int i = 0; i < 8; ++i) {
            int lin = tid + i * 256;
            int cc = lin >> 7, nn = lin & 127;
            sQ[cc * 129 + nn] = qb[(long)cc * HW + n0 + nn];
            sK[cc * 129 + nn] = kb[(long)cc * HW + n0 + nn];
        }
        __syncthreads();
        const float* qr = sQ + c * 129;
        const float* kr = sK + d * 129;
#pragma unroll 8
        for (int nn = 0; nn < 128; ++nn) accG += qr[nn] * kr[nn];
        if (d == 0) {
#pragma unroll 8
            for (int nn = 0; nn < 128; ++nn) accQ += qr[nn] * qr[nn];
        }
        if (c == 0) {
#pragma unroll 8
            for (int nn = 0; nn < 128; ++nn) accK += kr[nn] * kr[nn];
        }
        __syncthreads();
    }
    float* pp = part + ((long)g * NCHUNK + blockIdx.x) * 288;
    pp[tid] = accG;
    if (d == 0) pp[256 + c] = accQ;
    if (c == 0) pp[272 + d] = accK;
}

// ---- softmax + fold W_proj -> M[b][64][64] ----
__global__ void attn_finish_kernel(const float* __restrict__ part, const float* __restrict__ wproj,
                                   const float* __restrict__ temp, float* __restrict__ Mout)
{
    int b = blockIdx.x, tid = threadIdx.x;
    __shared__ float sG[4][256];
    __shared__ float sq[4][16], sk[4][16];
    __shared__ float sA[4][16][16];
    for (int h = 0; h < 4; ++h) {
        const float* pp = part + ((long)(b * 4 + h)) * NCHUNK * 288;
        float s = 0.f;
        for (int ch = 0; ch < NCHUNK; ++ch) s += pp[ch * 288 + tid];
        sG[h][tid] = s;
        if (tid < 32) {
            float s2 = 0.f;
            for (int ch = 0; ch < NCHUNK; ++ch) s2 += pp[ch * 288 + 256 + tid];
            if (tid < 16) sq[h][tid] = s2; else sk[h][tid - 16] = s2;
        }
    }
    __syncthreads();
    if (tid < 64) {
        int h = tid >> 4, c = tid & 15;
        float qn = fmaxf(sqrtf(sq[h][c]), 1e-12f);
        float tp = temp[h];
        float lg[16];
        float mx = -1e30f;
#pragma unroll
        for (int d = 0; d < 16; ++d) {
            float kn = fmaxf(sqrtf(sk[h][d]), 1e-12f);
            lg[d] = tp * sG[h][c * 16 + d] / (qn * kn);
            mx = fmaxf(mx, lg[d]);
        }
        float ssum = 0.f;
#pragma unroll
        for (int d = 0; d < 16; ++d) { lg[d] = expf(lg[d] - mx); ssum += lg[d]; }
        float inv = 1.f / ssum;
#pragma unroll
        for (int d = 0; d < 16; ++d) sA[h][c][d] = lg[d] * inv;
    }
    __syncthreads();
    for (int e = tid; e < 4096; e += 256) {
        int oc = e >> 6, j = e & 63, h = j >> 4, d = j & 15;
        float s = 0.f;
#pragma unroll
        for (int r = 0; r < 16; ++r) s += wproj[oc * 64 + h * 16 + r] * sA[h][r][d];
        Mout[b * 4096 + e] = s;
    }
}

// ---- dense 3x3 conv via mma.sync tf32, M=64, streamed X+W chunks, 3 CTAs/SM ----
// CTA: 256 thr / 8 warps. Tile: M=64 oc x N=128 px (half row).
// Per ic-chunk(8): X = [3 rows][8 ic][136 px], W = [9 taps][64 m][8 k'] ; double-buffered.
// EPI: 0 none, 1 gelu+rnd, 2 mix out=tf32r(aux1*sig(acc)+aux2), 3 acc+aux1 fp32
template<int EPI>
__global__ void __launch_bounds__(256, 3)
conv3x3_mma(const float* __restrict__ in, const float* __restrict__ wimg,
            const float* __restrict__ aux1, const float* __restrict__ aux2,
            float* __restrict__ out)
{
    extern __shared__ float smem[];
    float* Wb = smem;               // 2 x 4608
    float* Xb = smem + 9216;        // 2 x 3264
    float* Db = smem;               // overlay after compute: 64*132
    uint32_t sbW = smaddr(Wb), sbX = smaddr(Xb);

    int tid = threadIdx.x, wid = tid >> 5, lane = tid & 31;
    int gr = lane >> 2, tk = lane & 3;
    int half = blockIdx.x & 1, y = blockIdx.x >> 1, b = blockIdx.y;
    int x0 = half * 128;
    const float* inb = in + (long)b * (64 * HW);

#define STAGE(C, BUF) do { \
        for (int idx = tid; idx < 816; idx += 256) { \
            int c4 = idx % 34; \
            int ri = idx / 34; \
            int ic = ri & 7, row = ri >> 3; \
            int gx = x0 - 4 + c4 * 4; \
            int gy = y + row - 1; \
            bool ok = (gx >= 0) && (gx <= 252) && (gy >= 0) && (gy < 256); \
            const float* g_ = inb + (long)((C) * 8 + ic) * HW + gy * 256 + gx; \
            cpa16z(sbX + ((BUF) * 3264 + ri * 136 + c4 * 4) * 4, ok ? g_ : inb, ok); \
        } \
        const float4* s_ = (const float4*)(wimg + (long)(C) * 4608); \
        uint32_t d_ = sbW + (BUF) * 18432; \
        for (int t_ = tid; t_ < 1152; t_ += 256) cpa16(d_ + t_ * 16, s_ + t_); \
    } while (0)

    STAGE(0, 0);
    cpa_commit();
    STAGE(1, 1);
    cpa_commit();

    int mw = wid & 1, nw = wid >> 1;
    int m0 = mw * 32, n0 = nw * 32;
    float d[2][4][4];
#pragma unroll
    for (int mt = 0; mt < 2; ++mt)
#pragma unroll
        for (int nt = 0; nt < 4; ++nt)
#pragma unroll
            for (int q = 0; q < 4; ++q) d[mt][nt][q] = 0.f;

    for (int cc = 0; cc < 8; ++cc) {
        if (cc < 7) cpa_wait1(); else cpa_wait0();
        __syncthreads();
        const float* wb = Wb + (cc & 1) * 4608;
        const float* xb = Xb + (cc & 1) * 3264;
#pragma unroll
        for (int tap = 0; tap < 9; ++tap) {
            int ky = tap / 3, kx = tap - ky * 3;
            const float* xr = xb + (ky * 8 + tk) * 136 + n0 + gr + kx + 3;
            uint32_t bf[4][2];
#pragma unroll
            for (int nt = 0; nt < 4; ++nt) {
                bf[nt][0] = __float_as_uint(xr[nt * 8]);
                bf[nt][1] = __float_as_uint(xr[nt * 8 + 4 * 136]);
            }
#pragma unroll
            for (int mt = 0; mt < 2; ++mt) {
                const float* wp = wb + (tap * 64 + m0 + mt * 16) * 8;
                float2 aA = *(const float2*)(wp + gr * 8 + tk * 2);
                float2 aB = *(const float2*)(wp + (gr + 8) * 8 + tk * 2);
                uint32_t af[4];
                af[0] = __float_as_uint(aA.x);
                af[1] = __float_as_uint(aB.x);
                af[2] = __float_as_uint(aA.y);
                af[3] = __float_as_uint(aB.y);
#pragma unroll
                for (int nt = 0; nt < 4; ++nt)
                    mma_tf32(d[mt][nt], af, bf[nt]);
            }
        }
        __syncthreads();
        if (cc + 2 < 8) { STAGE(cc + 2, cc & 1); cpa_commit(); }
    }
#undef STAGE

    // store fragments to smem D[64][132]
#pragma unroll
    for (int mt = 0; mt < 2; ++mt) {
        int mr = m0 + mt * 16 + gr;
#pragma unroll
        for (int nt = 0; nt < 4; ++nt) {
            int nc = n0 + nt * 8 + tk * 2;
            *(float2*)&Db[mr * 132 + nc] = make_float2(d[mt][nt][0], d[mt][nt][1]);
            *(float2*)&Db[(mr + 8) * 132 + nc] = make_float2(d[mt][nt][2], d[mt][nt][3]);
        }
    }
    __syncthreads();

    long obase = (long)(b * 64) * HW + y * 256 + x0;
    for (int it = 0; it < 32; ++it) {
        int e = it * 256 + tid;
        int px = e & 127, oc = e >> 7;
        float v = Db[oc * 132 + px];
        long o = obase + (long)oc * HW + px;
        if (EPI == 1) v = tf32r(gelu_f(v));
        else if (EPI == 2) {
            float s = 1.f / (1.f + expf(-v));
            v = tf32r(aux1[o] * s + aux2[o]);
        } else if (EPI == 3) v += aux1[o];
        out[o] = v;
    }
}

extern "C" void kernel_launch(void* const* d_in, const int* in_sizes, int n_in,
                              void* d_out, int out_size)
{
    const float* x       = (const float*)d_in[0];
    const float* ref     = (const float*)d_in[1];
    const float* ln1w    = (const float*)d_in[2];
    const float* ln1b    = (const float*)d_in[3];
    const float* ln2w    = (const float*)d_in[4];
    const float* ln2b    = (const float*)d_in[5];
    const float* ln3w    = (const float*)d_in[6];
    const float* ln3b    = (const float*)d_in[7];
    const float* w_kv    = (const float*)d_in[8];
    const float* w_kv_dw = (const float*)d_in[9];
    const float* w_q     = (const float*)d_in[10];
    const float* w_q_dw  = (const float*)d_in[11];
    const float* w_proj  = (const float*)d_in[12];
    const float* temp    = (const float*)d_in[13];
    const float* w_add1  = (const float*)d_in[14];
    const float* w_add2  = (const float*)d_in[15];
    const float* w_mul1  = (const float*)d_in[16];
    const float* w_fuse  = (const float*)d_in[17];
    float* out = (float*)d_out;

    float* pool = nullptr;
    cudaGetSymbolAddress((void**)&pool, g_pool);
    const long SZ = 16777216L, SZ2 = 33554432L;
    float* kv0  = pool;
    float* kv1  = pool + SZ2;
    float* bufA = pool + 2 * SZ2;
    float* bufB = bufA + SZ;
    float* bufC = bufB + SZ;
    float* bufD = bufC + SZ;
    float* bufE = bufD + SZ;
    float* x1   = bufE + SZ;
    float* Mb   = x1 + SZ;
    float* part = Mb + 16384;
    float* wIa1 = part + 294912;
    float* wIa2 = wIa1 + 36864;
    float* wIm  = wIa2 + 36864;
    float* wIf  = wIm + 36864;

    cudaFuncSetAttribute(conv3x3_mma<0>, cudaFuncAttributeMaxDynamicSharedMemorySize, CSM);
    cudaFuncSetAttribute(conv3x3_mma<1>, cudaFuncAttributeMaxDynamicSharedMemorySize, CSM);
    cudaFuncSetAttribute(conv3x3_mma<2>, cudaFuncAttributeMaxDynamicSharedMemorySize, CSM);
    cudaFuncSetAttribute(conv3x3_mma<3>, cudaFuncAttributeMaxDynamicSharedMemorySize, CSM);

    wprep_kernel<<<144, 256>>>(w_add1, wIa1);
    wprep_kernel<<<144, 256>>>(w_add2, wIa2);
    wprep_kernel<<<144, 256>>>(w_mul1, wIm);
    wprep_kernel<<<144, 256>>>(w_fuse, wIf);

    // ---- Attention branch ----
    conv1x1_kernel<128, true, false, false><<<dim3(1024, 4), 128>>>(ref, w_kv, ln1w, ln1b, nullptr, kv0, 64 * HW, 0);
    conv1x1_kernel<64,  true, false, false><<<dim3(512, 4), 128>>>(x, w_q, ln3w, ln3b, nullptr, bufC, 64 * HW, 0);
    dw3x3_kernel<128><<<16384, 256>>>(kv0,  w_kv_dw, kv1);
    dw3x3_kernel<64><<<8192, 256>>>(bufC, w_q_dw, bufD);
    attn_stats_kernel<<<dim3(NCHUNK, 16), 256>>>(bufD, kv1, part);
    attn_finish_kernel<<<4, 256>>>(part, w_proj, temp, Mb);
    conv1x1_kernel<64, false, true, true><<<dim3(512, 4), 128>>>(kv1, Mb, nullptr, nullptr, x, x1, 128 * HW, 64);

    // ---- SFM branch (mma convs) ----
    ln_kernel<<<1024, 256>>>(x1, ln2w, ln2b, bufA);                                     // y (tf32)
    conv3x3_mma<1><<<dim3(512, 4), 256, CSM>>>(bufA, wIa1, nullptr, nullptr, bufB);     // ga1
    conv3x3_mma<0><<<dim3(512, 4), 256, CSM>>>(bufB, wIa2, nullptr, nullptr, bufC);     // x_add
    conv3x3_mma<1><<<dim3(512, 4), 256, CSM>>>(bufA, wIm, nullptr, nullptr, bufD);      // gm1
    conv3x3_mma<2><<<dim3(512, 4), 256, CSM>>>(bufD, wIm, bufA, bufC, bufE);            // z
    conv3x3_mma<3><<<dim3(512, 4), 256, CSM>>>(bufE, wIf, x1, nullptr, out);            // out
}

// round 12
// speedup vs baseline: 2.2642x; 1.2672x over previous
#include <cuda_runtime.h>
#include <math.h>
#include <stdint.h>

typedef unsigned long long ull;
#define HW 65536
#define NCHUNK 64
#define CSM 62976
#define CSM1KV 67584
#define CSM1 51200

__device__ float g_pool[168378368];

__device__ __forceinline__ float gelu_f(float v) {
    return 0.5f * v * (1.0f + erff(v * 0.70710678118654752f));
}
__device__ __forceinline__ uint32_t smaddr(const void* p) {
    uint32_t a;
    asm("{.reg .u64 t; cvta.to.shared.u64 t, %1; cvt.u32.u64 %0, t;}" : "=r"(a) : "l"(p));
    return a;
}
__device__ __forceinline__ float tf32r(float f) {
    uint32_t r; asm("cvt.rna.tf32.f32 %0, %1;" : "=r"(r) : "f"(f));
    return __uint_as_float(r);
}
__device__ __forceinline__ void cpa16(uint32_t s, const void* g) {
    asm volatile("cp.async.cg.shared.global [%0], [%1], 16;" :: "r"(s), "l"(g));
}
__device__ __forceinline__ void cpa16z(uint32_t s, const void* g, bool ok) {
    int sz = ok ? 16 : 0;
    asm volatile("cp.async.cg.shared.global [%0], [%1], 16, %2;" :: "r"(s), "l"(g), "r"(sz));
}
__device__ __forceinline__ void cpa_commit() { asm volatile("cp.async.commit_group;"); }
__device__ __forceinline__ void cpa_wait1() { asm volatile("cp.async.wait_group 1;"); }
__device__ __forceinline__ void cpa_wait0() { asm volatile("cp.async.wait_group 0;"); }
__device__ __forceinline__ void mma_tf32(float* d, const uint32_t* a, const uint32_t* b) {
    asm volatile("mma.sync.aligned.m16n8k8.row.col.f32.tf32.tf32.f32 "
        "{%0,%1,%2,%3}, {%4,%5,%6,%7}, {%8,%9}, {%0,%1,%2,%3};"
        : "+f"(d[0]), "+f"(d[1]), "+f"(d[2]), "+f"(d[3])
        : "r"(a[0]), "r"(a[1]), "r"(a[2]), "r"(a[3]), "r"(b[0]), "r"(b[1]));
}

// ---- 3x3 weight prep: [(chunk8*9+tap)*64 + oc]*8 + k' ; k' pairs (k,k+4) adjacent ----
__global__ void wprep_kernel(const float* __restrict__ w, float* __restrict__ img)
{
    int e = blockIdx.x * 256 + threadIdx.x;   // < 36864
    int kp = e & 7;
    int m = (e >> 3) & 63;
    int j = e >> 9;
    int tap = j % 9, c = j / 9;
    int k = (kp >> 1) + ((kp & 1) << 2);
    int ic = c * 8 + k;
    img[e] = tf32r(w[(m * 64 + ic) * 9 + tap]);
}

// ---- 1x1 weight prep: [cc][m][k'] tf32 ----
__global__ void wprep1_kernel(const float* __restrict__ w, float* __restrict__ img, int OC)
{
    int e = blockIdx.x * 256 + threadIdx.x;
    if (e >= OC * 64) return;
    int kp = e & 7, rest = e >> 3;
    int m = rest % OC, cc = rest / OC;
    int k = (kp >> 1) + ((kp & 1) << 2);
    img[e] = tf32r(w[m * 64 + cc * 8 + k]);
}

// ---- LayerNorm over channels (tf32-rounded) ----
__global__ void ln_kernel(const float* __restrict__ in, const float* __restrict__ w,
                          const float* __restrict__ bb, float* __restrict__ out)
{
    int p = blockIdx.x * blockDim.x + threadIdx.x;
    int b = p >> 16, pix = p & 65535;
    const float* ip = in + (long)b * (64 * HW) + pix;
    float s = 0.f, ss = 0.f;
#pragma unroll 8
    for (int c = 0; c < 64; ++c) { float v = ip[(long)c * HW]; s += v; ss += v * v; }
    float mu = s * (1.0f / 64);
    float var = ss * (1.0f / 64) - mu * mu;
    float r = rsqrtf(var + 1e-5f);
    float* op = out + (long)b * (64 * HW) + pix;
#pragma unroll 8
    for (int c = 0; c < 64; ++c) {
        float v = ip[(long)c * HW];
        op[(long)c * HW] = tf32r((v - mu) * r * w[c] + bb[c]);
    }
}

// ---- 1x1 conv via mma.sync tf32. M=OC, N=128 px. Optional fused LN / runtime per-batch W / residual ----
template<int OC, bool LNORM, bool PBW, bool RES>
__global__ void __launch_bounds__(256, 2)
conv1x1_mma(const float* __restrict__ in, const float* __restrict__ wsrc,
            const float* __restrict__ lnw, const float* __restrict__ lnb,
            const float* __restrict__ res, float* __restrict__ out,
            int in_bstride, int ic_off)
{
    extern __shared__ float smem[];
    float* Xb = smem;            // 64 x 136
    float* Wb = smem + 8704;     // [cc][OC][8k']
    float* Db = smem;            // overlay OC x 132
    uint32_t sbX = smaddr(Xb), sbW = smaddr(Wb);
    int tid = threadIdx.x, wid = tid >> 5, lane = tid & 31;
    int gr = lane >> 2, tk = lane & 3;
    int b = blockIdx.y, pix0 = blockIdx.x * 128;
    const float* inb = in + (long)b * in_bstride + (long)ic_off * HW + pix0;

    for (int idx = tid; idx < 2048; idx += 256) {
        int c4 = idx & 31, ic = idx >> 5;
        cpa16(sbX + (ic * 136 + c4 * 4) * 4, inb + (long)ic * HW + c4 * 4);
    }
    if (!PBW) {
        const float4* s_ = (const float4*)wsrc;
        for (int t_ = tid; t_ < OC * 16; t_ += 256) cpa16(sbW + t_ * 16, s_ + t_);
    }
    cpa_commit();
    if (PBW) {
        const float* wb = wsrc + b * 64 * OC;
        for (int idx = tid; idx < OC * 64; idx += 256) {
            int kp = idx & 7, rest = idx >> 3;
            int m = rest & (OC - 1), cc = rest / OC;
            int k = (kp >> 1) + ((kp & 1) << 2);
            Wb[idx] = tf32r(wb[m * 64 + cc * 8 + k]);
        }
    }
    cpa_wait0();
    __syncthreads();
    if (LNORM) {
        if (tid < 128) {
            float s = 0.f, ss = 0.f;
#pragma unroll 8
            for (int c = 0; c < 64; ++c) { float v = Xb[c * 136 + tid]; s += v; ss += v * v; }
            float mu = s * (1.f / 64), var = ss * (1.f / 64) - mu * mu;
            float r = rsqrtf(var + 1e-5f);
#pragma unroll 8
            for (int c = 0; c < 64; ++c)
                Xb[c * 136 + tid] = tf32r((Xb[c * 136 + tid] - mu) * r * lnw[c] + lnb[c]);
        }
    } else {
        for (int i = tid; i < 8192; i += 256) {
            int px = i & 127, ic = i >> 7;
            Xb[ic * 136 + px] = tf32r(Xb[ic * 136 + px]);
        }
    }
    __syncthreads();

    constexpr int MT = OC / 32;
    int mw = wid & 1, nw = wid >> 1;
    int m0 = mw * (OC / 2), n0 = nw * 32;
    float d[MT][4][4];
#pragma unroll
    for (int mt = 0; mt < MT; ++mt)
#pragma unroll
        for (int nt = 0; nt < 4; ++nt)
#pragma unroll
            for (int q = 0; q < 4; ++q) d[mt][nt][q] = 0.f;

#pragma unroll
    for (int cc = 0; cc < 8; ++cc) {
        uint32_t bf[4][2];
#pragma unroll
        for (int nt = 0; nt < 4; ++nt) {
            const float* xr = Xb + (cc * 8 + tk) * 136 + n0 + nt * 8 + gr;
            bf[nt][0] = __float_as_uint(xr[0]);
            bf[nt][1] = __float_as_uint(xr[4 * 136]);
        }
#pragma unroll
        for (int mt = 0; mt < MT; ++mt) {
            const float* wp = Wb + (cc * OC + m0 + mt * 16) * 8;
            float2 aA = *(const float2*)(wp + gr * 8 + tk * 2);
            float2 aB = *(const float2*)(wp + (gr + 8) * 8 + tk * 2);
            uint32_t af[4] = {__float_as_uint(aA.x), __float_as_uint(aB.x),
                              __float_as_uint(aA.y), __float_as_uint(aB.y)};
#pragma unroll
            for (int nt = 0; nt < 4; ++nt) mma_tf32(d[mt][nt], af, bf[nt]);
        }
    }
    __syncthreads();
#pragma unroll
    for (int mt = 0; mt < MT; ++mt) {
        int mr = m0 + mt * 16 + gr;
#pragma unroll
        for (int nt = 0; nt < 4; ++nt) {
            int nc = n0 + nt * 8 + tk * 2;
            *(float2*)&Db[mr * 132 + nc] = make_float2(d[mt][nt][0], d[mt][nt][1]);
            *(float2*)&Db[(mr + 8) * 132 + nc] = make_float2(d[mt][nt][2], d[mt][nt][3]);
        }
    }
    __syncthreads();
    for (int it = 0; it < OC / 2; ++it) {
        int e = it * 256 + tid;
        int px = e & 127, oc = e >> 7;
        float v = Db[oc * 132 + px];
        long o = (long)(b * OC + oc) * HW + pix0 + px;
        if (RES) v += res[o];
        out[o] = v;
    }
}

// ---- depthwise 3x3 ----
template<int CH>
__global__ void dw3x3_kernel(const float* __restrict__ in, const float* __restrict__ w,
                             float* __restrict__ out)
{
    int p = blockIdx.x * 256 + threadIdx.x;
    int xg = p & 31, y = (p >> 5) & 255, g = p >> 13;
    int c = g & (CH - 1);
    int x0 = xg * 8;
    const float* wp = w + c * 9;
    float wr[9];
#pragma unroll
    for (int t = 0; t < 9; ++t) wr[t] = wp[t];
    const float* ip = in + (long)g * HW;
    float r[3][10];
    bool interior = (y > 0) && (y < 255) && (xg > 0) && (xg < 31);
    if (interior) {
#pragma unroll
        for (int rr = 0; rr < 3; ++rr) {
            const float* base = ip + (y - 1 + rr) * 256 + x0;
            float4 a = *(const float4*)base;
            float4 bq = *(const float4*)(base + 4);
            r[rr][0] = base[-1];
            r[rr][1] = a.x; r[rr][2] = a.y; r[rr][3] = a.z; r[rr][4] = a.w;
            r[rr][5] = bq.x; r[rr][6] = bq.y; r[rr][7] = bq.z; r[rr][8] = bq.w;
            r[rr][9] = base[8];
        }
    } else {
#pragma unroll
        for (int rr = 0; rr < 3; ++rr) {
            int iy = y - 1 + rr;
#pragma unroll
            for (int j = 0; j < 10; ++j) {
                int ix = x0 - 1 + j;
                r[rr][j] = (iy >= 0 && iy < 256 && ix >= 0 && ix < 256) ? ip[iy * 256 + ix] : 0.f;
            }
        }
    }
    float acc[8];
#pragma unroll
    for (int q = 0; q < 8; ++q) acc[q] = 0.f;
#pragma unroll
    for (int ky = 0; ky < 3; ++ky)
#pragma unroll
        for (int kx = 0; kx < 3; ++kx) {
            float wv = wr[ky * 3 + kx];
#pragma unroll
            for (int q = 0; q < 8; ++q) acc[q] += wv * r[ky][q + kx];
        }
    float* op = out + (long)g * HW + y * 256 + x0;
    *(float4*)op = make_float4(acc[0], acc[1], acc[2], acc[3]);
    *(float4*)(op + 4) = make_float4(acc[4], acc[5], acc[6], acc[7]);
}

// ---- attention stats ----
__global__ void attn_stats_kernel(const float* __restrict__ q, const float* __restrict__ k,
                                  float* __restrict__ part)
{
    __shared__ float sQ[16 * 129];
    __shared__ float sK[16 * 129];
    int g = blockIdx.y;
    int b = g >> 2, h = g & 3;
    const float* qb = q + (long)b * 64 * HW + (long)h * 16 * HW;
    const float* kb = k + (long)b * 128 * HW + (long)h * 16 * HW;
    int tid = threadIdx.x;
    int c = tid >> 4, d = tid & 15;
    float accG = 0.f, accQ = 0.f, accK = 0.f;
    int nbase = blockIdx.x * (HW / NCHUNK);
    for (int sub = 0; sub < (HW / NCHUNK) / 128; ++sub) {
        int n0 = nbase + sub * 128;
#pragma unroll
        for (int i = 0; i < 8; ++i) {
            int lin = tid + i * 256;
            int cc = lin >> 7, nn = lin & 127;
            sQ[cc * 129 + nn] = qb[(long)cc * HW + n0 + nn];
            sK[cc * 129 + nn] = kb[(long)cc * HW + n0 + nn];
        }
        __syncthreads();
        const float* qr = sQ + c * 129;
        const float* kr = sK + d * 129;
#pragma unroll 8
        for (int nn = 0; nn < 128; ++nn) accG += qr[nn] * kr[nn];
        if (d == 0) {
#pragma unroll 8
            for (int nn = 0; nn < 128; ++nn) accQ += qr[nn] * qr[nn];
        }
        if (c == 0) {
#pragma unroll 8
            for (int nn = 0; nn < 128; ++nn) accK += kr[nn] * kr[nn];
        }
        __syncthreads();
    }
    float* pp = part + ((long)g * NCHUNK + blockIdx.x) * 288;
    pp[tid] = accG;
    if (d == 0) pp[256 + c] = accQ;
    if (c == 0) pp[272 + d] = accK;
}

// ---- softmax + fold W_proj -> M[b][64][64] ----
__global__ void attn_finish_kernel(const float* __restrict__ part, const float* __restrict__ wproj,
                                   const float* __restrict__ temp, float* __restrict__ Mout)
{
    int b = blockIdx.x, tid = threadIdx.x;
    __shared__ float sG[4][256];
    __shared__ float sq[4][16], sk[4][16];
    __shared__ float sA[4][16][16];
    for (int h = 0; h < 4; ++h) {
        const float* pp = part + ((long)(b * 4 + h)) * NCHUNK * 288;
        float s = 0.f;
        for (int ch = 0; ch < NCHUNK; ++ch) s += pp[ch * 288 + tid];
        sG[h][tid] = s;
        if (tid < 32) {
            float s2 = 0.f;
            for (int ch = 0; ch < NCHUNK; ++ch) s2 += pp[ch * 288 + 256 + tid];
            if (tid < 16) sq[h][tid] = s2; else sk[h][tid - 16] = s2;
        }
    }
    __syncthreads();
    if (tid < 64) {
        int h = tid >> 4, c = tid & 15;
        float qn = fmaxf(sqrtf(sq[h][c]), 1e-12f);
        float tp = temp[h];
        float lg[16];
        float mx = -1e30f;
#pragma unroll
        for (int d = 0; d < 16; ++d) {
            float kn = fmaxf(sqrtf(sk[h][d]), 1e-12f);
            lg[d] = tp * sG[h][c * 16 + d] / (qn * kn);
            mx = fmaxf(mx, lg[d]);
        }
        float ssum = 0.f;
#pragma unroll
        for (int d = 0; d < 16; ++d) { lg[d] = expf(lg[d] - mx); ssum += lg[d]; }
        float inv = 1.f / ssum;
#pragma unroll
        for (int d = 0; d < 16; ++d) sA[h][c][d] = lg[d] * inv;
    }
    __syncthreads();
    for (int e = tid; e < 4096; e += 256) {
        int oc = e >> 6, j = e & 63, h = j >> 4, d = j & 15;
        float s = 0.f;
#pragma unroll
        for (int r = 0; r < 16; ++r) s += wproj[oc * 64 + h * 16 + r] * sA[h][r][d];
        Mout[b * 4096 + e] = s;
    }
}

// ---- dense 3x3 conv via mma.sync tf32, M=64, streamed X+W chunks ----
template<int EPI>
__global__ void __launch_bounds__(256, 3)
conv3x3_mma(const float* __restrict__ in, const float* __restrict__ wimg,
            const float* __restrict__ aux1, const float* __restrict__ aux2,
            float* __restrict__ out)
{
    extern __shared__ float smem[];
    float* Wb = smem;               // 2 x 4608
    float* Xb = smem + 9216;        // 2 x 3264
    float* Db = smem;               // overlay: 64*132
    uint32_t sbW = smaddr(Wb), sbX = smaddr(Xb);

    int tid = threadIdx.x, wid = tid >> 5, lane = tid & 31;
    int gr = lane >> 2, tk = lane & 3;
    int half = blockIdx.x & 1, y = blockIdx.x >> 1, b = blockIdx.y;
    int x0 = half * 128;
    const float* inb = in + (long)b * (64 * HW);

#define STAGE(C, BUF) do { \
        for (int idx = tid; idx < 816; idx += 256) { \
            int c4 = idx % 34; \
            int ri = idx / 34; \
            int ic = ri & 7, row = ri >> 3; \
            int gx = x0 - 4 + c4 * 4; \
            int gy = y + row - 1; \
            bool ok = (gx >= 0) && (gx <= 252) && (gy >= 0) && (gy < 256); \
            const float* g_ = inb + (long)((C) * 8 + ic) * HW + gy * 256 + gx; \
            cpa16z(sbX + ((BUF) * 3264 + ri * 136 + c4 * 4) * 4, ok ? g_ : inb, ok); \
        } \
        const float4* s_ = (const float4*)(wimg + (long)(C) * 4608); \
        uint32_t d_ = sbW + (BUF) * 18432; \
        for (int t_ = tid; t_ < 1152; t_ += 256) cpa16(d_ + t_ * 16, s_ + t_); \
    } while (0)

    STAGE(0, 0);
    cpa_commit();
    STAGE(1, 1);
    cpa_commit();

    int mw = wid & 1, nw = wid >> 1;
    int m0 = mw * 32, n0 = nw * 32;
    float d[2][4][4];
#pragma unroll
    for (int mt = 0; mt < 2; ++mt)
#pragma unroll
        for (int nt = 0; nt < 4; ++nt)
#pragma unroll
            for (int q = 0; q < 4; ++q) d[mt][nt][q] = 0.f;

    for (int cc = 0; cc < 8; ++cc) {
        if (cc < 7) cpa_wait1(); else cpa_wait0();
        __syncthreads();
        const float* wb = Wb + (cc & 1) * 4608;
        const float* xb = Xb + (cc & 1) * 3264;
#pragma unroll
        for (int tap = 0; tap < 9; ++tap) {
            int ky = tap / 3, kx = tap - ky * 3;
            const float* xr = xb + (ky * 8 + tk) * 136 + n0 + gr + kx + 3;
            uint32_t bf[4][2];
#pragma unroll
            for (int nt = 0; nt < 4; ++nt) {
                bf[nt][0] = __float_as_uint(xr[nt * 8]);
                bf[nt][1] = __float_as_uint(xr[nt * 8 + 4 * 136]);
            }
#pragma unroll
            for (int mt = 0; mt < 2; ++mt) {
                const float* wp = wb + (tap * 64 + m0 + mt * 16) * 8;
                float2 aA = *(const float2*)(wp + gr * 8 + tk * 2);
                float2 aB = *(const float2*)(wp + (gr + 8) * 8 + tk * 2);
                uint32_t af[4];
                af[0] = __float_as_uint(aA.x);
                af[1] = __float_as_uint(aB.x);
                af[2] = __float_as_uint(aA.y);
                af[3] = __float_as_uint(aB.y);
#pragma unroll
                for (int nt = 0; nt < 4; ++nt)
                    mma_tf32(d[mt][nt], af, bf[nt]);
            }
        }
        __syncthreads();
        if (cc + 2 < 8) { STAGE(cc + 2, cc & 1); cpa_commit(); }
    }
#undef STAGE

#pragma unroll
    for (int mt = 0; mt < 2; ++mt) {
        int mr = m0 + mt * 16 + gr;
#pragma unroll
        for (int nt = 0; nt < 4; ++nt) {
            int nc = n0 + nt * 8 + tk * 2;
            *(float2*)&Db[mr * 132 + nc] = make_float2(d[mt][nt][0], d[mt][nt][1]);
            *(float2*)&Db[(mr + 8) * 132 + nc] = make_float2(d[mt][nt][2], d[mt][nt][3]);
        }
    }
    __syncthreads();

    long obase = (long)(b * 64) * HW + y * 256 + x0;
    for (int it = 0; it < 32; ++it) {
        int e = it * 256 + tid;
        int px = e & 127, oc = e >> 7;
        float v = Db[oc * 132 + px];
        long o = obase + (long)oc * HW + px;
        if (EPI == 1) v = tf32r(gelu_f(v));
        else if (EPI == 2) {
            float s = 1.f / (1.f + expf(-v));
            v = tf32r(aux1[o] * s + aux2[o]);
        } else if (EPI == 3) v += aux1[o];
        out[o] = v;
    }
}

extern "C" void kernel_launch(void* const* d_in, const int* in_sizes, int n_in,
                              void* d_out, int out_size)
{
    const float* x       = (const float*)d_in[0];
    const float* ref     = (const float*)d_in[1];
    const float* ln1w    = (const float*)d_in[2];
    const float* ln1b    = (const float*)d_in[3];
    const float* ln2w    = (const float*)d_in[4];
    const float* ln2b    = (const float*)d_in[5];
    const float* ln3w    = (const float*)d_in[6];
    const float* ln3b    = (const float*)d_in[7];
    const float* w_kv    = (const float*)d_in[8];
    const float* w_kv_dw = (const float*)d_in[9];
    const float* w_q     = (const float*)d_in[10];
    const float* w_q_dw  = (const float*)d_in[11];
    const float* w_proj  = (const float*)d_in[12];
    const float* temp    = (const float*)d_in[13];
    const float* w_add1  = (const float*)d_in[14];
    const float* w_add2  = (const float*)d_in[15];
    const float* w_mul1  = (const float*)d_in[16];
    const float* w_fuse  = (const float*)d_in[17];
    float* out = (float*)d_out;

    float* pool = nullptr;
    cudaGetSymbolAddress((void**)&pool, g_pool);
    const long SZ = 16777216L, SZ2 = 33554432L;
    float* kv0  = pool;
    float* kv1  = pool + SZ2;
    float* bufA = pool + 2 * SZ2;
    float* bufB = bufA + SZ;
    float* bufC = bufB + SZ;
    float* bufD = bufC + SZ;
    float* bufE = bufD + SZ;
    float* x1   = bufE + SZ;
    float* Mb   = x1 + SZ;
    float* part = Mb + 16384;
    float* wIa1 = part + 294912;
    float* wIa2 = wIa1 + 36864;
    float* wIm  = wIa2 + 36864;
    float* wIf  = wIm + 36864;
    float* wIkv = wIf + 36864;
    float* wIq  = wIkv + 8192;

    cudaFuncSetAttribute(conv3x3_mma<0>, cudaFuncAttributeMaxDynamicSharedMemorySize, CSM);
    cudaFuncSetAttribute(conv3x3_mma<1>, cudaFuncAttributeMaxDynamicSharedMemorySize, CSM);
    cudaFuncSetAttribute(conv3x3_mma<2>, cudaFuncAttributeMaxDynamicSharedMemorySize, CSM);
    cudaFuncSetAttribute(conv3x3_mma<3>, cudaFuncAttributeMaxDynamicSharedMemorySize, CSM);
    cudaFuncSetAttribute((conv1x1_mma<128, true, false, false>), cudaFuncAttributeMaxDynamicSharedMemorySize, CSM1KV);
    cudaFuncSetAttribute((conv1x1_mma<64, true, false, false>), cudaFuncAttributeMaxDynamicSharedMemorySize, CSM1);
    cudaFuncSetAttribute((conv1x1_mma<64, false, true, true>), cudaFuncAttributeMaxDynamicSharedMemorySize, CSM1);

    wprep_kernel<<<144, 256>>>(w_add1, wIa1);
    wprep_kernel<<<144, 256>>>(w_add2, wIa2);
    wprep_kernel<<<144, 256>>>(w_mul1, wIm);
    wprep_kernel<<<144, 256>>>(w_fuse, wIf);
    wprep1_kernel<<<32, 256>>>(w_kv, wIkv, 128);
    wprep1_kernel<<<16, 256>>>(w_q, wIq, 64);

    // ---- Attention branch (mma 1x1s) ----
    conv1x1_mma<128, true, false, false><<<dim3(512, 4), 256, CSM1KV>>>(ref, wIkv, ln1w, ln1b, nullptr, kv0, 64 * HW, 0);
    conv1x1_mma<64, true, false, false><<<dim3(512, 4), 256, CSM1>>>(x, wIq, ln3w, ln3b, nullptr, bufC, 64 * HW, 0);
    dw3x3_kernel<128><<<16384, 256>>>(kv0,  w_kv_dw, kv1);
    dw3x3_kernel<64><<<8192, 256>>>(bufC, w_q_dw, bufD);
    attn_stats_kernel<<<dim3(NCHUNK, 16), 256>>>(bufD, kv1, part);
    attn_finish_kernel<<<4, 256>>>(part, w_proj, temp, Mb);
    conv1x1_mma<64, false, true, true><<<dim3(512, 4), 256, CSM1>>>(kv1, Mb, nullptr, nullptr, x, x1, 128 * HW, 64);

    // ---- SFM branch (mma 3x3s) ----
    ln_kernel<<<1024, 256>>>(x1, ln2w, ln2b, bufA);                                     // y (tf32)
    conv3x3_mma<1><<<dim3(512, 4), 256, CSM>>>(bufA, wIa1, nullptr, nullptr, bufB);     // ga1
    conv3x3_mma<0><<<dim3(512, 4), 256, CSM>>>(bufB, wIa2, nullptr, nullptr, bufC);     // x_add
    conv3x3_mma<1><<<dim3(512, 4), 256, CSM>>>(bufA, wIm, nullptr, nullptr, bufD);      // gm1
    conv3x3_mma<2><<<dim3(512, 4), 256, CSM>>>(bufD, wIm, bufA, bufC, bufE);            // z
    conv3x3_mma<3><<<dim3(512, 4), 256, CSM>>>(bufE, wIf, x1, nullptr, out);            // out
}

// round 13
// speedup vs baseline: 2.4090x; 1.0640x over previous
#include <cuda_runtime.h>
#include <math.h>
#include <stdint.h>

typedef unsigned long long ull;
#define HW 65536
#define NCHUNK 64
#define CSM3 87552
#define CSM1KV 67584
#define CSM1 51200

__device__ float g_pool[168378368];

__device__ __forceinline__ float gelu_f(float v) {
    return 0.5f * v * (1.0f + erff(v * 0.70710678118654752f));
}
__device__ __forceinline__ uint32_t smaddr(const void* p) {
    uint32_t a;
    asm("{.reg .u64 t; cvta.to.shared.u64 t, %1; cvt.u32.u64 %0, t;}" : "=r"(a) : "l"(p));
    return a;
}
__device__ __forceinline__ float tf32r(float f) {
    uint32_t r; asm("cvt.rna.tf32.f32 %0, %1;" : "=r"(r) : "f"(f));
    return __uint_as_float(r);
}
__device__ __forceinline__ void cpa16(uint32_t s, const void* g) {
    asm volatile("cp.async.cg.shared.global [%0], [%1], 16;" :: "r"(s), "l"(g));
}
__device__ __forceinline__ void cpa16z(uint32_t s, const void* g, bool ok) {
    int sz = ok ? 16 : 0;
    asm volatile("cp.async.cg.shared.global [%0], [%1], 16, %2;" :: "r"(s), "l"(g), "r"(sz));
}
__device__ __forceinline__ void cpa_commit() { asm volatile("cp.async.commit_group;"); }
__device__ __forceinline__ void cpa_wait1() { asm volatile("cp.async.wait_group 1;"); }
__device__ __forceinline__ void cpa_wait0() { asm volatile("cp.async.wait_group 0;"); }
__device__ __forceinline__ void mma_tf32(float* d, const uint32_t* a, const uint32_t* b) {
    asm volatile("mma.sync.aligned.m16n8k8.row.col.f32.tf32.tf32.f32 "
        "{%0,%1,%2,%3}, {%4,%5,%6,%7}, {%8,%9}, {%0,%1,%2,%3};"
        : "+f"(d[0]), "+f"(d[1]), "+f"(d[2]), "+f"(d[3])
        : "r"(a[0]), "r"(a[1]), "r"(a[2]), "r"(a[3]), "r"(b[0]), "r"(b[1]));
}

// ---- merged weight prep: four 3x3 images + kv 1x1 + q 1x1 ----
__global__ void wprep_all(const float* __restrict__ wa1, const float* __restrict__ wa2,
                          const float* __restrict__ wm, const float* __restrict__ wf,
                          const float* __restrict__ wkv, const float* __restrict__ wq,
                          float* __restrict__ ia1, float* __restrict__ ia2,
                          float* __restrict__ im, float* __restrict__ iff,
                          float* __restrict__ ikv, float* __restrict__ iq)
{
    int e = blockIdx.x * 256 + threadIdx.x;
    if (e < 147456) {
        int seg = e / 36864, r = e % 36864;
        const float* w = (seg == 0) ? wa1 : (seg == 1) ? wa2 : (seg == 2) ? wm : wf;
        float* img = (seg == 0) ? ia1 : (seg == 1) ? ia2 : (seg == 2) ? im : iff;
        int kp = r & 7, m = (r >> 3) & 63, j = r >> 9;
        int tap = j % 9, c = j / 9;
        int k = (kp >> 1) + ((kp & 1) << 2);
        img[r] = tf32r(w[(m * 64 + c * 8 + k) * 9 + tap]);
    } else if (e < 155648) {
        int r = e - 147456;
        int kp = r & 7, rest = r >> 3, m = rest % 128, cc = rest / 128;
        int k = (kp >> 1) + ((kp & 1) << 2);
        ikv[r] = tf32r(wkv[m * 64 + cc * 8 + k]);
    } else if (e < 159744) {
        int r = e - 155648;
        int kp = r & 7, rest = r >> 3, m = rest & 63, cc = rest >> 6;
        int k = (kp >> 1) + ((kp & 1) << 2);
        iq[r] = tf32r(wq[m * 64 + cc * 8 + k]);
    }
}

// ---- LayerNorm over channels (tf32-rounded) ----
__global__ void ln_kernel(const float* __restrict__ in, const float* __restrict__ w,
                          const float* __restrict__ bb, float* __restrict__ out)
{
    int p = blockIdx.x * blockDim.x + threadIdx.x;
    int b = p >> 16, pix = p & 65535;
    const float* ip = in + (long)b * (64 * HW) + pix;
    float s = 0.f, ss = 0.f;
#pragma unroll 8
    for (int c = 0; c < 64; ++c) { float v = ip[(long)c * HW]; s += v; ss += v * v; }
    float mu = s * (1.0f / 64);
    float var = ss * (1.0f / 64) - mu * mu;
    float r = rsqrtf(var + 1e-5f);
    float* op = out + (long)b * (64 * HW) + pix;
#pragma unroll 8
    for (int c = 0; c < 64; ++c) {
        float v = ip[(long)c * HW];
        op[(long)c * HW] = tf32r((v - mu) * r * w[c] + bb[c]);
    }
}

// ---- 1x1 conv via mma.sync tf32, direct-STG epilogue ----
template<int OC, bool LNORM, bool PBW, bool RES>
__global__ void __launch_bounds__(256, 2)
conv1x1_mma(const float* __restrict__ in, const float* __restrict__ wsrc,
            const float* __restrict__ lnw, const float* __restrict__ lnb,
            const float* __restrict__ res, float* __restrict__ out,
            int in_bstride, int ic_off)
{
    extern __shared__ float smem[];
    float* Xb = smem;            // 64 x 136
    float* Wb = smem + 8704;     // [cc][OC][8k']
    uint32_t sbX = smaddr(Xb), sbW = smaddr(Wb);
    int tid = threadIdx.x, wid = tid >> 5, lane = tid & 31;
    int gr = lane >> 2, tk = lane & 3;
    int b = blockIdx.y, pix0 = blockIdx.x * 128;
    const float* inb = in + (long)b * in_bstride + (long)ic_off * HW + pix0;

    for (int idx = tid; idx < 2048; idx += 256) {
        int c4 = idx & 31, ic = idx >> 5;
        cpa16(sbX + (ic * 136 + c4 * 4) * 4, inb + (long)ic * HW + c4 * 4);
    }
    if (!PBW) {
        const float4* s_ = (const float4*)wsrc;
        for (int t_ = tid; t_ < OC * 16; t_ += 256) cpa16(sbW + t_ * 16, s_ + t_);
    }
    cpa_commit();
    if (PBW) {
        const float* wb = wsrc + b * 64 * OC;
        for (int idx = tid; idx < OC * 64; idx += 256) {
            int kp = idx & 7, rest = idx >> 3;
            int m = rest & (OC - 1), cc = rest / OC;
            int k = (kp >> 1) + ((kp & 1) << 2);
            Wb[idx] = tf32r(wb[m * 64 + cc * 8 + k]);
        }
    }
    cpa_wait0();
    __syncthreads();
    if (LNORM) {
        if (tid < 128) {
            float s = 0.f, ss = 0.f;
#pragma unroll 8
            for (int c = 0; c < 64; ++c) { float v = Xb[c * 136 + tid]; s += v; ss += v * v; }
            float mu = s * (1.f / 64), var = ss * (1.f / 64) - mu * mu;
            float r = rsqrtf(var + 1e-5f);
#pragma unroll 8
            for (int c = 0; c < 64; ++c)
                Xb[c * 136 + tid] = tf32r((Xb[c * 136 + tid] - mu) * r * lnw[c] + lnb[c]);
        }
    } else {
        for (int i = tid; i < 8192; i += 256) {
            int px = i & 127, ic = i >> 7;
            Xb[ic * 136 + px] = tf32r(Xb[ic * 136 + px]);
        }
    }
    __syncthreads();

    constexpr int MT = OC / 32;
    int mw = wid & 1, nw = wid >> 1;
    int m0 = mw * (OC / 2), n0 = nw * 32;
    float d[MT][4][4];
#pragma unroll
    for (int mt = 0; mt < MT; ++mt)
#pragma unroll
        for (int nt = 0; nt < 4; ++nt)
#pragma unroll
            for (int q = 0; q < 4; ++q) d[mt][nt][q] = 0.f;

#pragma unroll
    for (int cc = 0; cc < 8; ++cc) {
        uint32_t bf[4][2];
#pragma unroll
        for (int nt = 0; nt < 4; ++nt) {
            const float* xr = Xb + (cc * 8 + tk) * 136 + n0 + nt * 8 + gr;
            bf[nt][0] = __float_as_uint(xr[0]);
            bf[nt][1] = __float_as_uint(xr[4 * 136]);
        }
#pragma unroll
        for (int mt = 0; mt < MT; ++mt) {
            const float* wp = Wb + (cc * OC + m0 + mt * 16) * 8;
            float2 aA = *(const float2*)(wp + gr * 8 + tk * 2);
            float2 aB = *(const float2*)(wp + (gr + 8) * 8 + tk * 2);
            uint32_t af[4] = {__float_as_uint(aA.x), __float_as_uint(aB.x),
                              __float_as_uint(aA.y), __float_as_uint(aB.y)};
#pragma unroll
            for (int nt = 0; nt < 4; ++nt) mma_tf32(d[mt][nt], af, bf[nt]);
        }
    }
#pragma unroll
    for (int mt = 0; mt < MT; ++mt) {
#pragma unroll
        for (int h2 = 0; h2 < 2; ++h2) {
            int mr = m0 + mt * 16 + gr + h2 * 8;
            long rowo = (long)(b * OC + mr) * HW + pix0;
#pragma unroll
            for (int nt = 0; nt < 4; ++nt) {
                long o = rowo + n0 + nt * 8 + tk * 2;
                float v0 = d[mt][nt][h2 * 2], v1 = d[mt][nt][h2 * 2 + 1];
                if (RES) {
                    float2 rv = *(const float2*)&res[o];
                    v0 += rv.x; v1 += rv.y;
                }
                *(float2*)&out[o] = make_float2(v0, v1);
            }
        }
    }
}

// ---- depthwise 3x3 body + merged launcher ----
template<int CH>
__device__ __forceinline__ void dw_body(const float* __restrict__ in, const float* __restrict__ w,
                                        float* __restrict__ out, int bid)
{
    int p = bid * 256 + threadIdx.x;
    int xg = p & 31, y = (p >> 5) & 255, g = p >> 13;
    int c = g & (CH - 1);
    int x0 = xg * 8;
    const float* wp = w + c * 9;
    float wr[9];
#pragma unroll
    for (int t = 0; t < 9; ++t) wr[t] = wp[t];
    const float* ip = in + (long)g * HW;
    float r[3][10];
    bool interior = (y > 0) && (y < 255) && (xg > 0) && (xg < 31);
    if (interior) {
#pragma unroll
        for (int rr = 0; rr < 3; ++rr) {
            const float* base = ip + (y - 1 + rr) * 256 + x0;
            float4 a = *(const float4*)base;
            float4 bq = *(const float4*)(base + 4);
            r[rr][0] = base[-1];
            r[rr][1] = a.x; r[rr][2] = a.y; r[rr][3] = a.z; r[rr][4] = a.w;
            r[rr][5] = bq.x; r[rr][6] = bq.y; r[rr][7] = bq.z; r[rr][8] = bq.w;
            r[rr][9] = base[8];
        }
    } else {
#pragma unroll
        for (int rr = 0; rr < 3; ++rr) {
            int iy = y - 1 + rr;
#pragma unroll
            for (int j = 0; j < 10; ++j) {
                int ix = x0 - 1 + j;
                r[rr][j] = (iy >= 0 && iy < 256 && ix >= 0 && ix < 256) ? ip[iy * 256 + ix] : 0.f;
            }
        }
    }
    float acc[8];
#pragma unroll
    for (int q = 0; q < 8; ++q) acc[q] = 0.f;
#pragma unroll
    for (int ky = 0; ky < 3; ++ky)
#pragma unroll
        for (int kx = 0; kx < 3; ++kx) {
            float wv = wr[ky * 3 + kx];
#pragma unroll
            for (int q = 0; q < 8; ++q) acc[q] += wv * r[ky][q + kx];
        }
    float* op = out + (long)g * HW + y * 256 + x0;
    *(float4*)op = make_float4(acc[0], acc[1], acc[2], acc[3]);
    *(float4*)(op + 4) = make_float4(acc[4], acc[5], acc[6], acc[7]);
}

__global__ void dw3x3_both(const float* __restrict__ inkv, const float* __restrict__ wkv,
                           float* __restrict__ outkv,
                           const float* __restrict__ inq, const float* __restrict__ wq,
                           float* __restrict__ outq)
{
    int bid = blockIdx.x;
    if (bid < 16384) dw_body<128>(inkv, wkv, outkv, bid);
    else dw_body<64>(inq, wq, outq, bid - 16384);
}

// ---- attention stats ----
__global__ void attn_stats_kernel(const float* __restrict__ q, const float* __restrict__ k,
                                  float* __restrict__ part)
{
    __shared__ float sQ[16 * 129];
    __shared__ float sK[16 * 129];
    int g = blockIdx.y;
    int b = g >> 2, h = g & 3;
    const float* qb = q + (long)b * 64 * HW + (long)h * 16 * HW;
    const float* kb = k + (long)b * 128 * HW + (long)h * 16 * HW;
    int tid = threadIdx.x;
    int c = tid >> 4, d = tid & 15;
    float accG = 0.f, accQ = 0.f, accK = 0.f;
    int nbase = blockIdx.x * (HW / NCHUNK);
    for (int sub = 0; sub < (HW / NCHUNK) / 128; ++sub) {
        int n0 = nbase + sub * 128;
#pragma unroll
        for (int i = 0; i < 8; ++i) {
            int lin = tid + i * 256;
            int cc = lin >> 7, nn = lin & 127;
            sQ[cc * 129 + nn] = qb[(long)cc * HW + n0 + nn];
            sK[cc * 129 + nn] = kb[(long)cc * HW + n0 + nn];
        }
        __syncthreads();
        const float* qr = sQ + c * 129;
        const float* kr = sK + d * 129;
#pragma unroll 8
        for (int nn = 0; nn < 128; ++nn) accG += qr[nn] * kr[nn];
        if (d == 0) {
#pragma unroll 8
            for (int nn = 0; nn < 128; ++nn) accQ += qr[nn] * qr[nn];
        }
        if (c == 0) {
#pragma unroll 8
            for (int nn = 0; nn < 128; ++nn) accK += kr[nn] * kr[nn];
        }
        __syncthreads();
    }
    float* pp = part + ((long)g * NCHUNK + blockIdx.x) * 288;
    pp[tid] = accG;
    if (d == 0) pp[256 + c] = accQ;
    if (c == 0) pp[272 + d] = accK;
}

// ---- softmax + fold W_proj -> M[b][64][64] ----
__global__ void attn_finish_kernel(const float* __restrict__ part, const float* __restrict__ wproj,
                                   const float* __restrict__ temp, float* __restrict__ Mout)
{
    int b = blockIdx.x, tid = threadIdx.x;
    __shared__ float sG[4][256];
    __shared__ float sq[4][16], sk[4][16];
    __shared__ float sA[4][16][16];
    for (int h = 0; h < 4; ++h) {
        const float* pp = part + ((long)(b * 4 + h)) * NCHUNK * 288;
        float s = 0.f;
        for (int ch = 0; ch < NCHUNK; ++ch) s += pp[ch * 288 + tid];
        sG[h][tid] = s;
        if (tid < 32) {
            float s2 = 0.f;
            for (int ch = 0; ch < NCHUNK; ++ch) s2 += pp[ch * 288 + 256 + tid];
            if (tid < 16) sq[h][tid] = s2; else sk[h][tid - 16] = s2;
        }
    }
    __syncthreads();
    if (tid < 64) {
        int h = tid >> 4, c = tid & 15;
        float qn = fmaxf(sqrtf(sq[h][c]), 1e-12f);
        float tp = temp[h];
        float lg[16];
        float mx = -1e30f;
#pragma unroll
        for (int d = 0; d < 16; ++d) {
            float kn = fmaxf(sqrtf(sk[h][d]), 1e-12f);
            lg[d] = tp * sG[h][c * 16 + d] / (qn * kn);
            mx = fmaxf(mx, lg[d]);
        }
        float ssum = 0.f;
#pragma unroll
        for (int d = 0; d < 16; ++d) { lg[d] = expf(lg[d] - mx); ssum += lg[d]; }
        float inv = 1.f / ssum;
#pragma unroll
        for (int d = 0; d < 16; ++d) sA[h][c][d] = lg[d] * inv;
    }
    __syncthreads();
    for (int e = tid; e < 4096; e += 256) {
        int oc = e >> 6, j = e & 63, h = j >> 4, d = j & 15;
        float s = 0.f;
#pragma unroll
        for (int r = 0; r < 16; ++r) s += wproj[oc * 64 + h * 16 + r] * sA[h][r][d];
        Mout[b * 4096 + e] = s;
    }
}

// ---- dense 3x3 conv via mma.sync tf32, M=64, N=256 (full row), direct STG ----
// CTA: 256 thr / 8 warps: mw = wid&1 (32 oc), nw = wid>>1 (64 px).
// Per ic-chunk(8): X = [3 rows][8 ic][264 px], W = [9 taps][64 m][8 k'] ; double-buffered.
// EPI: 0 none, 1 gelu+rnd, 2 mix out=tf32r(aux1*sig(acc)+aux2), 3 acc+aux1 fp32
template<int EPI>
__global__ void __launch_bounds__(256, 2)
conv3x3_mma(const float* __restrict__ in, const float* __restrict__ wimg,
            const float* __restrict__ aux1, const float* __restrict__ aux2,
            float* __restrict__ out)
{
    extern __shared__ float smem[];
    float* Wb = smem;               // 2 x 4608
    float* Xb = smem + 9216;        // 2 x 6336
    uint32_t sbW = smaddr(Wb), sbX = smaddr(Xb);

    int tid = threadIdx.x, wid = tid >> 5, lane = tid & 31;
    int gr = lane >> 2, tk = lane & 3;
    int y = blockIdx.x, b = blockIdx.y;
    const float* inb = in + (long)b * (64 * HW);

#define STAGE(C, BUF) do { \
        for (int idx = tid; idx < 1584; idx += 256) { \
            int c4 = idx % 66; \
            int ri = idx / 66; \
            int ic = ri & 7, row = ri >> 3; \
            int gx = -4 + c4 * 4; \
            int gy = y + row - 1; \
            bool ok = (gx >= 0) && (gx <= 252) && (gy >= 0) && (gy < 256); \
            const float* g_ = inb + (long)((C) * 8 + ic) * HW + gy * 256 + gx; \
            cpa16z(sbX + ((BUF) * 6336 + ri * 264 + c4 * 4) * 4, ok ? g_ : inb, ok); \
        } \
        const float4* s_ = (const float4*)(wimg + (long)(C) * 4608); \
        uint32_t d_ = sbW + (BUF) * 18432; \
        for (int t_ = tid; t_ < 1152; t_ += 256) cpa16(d_ + t_ * 16, s_ + t_); \
    } while (0)

    STAGE(0, 0);
    cpa_commit();
    STAGE(1, 1);
    cpa_commit();

    int mw = wid & 1, nw = wid >> 1;
    int m0 = mw * 32, n0 = nw * 64;
    float d[2][8][4];
#pragma unroll
    for (int mt = 0; mt < 2; ++mt)
#pragma unroll
        for (int nt = 0; nt < 8; ++nt)
#pragma unroll
            for (int q = 0; q < 4; ++q) d[mt][nt][q] = 0.f;

    for (int cc = 0; cc < 8; ++cc) {
        if (cc < 7) cpa_wait1(); else cpa_wait0();
        __syncthreads();
        const float* wb = Wb + (cc & 1) * 4608;
        const float* xb = Xb + (cc & 1) * 6336;
#pragma unroll
        for (int tap = 0; tap < 9; ++tap) {
            int ky = tap / 3, kx = tap - ky * 3;
            const float* xr = xb + (ky * 8 + tk) * 264 + n0 + gr + kx + 3;
            uint32_t bf[8][2];
#pragma unroll
            for (int nt = 0; nt < 8; ++nt) {
                bf[nt][0] = __float_as_uint(xr[nt * 8]);
                bf[nt][1] = __float_as_uint(xr[nt * 8 + 4 * 264]);
            }
#pragma unroll
            for (int mt = 0; mt < 2; ++mt) {
                const float* wp = wb + (tap * 64 + m0 + mt * 16) * 8;
                float2 aA = *(const float2*)(wp + gr * 8 + tk * 2);
                float2 aB = *(const float2*)(wp + (gr + 8) * 8 + tk * 2);
                uint32_t af[4];
                af[0] = __float_as_uint(aA.x);
                af[1] = __float_as_uint(aB.x);
                af[2] = __float_as_uint(aA.y);
                af[3] = __float_as_uint(aB.y);
#pragma unroll
                for (int nt = 0; nt < 8; ++nt)
                    mma_tf32(d[mt][nt], af, bf[nt]);
            }
        }
        __syncthreads();
        if (cc + 2 < 8) { STAGE(cc + 2, cc & 1); cpa_commit(); }
    }
#undef STAGE

    long obase = (long)(b * 64) * HW + y * 256;
#pragma unroll
    for (int mt = 0; mt < 2; ++mt) {
#pragma unroll
        for (int h2 = 0; h2 < 2; ++h2) {
            int mr = m0 + mt * 16 + gr + h2 * 8;
            long rowo = obase + (long)mr * HW;
#pragma unroll
            for (int nt = 0; nt < 8; ++nt) {
                long o = rowo + n0 + nt * 8 + tk * 2;
                float v0 = d[mt][nt][h2 * 2], v1 = d[mt][nt][h2 * 2 + 1];
                if (EPI == 1) {
                    v0 = tf32r(gelu_f(v0));
                    v1 = tf32r(gelu_f(v1));
                } else if (EPI == 2) {
                    float2 a1v = *(const float2*)&aux1[o];
                    float2 a2v = *(const float2*)&aux2[o];
                    v0 = tf32r(a1v.x * (1.f / (1.f + expf(-v0))) + a2v.x);
                    v1 = tf32r(a1v.y * (1.f / (1.f + expf(-v1))) + a2v.y);
                } else if (EPI == 3) {
                    float2 rv = *(const float2*)&aux1[o];
                    v0 += rv.x; v1 += rv.y;
                }
                *(float2*)&out[o] = make_float2(v0, v1);
            }
        }
    }
}

extern "C" void kernel_launch(void* const* d_in, const int* in_sizes, int n_in,
                              void* d_out, int out_size)
{
    const float* x       = (const float*)d_in[0];
    const float* ref     = (const float*)d_in[1];
    const float* ln1w    = (const float*)d_in[2];
    const float* ln1b    = (const float*)d_in[3];
    const float* ln2w    = (const float*)d_in[4];
    const float* ln2b    = (const float*)d_in[5];
    const float* ln3w    = (const float*)d_in[6];
    const float* ln3b    = (const float*)d_in[7];
    const float* w_kv    = (const float*)d_in[8];
    const float* w_kv_dw = (const float*)d_in[9];
    const float* w_q     = (const float*)d_in[10];
    const float* w_q_dw  = (const float*)d_in[11];
    const float* w_proj  = (const float*)d_in[12];
    const float* temp    = (const float*)d_in[13];
    const float* w_add1  = (const float*)d_in[14];
    const float* w_add2  = (const float*)d_in[15];
    const float* w_mul1  = (const float*)d_in[16];
    const float* w_fuse  = (const float*)d_in[17];
    float* out = (float*)d_out;

    float* pool = nullptr;
    cudaGetSymbolAddress((void**)&pool, g_pool);
    const long SZ = 16777216L, SZ2 = 33554432L;
    float* kv0  = pool;
    float* kv1  = pool + SZ2;
    float* bufA = pool + 2 * SZ2;
    float* bufB = bufA + SZ;
    float* bufC = bufB + SZ;
    float* bufD = bufC + SZ;
    float* bufE = bufD + SZ;
    float* x1   = bufE + SZ;
    float* Mb   = x1 + SZ;
    float* part = Mb + 16384;
    float* wIa1 = part + 294912;
    float* wIa2 = wIa1 + 36864;
    float* wIm  = wIa2 + 36864;
    float* wIf  = wIm + 36864;
    float* wIkv = wIf + 36864;
    float* wIq  = wIkv + 8192;

    cudaFuncSetAttribute(conv3x3_mma<0>, cudaFuncAttributeMaxDynamicSharedMemorySize, CSM3);
    cudaFuncSetAttribute(conv3x3_mma<1>, cudaFuncAttributeMaxDynamicSharedMemorySize, CSM3);
    cudaFuncSetAttribute(conv3x3_mma<2>, cudaFuncAttributeMaxDynamicSharedMemorySize, CSM3);
    cudaFuncSetAttribute(conv3x3_mma<3>, cudaFuncAttributeMaxDynamicSharedMemorySize, CSM3);
    cudaFuncSetAttribute((conv1x1_mma<128, true, false, false>), cudaFuncAttributeMaxDynamicSharedMemorySize, CSM1KV);
    cudaFuncSetAttribute((conv1x1_mma<64, true, false, false>), cudaFuncAttributeMaxDynamicSharedMemorySize, CSM1);
    cudaFuncSetAttribute((conv1x1_mma<64, false, true, true>), cudaFuncAttributeMaxDynamicSharedMemorySize, CSM1);

    wprep_all<<<624, 256>>>(w_add1, w_add2, w_mul1, w_fuse, w_kv, w_q,
                            wIa1, wIa2, wIm, wIf, wIkv, wIq);

    // ---- Attention branch ----
    conv1x1_mma<128, true, false, false><<<dim3(512, 4), 256, CSM1KV>>>(ref, wIkv, ln1w, ln1b, nullptr, kv0, 64 * HW, 0);
    conv1x1_mma<64, true, false, false><<<dim3(512, 4), 256, CSM1>>>(x, wIq, ln3w, ln3b, nullptr, bufC, 64 * HW, 0);
    dw3x3_both<<<24576, 256>>>(kv0, w_kv_dw, kv1, bufC, w_q_dw, bufD);
    attn_stats_kernel<<<dim3(NCHUNK, 16), 256>>>(bufD, kv1, part);
    attn_finish_kernel<<<4, 256>>>(part, w_proj, temp, Mb);
    conv1x1_mma<64, false, true, true><<<dim3(512, 4), 256, CSM1>>>(kv1, Mb, nullptr, nullptr, x, x1, 128 * HW, 64);

    // ---- SFM branch ----
    ln_kernel<<<1024, 256>>>(x1, ln2w, ln2b, bufA);                                     // y (tf32)
    conv3x3_mma<1><<<dim3(256, 4), 256, CSM3>>>(bufA, wIa1, nullptr, nullptr, bufB);    // ga1
    conv3x3_mma<0><<<dim3(256, 4), 256, CSM3>>>(bufB, wIa2, nullptr, nullptr, bufC);    // x_add
    conv3x3_mma<1><<<dim3(256, 4), 256, CSM3>>>(bufA, wIm, nullptr, nullptr, bufD);     // gm1
    conv3x3_mma<2><<<dim3(256, 4), 256, CSM3>>>(bufD, wIm, bufA, bufC, bufE);           // z
    conv3x3_mma<3><<<dim3(256, 4), 256, CSM3>>>(bufE, wIf, x1, nullptr, out);           // out
}

// round 15
// speedup vs baseline: 2.4927x; 1.0347x over previous
#include <cuda_runtime.h>
#include <math.h>
#include <stdint.h>

typedef unsigned long long ull;
#define HW 65536
#define NCHUNK 64
#define CSM3 87552
#define CSM1KV 67584
#define CSM1R 84224

__device__ float g_pool[168378368];

__device__ __forceinline__ float gelu_f(float v) {
    return 0.5f * v * (1.0f + erff(v * 0.70710678118654752f));
}
__device__ __forceinline__ uint32_t smaddr(const void* p) {
    uint32_t a;
    asm("{.reg .u64 t; cvta.to.shared.u64 t, %1; cvt.u32.u64 %0, t;}" : "=r"(a) : "l"(p));
    return a;
}
__device__ __forceinline__ float tf32r(float f) {
    uint32_t r; asm("cvt.rna.tf32.f32 %0, %1;" : "=r"(r) : "f"(f));
    return __uint_as_float(r);
}
__device__ __forceinline__ void cpa16(uint32_t s, const void* g) {
    asm volatile("cp.async.cg.shared.global [%0], [%1], 16;" :: "r"(s), "l"(g));
}
__device__ __forceinline__ void cpa16z(uint32_t s, const void* g, bool ok) {
    int sz = ok ? 16 : 0;
    asm volatile("cp.async.cg.shared.global [%0], [%1], 16, %2;" :: "r"(s), "l"(g), "r"(sz));
}
__device__ __forceinline__ void cpa_commit() { asm volatile("cp.async.commit_group;"); }
__device__ __forceinline__ void cpa_wait1() { asm volatile("cp.async.wait_group 1;"); }
__device__ __forceinline__ void cpa_wait0() { asm volatile("cp.async.wait_group 0;"); }
__device__ __forceinline__ void mma_tf32(float* d, const uint32_t* a, const uint32_t* b) {
    asm volatile("mma.sync.aligned.m16n8k8.row.col.f32.tf32.tf32.f32 "
        "{%0,%1,%2,%3}, {%4,%5,%6,%7}, {%8,%9}, {%0,%1,%2,%3};"
        : "+f"(d[0]), "+f"(d[1]), "+f"(d[2]), "+f"(d[3])
        : "r"(a[0]), "r"(a[1]), "r"(a[2]), "r"(a[3]), "r"(b[0]), "r"(b[1]));
}

// ---- merged weight prep: four 3x3 images + kv 1x1 + q 1x1 ----
__global__ void wprep_all(const float* __restrict__ wa1, const float* __restrict__ wa2,
                          const float* __restrict__ wm, const float* __restrict__ wf,
                          const float* __restrict__ wkv, const float* __restrict__ wq,
                          float* __restrict__ ia1, float* __restrict__ ia2,
                          float* __restrict__ im, float* __restrict__ iff,
                          float* __restrict__ ikv, float* __restrict__ iq)
{
    int e = blockIdx.x * 256 + threadIdx.x;
    if (e < 147456) {
        int seg = e / 36864, r = e % 36864;
        const float* w = (seg == 0) ? wa1 : (seg == 1) ? wa2 : (seg == 2) ? wm : wf;
        float* img = (seg == 0) ? ia1 : (seg == 1) ? ia2 : (seg == 2) ? im : iff;
        int kp = r & 7, m = (r >> 3) & 63, j = r >> 9;
        int tap = j % 9, c = j / 9;
        int k = (kp >> 1) + ((kp & 1) << 2);
        img[r] = tf32r(w[(m * 64 + c * 8 + k) * 9 + tap]);
    } else if (e < 155648) {
        int r = e - 147456;
        int kp = r & 7, rest = r >> 3, m = rest % 128, cc = rest / 128;
        int k = (kp >> 1) + ((kp & 1) << 2);
        ikv[r] = tf32r(wkv[m * 64 + cc * 8 + k]);
    } else if (e < 159744) {
        int r = e - 155648;
        int kp = r & 7, rest = r >> 3, m = rest & 63, cc = rest >> 6;
        int k = (kp >> 1) + ((kp & 1) << 2);
        iq[r] = tf32r(wq[m * 64 + cc * 8 + k]);
    }
}

// ---- LayerNorm over channels (tf32-rounded) ----
__global__ void ln_kernel(const float* __restrict__ in, const float* __restrict__ w,
                          const float* __restrict__ bb, float* __restrict__ out)
{
    int p = blockIdx.x * blockDim.x + threadIdx.x;
    int b = p >> 16, pix = p & 65535;
    const float* ip = in + (long)b * (64 * HW) + pix;
    float s = 0.f, ss = 0.f;
#pragma unroll 8
    for (int c = 0; c < 64; ++c) { float v = ip[(long)c * HW]; s += v; ss += v * v; }
    float mu = s * (1.0f / 64);
    float var = ss * (1.0f / 64) - mu * mu;
    float r = rsqrtf(var + 1e-5f);
    float* op = out + (long)b * (64 * HW) + pix;
#pragma unroll 8
    for (int c = 0; c < 64; ++c) {
        float v = ip[(long)c * HW];
        op[(long)c * HW] = tf32r((v - mu) * r * w[c] + bb[c]);
    }
}

// ---- 1x1 conv OC=128 (kv), N=128, fused LN, direct STG ----
__global__ void __launch_bounds__(256, 2)
conv1x1_kv(const float* __restrict__ in, const float* __restrict__ wsrc,
           const float* __restrict__ lnw, const float* __restrict__ lnb,
           float* __restrict__ out)
{
    constexpr int OC = 128;
    extern __shared__ float smem[];
    float* Xb = smem;            // 64 x 136
    float* Wb = smem + 8704;     // [cc][128][8k']
    uint32_t sbX = smaddr(Xb), sbW = smaddr(Wb);
    int tid = threadIdx.x, wid = tid >> 5, lane = tid & 31;
    int gr = lane >> 2, tk = lane & 3;
    int b = blockIdx.y, pix0 = blockIdx.x * 128;
    const float* inb = in + (long)b * (64 * HW) + pix0;

    for (int idx = tid; idx < 2048; idx += 256) {
        int c4 = idx & 31, ic = idx >> 5;
        cpa16(sbX + (ic * 136 + c4 * 4) * 4, inb + (long)ic * HW + c4 * 4);
    }
    {
        const float4* s_ = (const float4*)wsrc;
        for (int t_ = tid; t_ < 2048, t_ < OC * 16; t_ += 256) cpa16(sbW + t_ * 16, s_ + t_);
    }
    cpa_commit();
    cpa_wait0();
    __syncthreads();
    if (tid < 128) {
        float s = 0.f, ss = 0.f;
#pragma unroll 8
        for (int c = 0; c < 64; ++c) { float v = Xb[c * 136 + tid]; s += v; ss += v * v; }
        float mu = s * (1.f / 64), var = ss * (1.f / 64) - mu * mu;
        float r = rsqrtf(var + 1e-5f);
#pragma unroll 8
        for (int c = 0; c < 64; ++c)
            Xb[c * 136 + tid] = tf32r((Xb[c * 136 + tid] - mu) * r * lnw[c] + lnb[c]);
    }
    __syncthreads();

    int mw = wid & 1, nw = wid >> 1;
    int m0 = mw * 64, n0 = nw * 32;
    float d[4][4][4];
#pragma unroll
    for (int mt = 0; mt < 4; ++mt)
#pragma unroll
        for (int nt = 0; nt < 4; ++nt)
#pragma unroll
            for (int q = 0; q < 4; ++q) d[mt][nt][q] = 0.f;

#pragma unroll
    for (int cc = 0; cc < 8; ++cc) {
        uint32_t bf[4][2];
#pragma unroll
        for (int nt = 0; nt < 4; ++nt) {
            const float* xr = Xb + (cc * 8 + tk) * 136 + n0 + nt * 8 + gr;
            bf[nt][0] = __float_as_uint(xr[0]);
            bf[nt][1] = __float_as_uint(xr[4 * 136]);
        }
#pragma unroll
        for (int mt = 0; mt < 4; ++mt) {
            const float* wp = Wb + (cc * OC + m0 + mt * 16) * 8;
            float2 aA = *(const float2*)(wp + gr * 8 + tk * 2);
            float2 aB = *(const float2*)(wp + (gr + 8) * 8 + tk * 2);
            uint32_t af[4] = {__float_as_uint(aA.x), __float_as_uint(aB.x),
                              __float_as_uint(aA.y), __float_as_uint(aB.y)};
#pragma unroll
            for (int nt = 0; nt < 4; ++nt) mma_tf32(d[mt][nt], af, bf[nt]);
        }
    }
#pragma unroll
    for (int mt = 0; mt < 4; ++mt) {
#pragma unroll
        for (int h2 = 0; h2 < 2; ++h2) {
            int mr = m0 + mt * 16 + gr + h2 * 8;
            long rowo = (long)(b * OC + mr) * HW + pix0;
#pragma unroll
            for (int nt = 0; nt < 4; ++nt) {
                long o = rowo + n0 + nt * 8 + tk * 2;
                *(float2*)&out[o] = make_float2(d[mt][nt][h2 * 2], d[mt][nt][h2 * 2 + 1]);
            }
        }
    }
}

// ---- 1x1 conv OC=64, N=256 full row (q and v paths), direct STG ----
template<bool LNORM, bool PBW, bool RES>
__global__ void __launch_bounds__(256, 2)
conv1x1r_mma(const float* __restrict__ in, const float* __restrict__ wsrc,
             const float* __restrict__ lnw, const float* __restrict__ lnb,
             const float* __restrict__ res, float* __restrict__ out,
             int in_bstride, int ic_off)
{
    extern __shared__ float smem[];
    float* Xb = smem;            // 64 x 264
    float* Wb = smem + 16896;    // [cc][64][8k']
    uint32_t sbX = smaddr(Xb), sbW = smaddr(Wb);
    int tid = threadIdx.x, wid = tid >> 5, lane = tid & 31;
    int gr = lane >> 2, tk = lane & 3;
    int b = blockIdx.y, pix0 = blockIdx.x * 256;
    const float* inb = in + (long)b * in_bstride + (long)ic_off * HW + pix0;

    for (int idx = tid; idx < 4096; idx += 256) {
        int c4 = idx & 63, ic = idx >> 6;
        cpa16(sbX + (ic * 264 + c4 * 4) * 4, inb + (long)ic * HW + c4 * 4);
    }
    if (!PBW) {
        const float4* s_ = (const float4*)wsrc;
        for (int t_ = tid; t_ < 1024; t_ += 256) cpa16(sbW + t_ * 16, s_ + t_);
    }
    cpa_commit();
    if (PBW) {
        const float* wb = wsrc + b * 4096;
        for (int idx = tid; idx < 4096; idx += 256) {
            int kp = idx & 7, rest = idx >> 3;
            int m = rest & 63, cc = rest >> 6;
            int k = (kp >> 1) + ((kp & 1) << 2);
            Wb[idx] = tf32r(wb[m * 64 + cc * 8 + k]);
        }
    }
    cpa_wait0();
    __syncthreads();
    if (LNORM) {
        float s = 0.f, ss = 0.f;
#pragma unroll 8
        for (int c = 0; c < 64; ++c) { float v = Xb[c * 264 + tid]; s += v; ss += v * v; }
        float mu = s * (1.f / 64), var = ss * (1.f / 64) - mu * mu;
        float r = rsqrtf(var + 1e-5f);
#pragma unroll 8
        for (int c = 0; c < 64; ++c)
            Xb[c * 264 + tid] = tf32r((Xb[c * 264 + tid] - mu) * r * lnw[c] + lnb[c]);
    } else {
        for (int i = tid; i < 16384; i += 256) {
            int px = i & 255, ic = i >> 8;
            Xb[ic * 264 + px] = tf32r(Xb[ic * 264 + px]);
        }
    }
    __syncthreads();

    int mw = wid & 1, nw = wid >> 1;
    int m0 = mw * 32, n0 = nw * 64;
    float d[2][8][4];
#pragma unroll
    for (int mt = 0; mt < 2; ++mt)
#pragma unroll
        for (int nt = 0; nt < 8; ++nt)
#pragma unroll
            for (int q = 0; q < 4; ++q) d[mt][nt][q] = 0.f;

#pragma unroll
    for (int cc = 0; cc < 8; ++cc) {
        uint32_t bf[8][2];
#pragma unroll
        for (int nt = 0; nt < 8; ++nt) {
            const float* xr = Xb + (cc * 8 + tk) * 264 + n0 + nt * 8 + gr;
            bf[nt][0] = __float_as_uint(xr[0]);
            bf[nt][1] = __float_as_uint(xr[4 * 264]);
        }
#pragma unroll
        for (int mt = 0; mt < 2; ++mt) {
            const float* wp = Wb + (cc * 64 + m0 + mt * 16) * 8;
            float2 aA = *(const float2*)(wp + gr * 8 + tk * 2);
            float2 aB = *(const float2*)(wp + (gr + 8) * 8 + tk * 2);
            uint32_t af[4] = {__float_as_uint(aA.x), __float_as_uint(aB.x),
                              __float_as_uint(aA.y), __float_as_uint(aB.y)};
#pragma unroll
            for (int nt = 0; nt < 8; ++nt) mma_tf32(d[mt][nt], af, bf[nt]);
        }
    }
#pragma unroll
    for (int mt = 0; mt < 2; ++mt) {
#pragma unroll
        for (int h2 = 0; h2 < 2; ++h2) {
            int mr = m0 + mt * 16 + gr + h2 * 8;
            long rowo = (long)(b * 64 + mr) * HW + pix0;
#pragma unroll
            for (int nt = 0; nt < 8; ++nt) {
                long o = rowo + n0 + nt * 8 + tk * 2;
                float v0 = d[mt][nt][h2 * 2], v1 = d[mt][nt][h2 * 2 + 1];
                if (RES) {
                    float2 rv = *(const float2*)&res[o];
                    v0 += rv.x; v1 += rv.y;
                }
                *(float2*)&out[o] = make_float2(v0, v1);
            }
        }
    }
}

// ---- depthwise 3x3: 2 rows x 8 px per thread ----
template<int CH>
__device__ __forceinline__ void dw_body(const float* __restrict__ in, const float* __restrict__ w,
                                        float* __restrict__ out, int bid)
{
    int p = bid * 256 + threadIdx.x;
    int xg = p & 31, yq = (p >> 5) & 127, g = p >> 12;
    int c = g & (CH - 1);
    int x0 = xg * 8, y0 = yq * 2;
    const float* wp = w + c * 9;
    float wr[9];
#pragma unroll
    for (int t = 0; t < 9; ++t) wr[t] = wp[t];
    const float* ip = in + (long)g * HW;
    float r[4][10];
    bool interior = (yq > 0) && (yq < 127) && (xg > 0) && (xg < 31);
    if (interior) {
#pragma unroll
        for (int rr = 0; rr < 4; ++rr) {
            const float* base = ip + (y0 - 1 + rr) * 256 + x0;
            float4 a = *(const float4*)base;
            float4 bq = *(const float4*)(base + 4);
            r[rr][0] = base[-1];
            r[rr][1] = a.x; r[rr][2] = a.y; r[rr][3] = a.z; r[rr][4] = a.w;
            r[rr][5] = bq.x; r[rr][6] = bq.y; r[rr][7] = bq.z; r[rr][8] = bq.w;
            r[rr][9] = base[8];
        }
    } else {
#pragma unroll
        for (int rr = 0; rr < 4; ++rr) {
            int iy = y0 - 1 + rr;
#pragma unroll
            for (int j = 0; j < 10; ++j) {
                int ix = x0 - 1 + j;
                r[rr][j] = (iy >= 0 && iy < 256 && ix >= 0 && ix < 256) ? ip[iy * 256 + ix] : 0.f;
            }
        }
    }
    float acc[2][8];
#pragma unroll
    for (int rr = 0; rr < 2; ++rr)
#pragma unroll
        for (int q = 0; q < 8; ++q) acc[rr][q] = 0.f;
#pragma unroll
    for (int ky = 0; ky < 3; ++ky)
#pragma unroll
        for (int kx = 0; kx < 3; ++kx) {
            float wv = wr[ky * 3 + kx];
#pragma unroll
            for (int rr = 0; rr < 2; ++rr)
#pragma unroll
                for (int q = 0; q < 8; ++q) acc[rr][q] += wv * r[rr + ky][q + kx];
        }
#pragma unroll
    for (int rr = 0; rr < 2; ++rr) {
        float* op = out + (long)g * HW + (y0 + rr) * 256 + x0;
        *(float4*)op = make_float4(acc[rr][0], acc[rr][1], acc[rr][2], acc[rr][3]);
        *(float4*)(op + 4) = make_float4(acc[rr][4], acc[rr][5], acc[rr][6], acc[rr][7]);
    }
}

__global__ void dw3x3_both(const float* __restrict__ inkv, const float* __restrict__ wkv,
                           float* __restrict__ outkv,
                           const float* __restrict__ inq, const float* __restrict__ wq,
                           float* __restrict__ outq)
{
    int bid = blockIdx.x;
    if (bid < 8192) dw_body<128>(inkv, wkv, outkv, bid);
    else dw_body<64>(inq, wq, outq, bid - 8192);
}

// ---- attention stats ----
__global__ void attn_stats_kernel(const float* __restrict__ q, const float* __restrict__ k,
                                  float* __restrict__ part)
{
    __shared__ float sQ[16 * 129];
    __shared__ float sK[16 * 129];
    int g = blockIdx.y;
    int b = g >> 2, h = g & 3;
    const float* qb = q + (long)b * 64 * HW + (long)h * 16 * HW;
    const float* kb = k + (long)b * 128 * HW + (long)h * 16 * HW;
    int tid = threadIdx.x;
    int c = tid >> 4, d = tid & 15;
    float accG = 0.f, accQ = 0.f, accK = 0.f;
    int nbase = blockIdx.x * (HW / NCHUNK);
    for (int sub = 0; sub < (HW / NCHUNK) / 128; ++sub) {
        int n0 = nbase + sub * 128;
#pragma unroll
        for (int i = 0; i < 8; ++i) {
            int lin = tid + i * 256;
            int cc = lin >> 7, nn = lin & 127;
            sQ[cc * 129 + nn] = qb[(long)cc * HW + n0 + nn];
            sK[cc * 129 + nn] = kb[(long)cc * HW + n0 + nn];
        }
        __syncthreads();
        const float* qr = sQ + c * 129;
        const float* kr = sK + d * 129;
#pragma unroll 8
        for (int nn = 0; nn < 128; ++nn) accG += qr[nn] * kr[nn];
        if (d == 0) {
#pragma unroll 8
            for (int nn = 0; nn < 128; ++nn) accQ += qr[nn] * qr[nn];
        }
        if (c == 0) {
#pragma unroll 8
            for (int nn = 0; nn < 128; ++nn) accK += kr[nn] * kr[nn];
        }
        __syncthreads();
    }
    float* pp = part + ((long)g * NCHUNK + blockIdx.x) * 288;
    pp[tid] = accG;
    if (d == 0) pp[256 + c] = accQ;
    if (c == 0) pp[272 + d] = accK;
}

// ---- softmax + fold W_proj -> M[b][64][64] ----
__global__ void attn_finish_kernel(const float* __restrict__ part, const float* __restrict__ wproj,
                                   const float* __restrict__ temp, float* __restrict__ Mout)
{
    int b = blockIdx.x, tid = threadIdx.x;
    __shared__ float sG[4][256];
    __shared__ float sq[4][16], sk[4][16];
    __shared__ float sA[4][16][16];
    for (int h = 0; h < 4; ++h) {
        const float* pp = part + ((long)(b * 4 + h)) * NCHUNK * 288;
        float s = 0.f;
        for (int ch = 0; ch < NCHUNK; ++ch) s += pp[ch * 288 + tid];
        sG[h][tid] = s;
        if (tid < 32) {
            float s2 = 0.f;
            for (int ch = 0; ch < NCHUNK; ++ch) s2 += pp[ch * 288 + 256 + tid];
            if (tid < 16) sq[h][tid] = s2; else sk[h][tid - 16] = s2;
        }
    }
    __syncthreads();
    if (tid < 64) {
        int h = tid >> 4, c = tid & 15;
        float qn = fmaxf(sqrtf(sq[h][c]), 1e-12f);
        float tp = temp[h];
        float lg[16];
        float mx = -1e30f;
#pragma unroll
        for (int d = 0; d < 16; ++d) {
            float kn = fmaxf(sqrtf(sk[h][d]), 1e-12f);
            lg[d] = tp * sG[h][c * 16 + d] / (qn * kn);
            mx = fmaxf(mx, lg[d]);
        }
        float ssum = 0.f;
#pragma unroll
        for (int d = 0; d < 16; ++d) { lg[d] = expf(lg[d] - mx); ssum += lg[d]; }
        float inv = 1.f / ssum;
#pragma unroll
        for (int d = 0; d < 16; ++d) sA[h][c][d] = lg[d] * inv;
    }
    __syncthreads();
    for (int e = tid; e < 4096; e += 256) {
        int oc = e >> 6, j = e & 63, h = j >> 4, d = j & 15;
        float s = 0.f;
#pragma unroll
        for (int r = 0; r < 16; ++r) s += wproj[oc * 64 + h * 16 + r] * sA[h][r][d];
        Mout[b * 4096 + e] = s;
    }
}

// ---- dense 3x3 conv via mma.sync tf32, M=64, N=256 (full row), direct STG ----
template<int EPI>
__global__ void __launch_bounds__(256, 2)
conv3x3_mma(const float* __restrict__ in, const float* __restrict__ wimg,
            const float* __restrict__ aux1, const float* __restrict__ aux2,
            float* __restrict__ out)
{
    extern __shared__ float smem[];
    float* Wb = smem;               // 2 x 4608
    float* Xb = smem + 9216;        // 2 x 6336
    uint32_t sbW = smaddr(Wb), sbX = smaddr(Xb);

    int tid = threadIdx.x, wid = tid >> 5, lane = tid & 31;
    int gr = lane >> 2, tk = lane & 3;
    int y = blockIdx.x, b = blockIdx.y;
    const float* inb = in + (long)b * (64 * HW);

#define STAGE(C, BUF) do { \
        for (int idx = tid; idx < 1584; idx += 256) { \
            int c4 = idx % 66; \
            int ri = idx / 66; \
            int ic = ri & 7, row = ri >> 3; \
            int gx = -4 + c4 * 4; \
            int gy = y + row - 1; \
            bool ok = (gx >= 0) && (gx <= 252) && (gy >= 0) && (gy < 256); \
            const float* g_ = inb + (long)((C) * 8 + ic) * HW + gy * 256 + gx; \
            cpa16z(sbX + ((BUF) * 6336 + ri * 264 + c4 * 4) * 4, ok ? g_ : inb, ok); \
        } \
        const float4* s_ = (const float4*)(wimg + (long)(C) * 4608); \
        uint32_t d_ = sbW + (BUF) * 18432; \
        for (int t_ = tid; t_ < 1152; t_ += 256) cpa16(d_ + t_ * 16, s_ + t_); \
    } while (0)

    STAGE(0, 0);
    cpa_commit();
    STAGE(1, 1);
    cpa_commit();

    int mw = wid & 1, nw = wid >> 1;
    int m0 = mw * 32, n0 = nw * 64;
    float d[2][8][4];
#pragma unroll
    for (int mt = 0; mt < 2; ++mt)
#pragma unroll
        for (int nt = 0; nt < 8; ++nt)
#pragma unroll
            for (int q = 0; q < 4; ++q) d[mt][nt][q] = 0.f;

    for (int cc = 0; cc < 8; ++cc) {
        if (cc < 7) cpa_wait1(); else cpa_wait0();
        __syncthreads();
        const float* wb = Wb + (cc & 1) * 4608;
        const float* xb = Xb + (cc & 1) * 6336;
#pragma unroll
        for (int tap = 0; tap < 9; ++tap) {
            int ky = tap / 3, kx = tap - ky * 3;
            const float* xr = xb + (ky * 8 + tk) * 264 + n0 + gr + kx + 3;
            uint32_t bf[8][2];
#pragma unroll
            for (int nt = 0; nt < 8; ++nt) {
                bf[nt][0] = __float_as_uint(xr[nt * 8]);
                bf[nt][1] = __float_as_uint(xr[nt * 8 + 4 * 264]);
            }
#pragma unroll
            for (int mt = 0; mt < 2; ++mt) {
                const float* wp = wb + (tap * 64 + m0 + mt * 16) * 8;
                float2 aA = *(const float2*)(wp + gr * 8 + tk * 2);
                float2 aB = *(const float2*)(wp + (gr + 8) * 8 + tk * 2);
                uint32_t af[4];
                af[0] = __float_as_uint(aA.x);
                af[1] = __float_as_uint(aB.x);
                af[2] = __float_as_uint(aA.y);
                af[3] = __float_as_uint(aB.y);
#pragma unroll
                for (int nt = 0; nt < 8; ++nt)
                    mma_tf32(d[mt][nt], af, bf[nt]);
            }
        }
        __syncthreads();
        if (cc + 2 < 8) { STAGE(cc + 2, cc & 1); cpa_commit(); }
    }
#undef STAGE

    long obase = (long)(b * 64) * HW + y * 256;
#pragma unroll
    for (int mt = 0; mt < 2; ++mt) {
#pragma unroll
        for (int h2 = 0; h2 < 2; ++h2) {
            int mr = m0 + mt * 16 + gr + h2 * 8;
            long rowo = obase + (long)mr * HW;
#pragma unroll
            for (int nt = 0; nt < 8; ++nt) {
                long o = rowo + n0 + nt * 8 + tk * 2;
                float v0 = d[mt][nt][h2 * 2], v1 = d[mt][nt][h2 * 2 + 1];
                if (EPI == 1) {
                    v0 = tf32r(gelu_f(v0));
                    v1 = tf32r(gelu_f(v1));
                } else if (EPI == 2) {
                    float2 a1v = *(const float2*)&aux1[o];
                    float2 a2v = *(const float2*)&aux2[o];
                    v0 = tf32r(a1v.x * (1.f / (1.f + expf(-v0))) + a2v.x);
                    v1 = tf32r(a1v.y * (1.f / (1.f + expf(-v1))) + a2v.y);
                } else if (EPI == 3) {
                    float2 rv = *(const float2*)&aux1[o];
                    v0 += rv.x; v1 += rv.y;
                }
                *(float2*)&out[o] = make_float2(v0, v1);
            }
        }
    }
}

extern "C" void kernel_launch(void* const* d_in, const int* in_sizes, int n_in,
                              void* d_out, int out_size)
{
    const float* x       = (const float*)d_in[0];
    const float* ref     = (const float*)d_in[1];
    const float* ln1w    = (const float*)d_in[2];
    const float* ln1b    = (const float*)d_in[3];
    const float* ln2w    = (const float*)d_in[4];
    const float* ln2b    = (const float*)d_in[5];
    const float* ln3w    = (const float*)d_in[6];
    const float* ln3b    = (const float*)d_in[7];
    const float* w_kv    = (const float*)d_in[8];
    const float* w_kv_dw = (const float*)d_in[9];
    const float* w_q     = (const float*)d_in[10];
    const float* w_q_dw  = (const float*)d_in[11];
    const float* w_proj  = (const float*)d_in[12];
    const float* temp    = (const float*)d_in[13];
    const float* w_add1  = (const float*)d_in[14];
    const float* w_add2  = (const float*)d_in[15];
    const float* w_mul1  = (const float*)d_in[16];
    const float* w_fuse  = (const float*)d_in[17];
    float* out = (float*)d_out;

    float* pool = nullptr;
    cudaGetSymbolAddress((void**)&pool, g_pool);
    const long SZ = 16777216L, SZ2 = 33554432L;
    float* kv0  = pool;
    float* kv1  = pool + SZ2;
    float* bufA = pool + 2 * SZ2;
    float* bufB = bufA + SZ;
    float* bufC = bufB + SZ;
    float* bufD = bufC + SZ;
    float* bufE = bufD + SZ;
    float* x1   = bufE + SZ;
    float* Mb   = x1 + SZ;
    float* part = Mb + 16384;
    float* wIa1 = part + 294912;
    float* wIa2 = wIa1 + 36864;
    float* wIm  = wIa2 + 36864;
    float* wIf  = wIm + 36864;
    float* wIkv = wIf + 36864;
    float* wIq  = wIkv + 8192;

    cudaFuncSetAttribute(conv3x3_mma<0>, cudaFuncAttributeMaxDynamicSharedMemorySize, CSM3);
    cudaFuncSetAttribute(conv3x3_mma<1>, cudaFuncAttributeMaxDynamicSharedMemorySize, CSM3);
    cudaFuncSetAttribute(conv3x3_mma<2>, cudaFuncAttributeMaxDynamicSharedMemorySize, CSM3);
    cudaFuncSetAttribute(conv3x3_mma<3>, cudaFuncAttributeMaxDynamicSharedMemorySize, CSM3);
    cudaFuncSetAttribute(conv1x1_kv, cudaFuncAttributeMaxDynamicSharedMemorySize, CSM1KV);
    cudaFuncSetAttribute((conv1x1r_mma<true, false, false>), cudaFuncAttributeMaxDynamicSharedMemorySize, CSM1R);
    cudaFuncSetAttribute((conv1x1r_mma<false, true, true>), cudaFuncAttributeMaxDynamicSharedMemorySize, CSM1R);

    wprep_all<<<624, 256>>>(w_add1, w_add2, w_mul1, w_fuse, w_kv, w_q,
                            wIa1, wIa2, wIm, wIf, wIkv, wIq);

    // ---- Attention branch ----
    conv1x1_kv<<<dim3(512, 4), 256, CSM1KV>>>(ref, wIkv, ln1w, ln1b, kv0);
    conv1x1r_mma<true, false, false><<<dim3(256, 4), 256, CSM1R>>>(x, wIq, ln3w, ln3b, nullptr, bufC, 64 * HW, 0);
    dw3x3_both<<<12288, 256>>>(kv0, w_kv_dw, kv1, bufC, w_q_dw, bufD);
    attn_stats_kernel<<<dim3(NCHUNK, 16), 256>>>(bufD, kv1, part);
    attn_finish_kernel<<<4, 256>>>(part, w_proj, temp, Mb);
    conv1x1r_mma<false, true, true><<<dim3(256, 4), 256, CSM1R>>>(kv1, Mb, nullptr, nullptr, x, x1, 128 * HW, 64);

    // ---- SFM branch ----
    ln_kernel<<<1024, 256>>>(x1, ln2w, ln2b, bufA);                                     // y (tf32)
    conv3x3_mma<1><<<dim3(256, 4), 256, CSM3>>>(bufA, wIa1, nullptr, nullptr, bufB);    // ga1
    conv3x3_mma<0><<<dim3(256, 4), 256, CSM3>>>(bufB, wIa2, nullptr, nullptr, bufC);    // x_add
    conv3x3_mma<1><<<dim3(256, 4), 256, CSM3>>>(bufA, wIm, nullptr, nullptr, bufD);     // gm1
    conv3x3_mma<2><<<dim3(256, 4), 256, CSM3>>>(bufD, wIm, bufA, bufC, bufE);           // z
    conv3x3_mma<3><<<dim3(256, 4), 256, CSM3>>>(bufE, wIf, x1, nullptr, out);           // out
}

// round 16
// speedup vs baseline: 2.5439x; 1.0206x over previous
#include <cuda_runtime.h>
#include <math.h>
#include <stdint.h>

typedef unsigned long long ull;
#define HW 65536
#define NCHUNK 64
#define CSM3 87552
#define CSM1KV 67584
#define CSM1R 84224

__device__ float g_pool[168378368];

__device__ __forceinline__ float gelu_f(float v) {
    return 0.5f * v * (1.0f + erff(v * 0.70710678118654752f));
}
__device__ __forceinline__ uint32_t smaddr(const void* p) {
    uint32_t a;
    asm("{.reg .u64 t; cvta.to.shared.u64 t, %1; cvt.u32.u64 %0, t;}" : "=r"(a) : "l"(p));
    return a;
}
__device__ __forceinline__ float tf32r(float f) {
    uint32_t r; asm("cvt.rna.tf32.f32 %0, %1;" : "=r"(r) : "f"(f));
    return __uint_as_float(r);
}
__device__ __forceinline__ void cpa16(uint32_t s, const void* g) {
    asm volatile("cp.async.cg.shared.global [%0], [%1], 16;" :: "r"(s), "l"(g));
}
__device__ __forceinline__ void cpa16z(uint32_t s, const void* g, bool ok) {
    int sz = ok ? 16 : 0;
    asm volatile("cp.async.cg.shared.global [%0], [%1], 16, %2;" :: "r"(s), "l"(g), "r"(sz));
}
__device__ __forceinline__ void cpa_commit() { asm volatile("cp.async.commit_group;"); }
__device__ __forceinline__ void cpa_wait1() { asm volatile("cp.async.wait_group 1;"); }
__device__ __forceinline__ void cpa_wait0() { asm volatile("cp.async.wait_group 0;"); }
__device__ __forceinline__ void mma_tf32(float* d, const uint32_t* a, const uint32_t* b) {
    asm volatile("mma.sync.aligned.m16n8k8.row.col.f32.tf32.tf32.f32 "
        "{%0,%1,%2,%3}, {%4,%5,%6,%7}, {%8,%9}, {%0,%1,%2,%3};"
        : "+f"(d[0]), "+f"(d[1]), "+f"(d[2]), "+f"(d[3])
        : "r"(a[0]), "r"(a[1]), "r"(a[2]), "r"(a[3]), "r"(b[0]), "r"(b[1]));
}

// ---- merged weight prep ----
__global__ void wprep_all(const float* __restrict__ wa1, const float* __restrict__ wa2,
                          const float* __restrict__ wm, const float* __restrict__ wf,
                          const float* __restrict__ wkv, const float* __restrict__ wq,
                          float* __restrict__ ia1, float* __restrict__ ia2,
                          float* __restrict__ im, float* __restrict__ iff,
                          float* __restrict__ ikv, float* __restrict__ iq)
{
    int e = blockIdx.x * 256 + threadIdx.x;
    if (e < 147456) {
        int seg = e / 36864, r = e % 36864;
        const float* w = (seg == 0) ? wa1 : (seg == 1) ? wa2 : (seg == 2) ? wm : wf;
        float* img = (seg == 0) ? ia1 : (seg == 1) ? ia2 : (seg == 2) ? im : iff;
        int kp = r & 7, m = (r >> 3) & 63, j = r >> 9;
        int tap = j % 9, c = j / 9;
        int k = (kp >> 1) + ((kp & 1) << 2);
        img[r] = tf32r(w[(m * 64 + c * 8 + k) * 9 + tap]);
    } else if (e < 155648) {
        int r = e - 147456;
        int kp = r & 7, rest = r >> 3, m = rest % 128, cc = rest / 128;
        int k = (kp >> 1) + ((kp & 1) << 2);
        ikv[r] = tf32r(wkv[m * 64 + cc * 8 + k]);
    } else if (e < 159744) {
        int r = e - 155648;
        int kp = r & 7, rest = r >> 3, m = rest & 63, cc = rest >> 6;
        int k = (kp >> 1) + ((kp & 1) << 2);
        iq[r] = tf32r(wq[m * 64 + cc * 8 + k]);
    }
}

// ---- 1x1 conv OC=128 (kv), N=128, fused LN, direct STG ----
__global__ void __launch_bounds__(256, 2)
conv1x1_kv(const float* __restrict__ in, const float* __restrict__ wsrc,
           const float* __restrict__ lnw, const float* __restrict__ lnb,
           float* __restrict__ out)
{
    constexpr int OC = 128;
    extern __shared__ float smem[];
    float* Xb = smem;            // 64 x 136
    float* Wb = smem + 8704;     // [cc][128][8k']
    uint32_t sbX = smaddr(Xb), sbW = smaddr(Wb);
    int tid = threadIdx.x, wid = tid >> 5, lane = tid & 31;
    int gr = lane >> 2, tk = lane & 3;
    int b = blockIdx.y, pix0 = blockIdx.x * 128;
    const float* inb = in + (long)b * (64 * HW) + pix0;

    for (int idx = tid; idx < 2048; idx += 256) {
        int c4 = idx & 31, ic = idx >> 5;
        cpa16(sbX + (ic * 136 + c4 * 4) * 4, inb + (long)ic * HW + c4 * 4);
    }
    {
        const float4* s_ = (const float4*)wsrc;
        for (int t_ = tid; t_ < 2048; t_ += 256) cpa16(sbW + t_ * 16, s_ + t_);
    }
    cpa_commit();
    cpa_wait0();
    __syncthreads();
    if (tid < 128) {
        float s = 0.f, ss = 0.f;
#pragma unroll 8
        for (int c = 0; c < 64; ++c) { float v = Xb[c * 136 + tid]; s += v; ss += v * v; }
        float mu = s * (1.f / 64), var = ss * (1.f / 64) - mu * mu;
        float r = rsqrtf(var + 1e-5f);
#pragma unroll 8
        for (int c = 0; c < 64; ++c)
            Xb[c * 136 + tid] = tf32r((Xb[c * 136 + tid] - mu) * r * lnw[c] + lnb[c]);
    }
    __syncthreads();

    int mw = wid & 1, nw = wid >> 1;
    int m0 = mw * 64, n0 = nw * 32;
    float d[4][4][4];
#pragma unroll
    for (int mt = 0; mt < 4; ++mt)
#pragma unroll
        for (int nt = 0; nt < 4; ++nt)
#pragma unroll
            for (int q = 0; q < 4; ++q) d[mt][nt][q] = 0.f;

#pragma unroll
    for (int cc = 0; cc < 8; ++cc) {
        uint32_t bf[4][2];
#pragma unroll
        for (int nt = 0; nt < 4; ++nt) {
            const float* xr = Xb + (cc * 8 + tk) * 136 + n0 + nt * 8 + gr;
            bf[nt][0] = __float_as_uint(xr[0]);
            bf[nt][1] = __float_as_uint(xr[4 * 136]);
        }
#pragma unroll
        for (int mt = 0; mt < 4; ++mt) {
            const float* wp = Wb + (cc * OC + m0 + mt * 16) * 8;
            float2 aA = *(const float2*)(wp + gr * 8 + tk * 2);
            float2 aB = *(const float2*)(wp + (gr + 8) * 8 + tk * 2);
            uint32_t af[4] = {__float_as_uint(aA.x), __float_as_uint(aB.x),
                              __float_as_uint(aA.y), __float_as_uint(aB.y)};
#pragma unroll
            for (int nt = 0; nt < 4; ++nt) mma_tf32(d[mt][nt], af, bf[nt]);
        }
    }
#pragma unroll
    for (int mt = 0; mt < 4; ++mt) {
#pragma unroll
        for (int h2 = 0; h2 < 2; ++h2) {
            int mr = m0 + mt * 16 + gr + h2 * 8;
            long rowo = (long)(b * OC + mr) * HW + pix0;
#pragma unroll
            for (int nt = 0; nt < 4; ++nt) {
                long o = rowo + n0 + nt * 8 + tk * 2;
                *(float2*)&out[o] = make_float2(d[mt][nt][h2 * 2], d[mt][nt][h2 * 2 + 1]);
            }
        }
    }
}

// ---- 1x1 conv OC=64, N=256 full row. LNORM: LN on input. LNOUT: also emit ln(out) to out2 ----
template<bool LNORM, bool PBW, bool RES, bool LNOUT>
__global__ void __launch_bounds__(256, 2)
conv1x1r_mma(const float* __restrict__ in, const float* __restrict__ wsrc,
             const float* __restrict__ lnw, const float* __restrict__ lnb,
             const float* __restrict__ res, float* __restrict__ out,
             float* __restrict__ out2, int in_bstride, int ic_off)
{
    extern __shared__ float smem[];
    float* Xb = smem;            // 64 x 264
    float* Wb = smem + 16896;    // [cc][64][8k']
    uint32_t sbX = smaddr(Xb), sbW = smaddr(Wb);
    int tid = threadIdx.x, wid = tid >> 5, lane = tid & 31;
    int gr = lane >> 2, tk = lane & 3;
    int b = blockIdx.y, pix0 = blockIdx.x * 256;
    const float* inb = in + (long)b * in_bstride + (long)ic_off * HW + pix0;

    for (int idx = tid; idx < 4096; idx += 256) {
        int c4 = idx & 63, ic = idx >> 6;
        cpa16(sbX + (ic * 264 + c4 * 4) * 4, inb + (long)ic * HW + c4 * 4);
    }
    if (!PBW) {
        const float4* s_ = (const float4*)wsrc;
        for (int t_ = tid; t_ < 1024; t_ += 256) cpa16(sbW + t_ * 16, s_ + t_);
    }
    cpa_commit();
    if (PBW) {
        const float* wb = wsrc + b * 4096;
        for (int idx = tid; idx < 4096; idx += 256) {
            int kp = idx & 7, rest = idx >> 3;
            int m = rest & 63, cc = rest >> 6;
            int k = (kp >> 1) + ((kp & 1) << 2);
            Wb[idx] = tf32r(wb[m * 64 + cc * 8 + k]);
        }
    }
    cpa_wait0();
    __syncthreads();
    if (LNORM) {
        float s = 0.f, ss = 0.f;
#pragma unroll 8
        for (int c = 0; c < 64; ++c) { float v = Xb[c * 264 + tid]; s += v; ss += v * v; }
        float mu = s * (1.f / 64), var = ss * (1.f / 64) - mu * mu;
        float r = rsqrtf(var + 1e-5f);
#pragma unroll 8
        for (int c = 0; c < 64; ++c)
            Xb[c * 264 + tid] = tf32r((Xb[c * 264 + tid] - mu) * r * lnw[c] + lnb[c]);
    } else {
        for (int i = tid; i < 16384; i += 256) {
            int px = i & 255, ic = i >> 8;
            Xb[ic * 264 + px] = tf32r(Xb[ic * 264 + px]);
        }
    }
    __syncthreads();

    int mw = wid & 1, nw = wid >> 1;
    int m0 = mw * 32, n0 = nw * 64;
    float d[2][8][4];
#pragma unroll
    for (int mt = 0; mt < 2; ++mt)
#pragma unroll
        for (int nt = 0; nt < 8; ++nt)
#pragma unroll
            for (int q = 0; q < 4; ++q) d[mt][nt][q] = 0.f;

#pragma unroll
    for (int cc = 0; cc < 8; ++cc) {
        uint32_t bf[8][2];
#pragma unroll
        for (int nt = 0; nt < 8; ++nt) {
            const float* xr = Xb + (cc * 8 + tk) * 264 + n0 + nt * 8 + gr;
            bf[nt][0] = __float_as_uint(xr[0]);
            bf[nt][1] = __float_as_uint(xr[4 * 264]);
        }
#pragma unroll
        for (int mt = 0; mt < 2; ++mt) {
            const float* wp = Wb + (cc * 64 + m0 + mt * 16) * 8;
            float2 aA = *(const float2*)(wp + gr * 8 + tk * 2);
            float2 aB = *(const float2*)(wp + (gr + 8) * 8 + tk * 2);
            uint32_t af[4] = {__float_as_uint(aA.x), __float_as_uint(aB.x),
                              __float_as_uint(aA.y), __float_as_uint(aB.y)};
#pragma unroll
            for (int nt = 0; nt < 8; ++nt) mma_tf32(d[mt][nt], af, bf[nt]);
        }
    }
    if (LNOUT) __syncthreads();   // all mma reads of Xb done before overwrite
#pragma unroll
    for (int mt = 0; mt < 2; ++mt) {
#pragma unroll
        for (int h2 = 0; h2 < 2; ++h2) {
            int mr = m0 + mt * 16 + gr + h2 * 8;
            long rowo = (long)(b * 64 + mr) * HW + pix0;
#pragma unroll
            for (int nt = 0; nt < 8; ++nt) {
                int px = n0 + nt * 8 + tk * 2;
                long o = rowo + px;
                float v0 = d[mt][nt][h2 * 2], v1 = d[mt][nt][h2 * 2 + 1];
                if (RES) {
                    float2 rv = *(const float2*)&res[o];
                    v0 += rv.x; v1 += rv.y;
                }
                *(float2*)&out[o] = make_float2(v0, v1);
                if (LNOUT) *(float2*)&Xb[mr * 264 + px] = make_float2(v0, v1);
            }
        }
    }
    if (LNOUT) {
        __syncthreads();
        float s = 0.f, ss = 0.f;
#pragma unroll 8
        for (int c = 0; c < 64; ++c) { float v = Xb[c * 264 + tid]; s += v; ss += v * v; }
        float mu = s * (1.f / 64), var = ss * (1.f / 64) - mu * mu;
        float r = rsqrtf(var + 1e-5f);
        long ob = (long)(b * 64) * HW + pix0 + tid;
#pragma unroll 8
        for (int c = 0; c < 64; ++c)
            out2[ob + (long)c * HW] = tf32r((Xb[c * 264 + tid] - mu) * r * lnw[c] + lnb[c]);
    }
}

// ---- depthwise 3x3: 4 rows x 8 px per thread, rolling row loads ----
template<int CH>
__device__ __forceinline__ void dw_body(const float* __restrict__ in, const float* __restrict__ w,
                                        float* __restrict__ out, int bid)
{
    int p = bid * 256 + threadIdx.x;
    int xg = p & 31, yq = (p >> 5) & 63, g = p >> 11;
    int c = g & (CH - 1);
    int x0 = xg * 8, y0 = yq * 4;
    const float* wp = w + c * 9;
    float wr[9];
#pragma unroll
    for (int t = 0; t < 9; ++t) wr[t] = wp[t];
    const float* ip = in + (long)g * HW;
    bool interior = (yq > 0) && (yq < 63) && (xg > 0) && (xg < 31);
    float acc[4][8];
#pragma unroll
    for (int rr = 0; rr < 4; ++rr)
#pragma unroll
        for (int q = 0; q < 8; ++q) acc[rr][q] = 0.f;
#pragma unroll
    for (int iy = 0; iy < 6; ++iy) {
        int gy = y0 - 1 + iy;
        float r[10];
        if (interior) {
            const float* base = ip + gy * 256 + x0;
            float4 a = *(const float4*)base;
            float4 bq = *(const float4*)(base + 4);
            r[0] = base[-1];
            r[1] = a.x; r[2] = a.y; r[3] = a.z; r[4] = a.w;
            r[5] = bq.x; r[6] = bq.y; r[7] = bq.z; r[8] = bq.w;
            r[9] = base[8];
        } else {
#pragma unroll
            for (int j = 0; j < 10; ++j) {
                int ix = x0 - 1 + j;
                r[j] = (gy >= 0 && gy < 256 && ix >= 0 && ix < 256) ? ip[gy * 256 + ix] : 0.f;
            }
        }
#pragma unroll
        for (int ky = 0; ky < 3; ++ky) {
            int rr = iy - ky;
            if (rr >= 0 && rr < 4) {
#pragma unroll
                for (int kx = 0; kx < 3; ++kx) {
                    float wv = wr[ky * 3 + kx];
#pragma unroll
                    for (int q = 0; q < 8; ++q) acc[rr][q] += wv * r[q + kx];
                }
            }
        }
    }
#pragma unroll
    for (int rr = 0; rr < 4; ++rr) {
        float* op = out + (long)g * HW + (y0 + rr) * 256 + x0;
        *(float4*)op = make_float4(acc[rr][0], acc[rr][1], acc[rr][2], acc[rr][3]);
        *(float4*)(op + 4) = make_float4(acc[rr][4], acc[rr][5], acc[rr][6], acc[rr][7]);
    }
}

__global__ void dw3x3_both(const float* __restrict__ inkv, const float* __restrict__ wkv,
                           float* __restrict__ outkv,
                           const float* __restrict__ inq, const float* __restrict__ wq,
                           float* __restrict__ outq)
{
    int bid = blockIdx.x;
    if (bid < 4096) dw_body<128>(inkv, wkv, outkv, bid);
    else dw_body<64>(inq, wq, outq, bid - 4096);
}

// ---- attention stats (float4 gram loops, pitch 132) ----
__global__ void attn_stats_kernel(const float* __restrict__ q, const float* __restrict__ k,
                                  float* __restrict__ part)
{
    __shared__ float sQ[16 * 132];
    __shared__ float sK[16 * 132];
    int g = blockIdx.y;
    int b = g >> 2, h = g & 3;
    const float* qb = q + (long)b * 64 * HW + (long)h * 16 * HW;
    const float* kb = k + (long)b * 128 * HW + (long)h * 16 * HW;
    int tid = threadIdx.x;
    int c = tid >> 4, d = tid & 15;
    float accG = 0.f, accQ = 0.f, accK = 0.f;
    int nbase = blockIdx.x * (HW / NCHUNK);
    for (int sub = 0; sub < (HW / NCHUNK) / 128; ++sub) {
        int n0 = nbase + sub * 128;
#pragma unroll
        for (int i = 0; i < 8; ++i) {
            int lin = tid + i * 256;
            int cc = lin >> 7, nn = lin & 127;
            sQ[cc * 132 + nn] = qb[(long)cc * HW + n0 + nn];
            sK[cc * 132 + nn] = kb[(long)cc * HW + n0 + nn];
        }
        __syncthreads();
        const float* qr = sQ + c * 132;
        const float* kr = sK + d * 132;
#pragma unroll 4
        for (int n4 = 0; n4 < 32; ++n4) {
            float4 qa = *(const float4*)(qr + n4 * 4);
            float4 ka = *(const float4*)(kr + n4 * 4);
            accG += qa.x * ka.x + qa.y * ka.y + qa.z * ka.z + qa.w * ka.w;
        }
        if (d == 0) {
#pragma unroll 4
            for (int n4 = 0; n4 < 32; ++n4) {
                float4 qa = *(const float4*)(qr + n4 * 4);
                accQ += qa.x * qa.x + qa.y * qa.y + qa.z * qa.z + qa.w * qa.w;
            }
        }
        if (c == 0) {
#pragma unroll 4
            for (int n4 = 0; n4 < 32; ++n4) {
                float4 ka = *(const float4*)(kr + n4 * 4);
                accK += ka.x * ka.x + ka.y * ka.y + ka.z * ka.z + ka.w * ka.w;
            }
        }
        __syncthreads();
    }
    float* pp = part + ((long)g * NCHUNK + blockIdx.x) * 288;
    pp[tid] = accG;
    if (d == 0) pp[256 + c] = accQ;
    if (c == 0) pp[272 + d] = accK;
}

// ---- softmax + fold W_proj -> M[b][64][64] ----
__global__ void attn_finish_kernel(const float* __restrict__ part, const float* __restrict__ wproj,
                                   const float* __restrict__ temp, float* __restrict__ Mout)
{
    int b = blockIdx.x, tid = threadIdx.x;
    __shared__ float sG[4][256];
    __shared__ float sq[4][16], sk[4][16];
    __shared__ float sA[4][16][16];
    for (int h = 0; h < 4; ++h) {
        const float* pp = part + ((long)(b * 4 + h)) * NCHUNK * 288;
        float s = 0.f;
        for (int ch = 0; ch < NCHUNK; ++ch) s += pp[ch * 288 + tid];
        sG[h][tid] = s;
        if (tid < 32) {
            float s2 = 0.f;
            for (int ch = 0; ch < NCHUNK; ++ch) s2 += pp[ch * 288 + 256 + tid];
            if (tid < 16) sq[h][tid] = s2; else sk[h][tid - 16] = s2;
        }
    }
    __syncthreads();
    if (tid < 64) {
        int h = tid >> 4, c = tid & 15;
        float qn = fmaxf(sqrtf(sq[h][c]), 1e-12f);
        float tp = temp[h];
        float lg[16];
        float mx = -1e30f;
#pragma unroll
        for (int d = 0; d < 16; ++d) {
            float kn = fmaxf(sqrtf(sk[h][d]), 1e-12f);
            lg[d] = tp * sG[h][c * 16 + d] / (qn * kn);
            mx = fmaxf(mx, lg[d]);
        }
        float ssum = 0.f;
#pragma unroll
        for (int d = 0; d < 16; ++d) { lg[d] = expf(lg[d] - mx); ssum += lg[d]; }
        float inv = 1.f / ssum;
#pragma unroll
        for (int d = 0; d < 16; ++d) sA[h][c][d] = lg[d] * inv;
    }
    __syncthreads();
    for (int e = tid; e < 4096; e += 256) {
        int oc = e >> 6, j = e & 63, h = j >> 4, d = j & 15;
        float s = 0.f;
#pragma unroll
        for (int r = 0; r < 16; ++r) s += wproj[oc * 64 + h * 16 + r] * sA[h][r][d];
        Mout[b * 4096 + e] = s;
    }
}

// ---- dense 3x3 conv via mma.sync tf32, M=64, N=256 (full row), direct STG ----
template<int EPI>
__global__ void __launch_bounds__(256, 2)
conv3x3_mma(const float* __restrict__ in, const float* __restrict__ wimg,
            const float* __restrict__ aux1, const float* __restrict__ aux2,
            float* __restrict__ out)
{
    extern __shared__ float smem[];
    float* Wb = smem;               // 2 x 4608
    float* Xb = smem + 9216;        // 2 x 6336
    uint32_t sbW = smaddr(Wb), sbX = smaddr(Xb);

    int tid = threadIdx.x, wid = tid >> 5, lane = tid & 31;
    int gr = lane >> 2, tk = lane & 3;
    int y = blockIdx.x, b = blockIdx.y;
    const float* inb = in + (long)b * (64 * HW);

#define STAGE(C, BUF) do { \
        for (int idx = tid; idx < 1584; idx += 256) { \
            int c4 = idx % 66; \
            int ri = idx / 66; \
            int ic = ri & 7, row = ri >> 3; \
            int gx = -4 + c4 * 4; \
            int gy = y + row - 1; \
            bool ok = (gx >= 0) && (gx <= 252) && (gy >= 0) && (gy < 256); \
            const float* g_ = inb + (long)((C) * 8 + ic) * HW + gy * 256 + gx; \
            cpa16z(sbX + ((BUF) * 6336 + ri * 264 + c4 * 4) * 4, ok ? g_ : inb, ok); \
        } \
        const float4* s_ = (const float4*)(wimg + (long)(C) * 4608); \
        uint32_t d_ = sbW + (BUF) * 18432; \
        for (int t_ = tid; t_ < 1152; t_ += 256) cpa16(d_ + t_ * 16, s_ + t_); \
    } while (0)

    STAGE(0, 0);
    cpa_commit();
    STAGE(1, 1);
    cpa_commit();

    int mw = wid & 1, nw = wid >> 1;
    int m0 = mw * 32, n0 = nw * 64;
    float d[2][8][4];
#pragma unroll
    for (int mt = 0; mt < 2; ++mt)
#pragma unroll
        for (int nt = 0; nt < 8; ++nt)
#pragma unroll
            for (int q = 0; q < 4; ++q) d[mt][nt][q] = 0.f;

    for (int cc = 0; cc < 8; ++cc) {
        if (cc < 7) cpa_wait1(); else cpa_wait0();
        __syncthreads();
        const float* wb = Wb + (cc & 1) * 4608;
        const float* xb = Xb + (cc & 1) * 6336;
#pragma unroll
        for (int tap = 0; tap < 9; ++tap) {
            int ky = tap / 3, kx = tap - ky * 3;
            const float* xr = xb + (ky * 8 + tk) * 264 + n0 + gr + kx + 3;
            uint32_t bf[8][2];
#pragma unroll
            for (int nt = 0; nt < 8; ++nt) {
                bf[nt][0] = __float_as_uint(xr[nt * 8]);
                bf[nt][1] = __float_as_uint(xr[nt * 8 + 4 * 264]);
            }
#pragma unroll
            for (int mt = 0; mt < 2; ++mt) {
                const float* wp = wb + (tap * 64 + m0 + mt * 16) * 8;
                float2 aA = *(const float2*)(wp + gr * 8 + tk * 2);
                float2 aB = *(const float2*)(wp + (gr + 8) * 8 + tk * 2);
                uint32_t af[4];
                af[0] = __float_as_uint(aA.x);
                af[1] = __float_as_uint(aB.x);
                af[2] = __float_as_uint(aA.y);
                af[3] = __float_as_uint(aB.y);
#pragma unroll
                for (int nt = 0; nt < 8; ++nt)
                    mma_tf32(d[mt][nt], af, bf[nt]);
            }
        }
        __syncthreads();
        if (cc + 2 < 8) { STAGE(cc + 2, cc & 1); cpa_commit(); }
    }
#undef STAGE

    long obase = (long)(b * 64) * HW + y * 256;
#pragma unroll
    for (int mt = 0; mt < 2; ++mt) {
#pragma unroll
        for (int h2 = 0; h2 < 2; ++h2) {
            int mr = m0 + mt * 16 + gr + h2 * 8;
            long rowo = obase + (long)mr * HW;
#pragma unroll
            for (int nt = 0; nt < 8; ++nt) {
                long o = rowo + n0 + nt * 8 + tk * 2;
                float v0 = d[mt][nt][h2 * 2], v1 = d[mt][nt][h2 * 2 + 1];
                if (EPI == 1) {
                    v0 = tf32r(gelu_f(v0));
                    v1 = tf32r(gelu_f(v1));
                } else if (EPI == 2) {
                    float2 a1v = *(const float2*)&aux1[o];
                    float2 a2v = *(const float2*)&aux2[o];
                    v0 = tf32r(a1v.x * (1.f / (1.f + expf(-v0))) + a2v.x);
                    v1 = tf32r(a1v.y * (1.f / (1.f + expf(-v1))) + a2v.y);
                } else if (EPI == 3) {
                    float2 rv = *(const float2*)&aux1[o];
                    v0 += rv.x; v1 += rv.y;
                }
                *(float2*)&out[o] = make_float2(v0, v1);
            }
        }
    }
}

extern "C" void kernel_launch(void* const* d_in, const int* in_sizes, int n_in,
                              void* d_out, int out_size)
{
    const float* x       = (const float*)d_in[0];
    const float* ref     = (const float*)d_in[1];
    const float* ln1w    = (const float*)d_in[2];
    const float* ln1b    = (const float*)d_in[3];
    const float* ln2w    = (const float*)d_in[4];
    const float* ln2b    = (const float*)d_in[5];
    const float* ln3w    = (const float*)d_in[6];
    const float* ln3b    = (const float*)d_in[7];
    const float* w_kv    = (const float*)d_in[8];
    const float* w_kv_dw = (const float*)d_in[9];
    const float* w_q     = (const float*)d_in[10];
    const float* w_q_dw  = (const float*)d_in[11];
    const float* w_proj  = (const float*)d_in[12];
    const float* temp    = (const float*)d_in[13];
    const float* w_add1  = (const float*)d_in[14];
    const float* w_add2  = (const float*)d_in[15];
    const float* w_mul1  = (const float*)d_in[16];
    const float* w_fuse  = (const float*)d_in[17];
    float* out = (float*)d_out;

    float* pool = nullptr;
    cudaGetSymbolAddress((void**)&pool, g_pool);
    const long SZ = 16777216L, SZ2 = 33554432L;
    float* kv0  = pool;
    float* kv1  = pool + SZ2;
    float* bufA = pool + 2 * SZ2;
    float* bufB = bufA + SZ;
    float* bufC = bufB + SZ;
    float* bufD = bufC + SZ;
    float* bufE = bufD + SZ;
    float* x1   = bufE + SZ;
    float* Mb   = x1 + SZ;
    float* part = Mb + 16384;
    float* wIa1 = part + 294912;
    float* wIa2 = wIa1 + 36864;
    float* wIm  = wIa2 + 36864;
    float* wIf  = wIm + 36864;
    float* wIkv = wIf + 36864;
    float* wIq  = wIkv + 8192;

    cudaFuncSetAttribute(conv3x3_mma<0>, cudaFuncAttributeMaxDynamicSharedMemorySize, CSM3);
    cudaFuncSetAttribute(conv3x3_mma<1>, cudaFuncAttributeMaxDynamicSharedMemorySize, CSM3);
    cudaFuncSetAttribute(conv3x3_mma<2>, cudaFuncAttributeMaxDynamicSharedMemorySize, CSM3);
    cudaFuncSetAttribute(conv3x3_mma<3>, cudaFuncAttributeMaxDynamicSharedMemorySize, CSM3);
    cudaFuncSetAttribute(conv1x1_kv, cudaFuncAttributeMaxDynamicSharedMemorySize, CSM1KV);
    cudaFuncSetAttribute((conv1x1r_mma<true, false, false, false>), cudaFuncAttributeMaxDynamicSharedMemorySize, CSM1R);
    cudaFuncSetAttribute((conv1x1r_mma<false, true, true, true>), cudaFuncAttributeMaxDynamicSharedMemorySize, CSM1R);

    wprep_all<<<624, 256>>>(w_add1, w_add2, w_mul1, w_fuse, w_kv, w_q,
                            wIa1, wIa2, wIm, wIf, wIkv, wIq);

    // ---- Attention branch ----
    conv1x1_kv<<<dim3(512, 4), 256, CSM1KV>>>(ref, wIkv, ln1w, ln1b, kv0);
    conv1x1r_mma<true, false, false, false><<<dim3(256, 4), 256, CSM1R>>>(x, wIq, ln3w, ln3b, nullptr, bufC, nullptr, 64 * HW, 0);
    dw3x3_both<<<6144, 256>>>(kv0, w_kv_dw, kv1, bufC, w_q_dw, bufD);
    attn_stats_kernel<<<dim3(NCHUNK, 16), 256>>>(bufD, kv1, part);
    attn_finish_kernel<<<4, 256>>>(part, w_proj, temp, Mb);
    // x1 = x + M_b @ v ; bufA = tf32(ln2(x1)) fused
    conv1x1r_mma<false, true, true, true><<<dim3(256, 4), 256, CSM1R>>>(kv1, Mb, ln2w, ln2b, x, x1, bufA, 128 * HW, 64);

    // ---- SFM branch ----
    conv3x3_mma<1><<<dim3(256, 4), 256, CSM3>>>(bufA, wIa1, nullptr, nullptr, bufB);    // ga1
    conv3x3_mma<0><<<dim3(256, 4), 256, CSM3>>>(bufB, wIa2, nullptr, nullptr, bufC);    // x_add
    conv3x3_mma<1><<<dim3(256, 4), 256, CSM3>>>(bufA, wIm, nullptr, nullptr, bufD);     // gm1
    conv3x3_mma<2><<<dim3(256, 4), 256, CSM3>>>(bufD, wIm, bufA, bufC, bufE);           // z
    conv3x3_mma<3><<<dim3(256, 4), 256, CSM3>>>(bufE, wIf, x1, nullptr, out);           // out
}

// round 17
// speedup vs baseline: 2.6289x; 1.0334x over previous
#include <cuda_runtime.h>
#include <math.h>
#include <stdint.h>

typedef unsigned long long ull;
#define HW 65536
#define NCHUNK 64
#define CSM3 87552
#define CSM3D 99840
#define CSM1KV 67584
#define CSM1R 84224

__device__ float g_pool[168378368];

__device__ __forceinline__ float gelu_f(float v) {
    return 0.5f * v * (1.0f + erff(v * 0.70710678118654752f));
}
__device__ __forceinline__ uint32_t smaddr(const void* p) {
    uint32_t a;
    asm("{.reg .u64 t; cvta.to.shared.u64 t, %1; cvt.u32.u64 %0, t;}" : "=r"(a) : "l"(p));
    return a;
}
__device__ __forceinline__ float tf32r(float f) {
    uint32_t r; asm("cvt.rna.tf32.f32 %0, %1;" : "=r"(r) : "f"(f));
    return __uint_as_float(r);
}
__device__ __forceinline__ void cpa16(uint32_t s, const void* g) {
    asm volatile("cp.async.cg.shared.global [%0], [%1], 16;" :: "r"(s), "l"(g));
}
__device__ __forceinline__ void cpa16z(uint32_t s, const void* g, bool ok) {
    int sz = ok ? 16 : 0;
    asm volatile("cp.async.cg.shared.global [%0], [%1], 16, %2;" :: "r"(s), "l"(g), "r"(sz));
}
__device__ __forceinline__ void cpa_commit() { asm volatile("cp.async.commit_group;"); }
__device__ __forceinline__ void cpa_wait1() { asm volatile("cp.async.wait_group 1;"); }
__device__ __forceinline__ void cpa_wait0() { asm volatile("cp.async.wait_group 0;"); }
__device__ __forceinline__ void mma_tf32(float* d, const uint32_t* a, const uint32_t* b) {
    asm volatile("mma.sync.aligned.m16n8k8.row.col.f32.tf32.tf32.f32 "
        "{%0,%1,%2,%3}, {%4,%5,%6,%7}, {%8,%9}, {%0,%1,%2,%3};"
        : "+f"(d[0]), "+f"(d[1]), "+f"(d[2]), "+f"(d[3])
        : "r"(a[0]), "r"(a[1]), "r"(a[2]), "r"(a[3]), "r"(b[0]), "r"(b[1]));
}

// ---- merged weight prep: stacked a1+mul image (M=128), a2, m, f (M=64), kv, q ----
__global__ void wprep_all(const float* __restrict__ wa1, const float* __restrict__ wa2,
                          const float* __restrict__ wm, const float* __restrict__ wf,
                          const float* __restrict__ wkv, const float* __restrict__ wq,
                          float* __restrict__ i1m, float* __restrict__ ia2,
                          float* __restrict__ im, float* __restrict__ iff,
                          float* __restrict__ ikv, float* __restrict__ iq)
{
    int e = blockIdx.x * 256 + threadIdx.x;
    if (e < 73728) {
        // stacked: [cc][tap][128 m][8 k'], m<64 = wa1, m>=64 = wm
        int kp = e & 7, m = (e >> 3) & 127, j = e >> 10;
        int tap = j % 9, c = j / 9;
        int k = (kp >> 1) + ((kp & 1) << 2);
        int oc = m & 63;
        const float* w = (m < 64) ? wa1 : wm;
        i1m[e] = tf32r(w[(oc * 64 + c * 8 + k) * 9 + tap]);
    } else if (e < 184320) {
        int seg = (e - 73728) / 36864, r = (e - 73728) % 36864;
        const float* w = (seg == 0) ? wa2 : (seg == 1) ? wm : wf;
        float* img = (seg == 0) ? ia2 : (seg == 1) ? im : iff;
        int kp = r & 7, m = (r >> 3) & 63, j = r >> 9;
        int tap = j % 9, c = j / 9;
        int k = (kp >> 1) + ((kp & 1) << 2);
        img[r] = tf32r(w[(m * 64 + c * 8 + k) * 9 + tap]);
    } else if (e < 192512) {
        int r = e - 184320;
        int kp = r & 7, rest = r >> 3, m = rest % 128, cc = rest / 128;
        int k = (kp >> 1) + ((kp & 1) << 2);
        ikv[r] = tf32r(wkv[m * 64 + cc * 8 + k]);
    } else if (e < 196608) {
        int r = e - 192512;
        int kp = r & 7, rest = r >> 3, m = rest & 63, cc = rest >> 6;
        int k = (kp >> 1) + ((kp & 1) << 2);
        iq[r] = tf32r(wq[m * 64 + cc * 8 + k]);
    }
}

// ---- 1x1 conv OC=128 (kv), N=128, fused LN, direct STG ----
__global__ void __launch_bounds__(256, 2)
conv1x1_kv(const float* __restrict__ in, const float* __restrict__ wsrc,
           const float* __restrict__ lnw, const float* __restrict__ lnb,
           float* __restrict__ out)
{
    constexpr int OC = 128;
    extern __shared__ float smem[];
    float* Xb = smem;            // 64 x 136
    float* Wb = smem + 8704;     // [cc][128][8k']
    uint32_t sbX = smaddr(Xb), sbW = smaddr(Wb);
    int tid = threadIdx.x, wid = tid >> 5, lane = tid & 31;
    int gr = lane >> 2, tk = lane & 3;
    int b = blockIdx.y, pix0 = blockIdx.x * 128;
    const float* inb = in + (long)b * (64 * HW) + pix0;

    for (int idx = tid; idx < 2048; idx += 256) {
        int c4 = idx & 31, ic = idx >> 5;
        cpa16(sbX + (ic * 136 + c4 * 4) * 4, inb + (long)ic * HW + c4 * 4);
    }
    {
        const float4* s_ = (const float4*)wsrc;
        for (int t_ = tid; t_ < 2048; t_ += 256) cpa16(sbW + t_ * 16, s_ + t_);
    }
    cpa_commit();
    cpa_wait0();
    __syncthreads();
    if (tid < 128) {
        float s = 0.f, ss = 0.f;
#pragma unroll 8
        for (int c = 0; c < 64; ++c) { float v = Xb[c * 136 + tid]; s += v; ss += v * v; }
        float mu = s * (1.f / 64), var = ss * (1.f / 64) - mu * mu;
        float r = rsqrtf(var + 1e-5f);
#pragma unroll 8
        for (int c = 0; c < 64; ++c)
            Xb[c * 136 + tid] = tf32r((Xb[c * 136 + tid] - mu) * r * lnw[c] + lnb[c]);
    }
    __syncthreads();

    int mw = wid & 1, nw = wid >> 1;
    int m0 = mw * 64, n0 = nw * 32;
    float d[4][4][4];
#pragma unroll
    for (int mt = 0; mt < 4; ++mt)
#pragma unroll
        for (int nt = 0; nt < 4; ++nt)
#pragma unroll
            for (int q = 0; q < 4; ++q) d[mt][nt][q] = 0.f;

#pragma unroll
    for (int cc = 0; cc < 8; ++cc) {
        uint32_t bf[4][2];
#pragma unroll
        for (int nt = 0; nt < 4; ++nt) {
            const float* xr = Xb + (cc * 8 + tk) * 136 + n0 + nt * 8 + gr;
            bf[nt][0] = __float_as_uint(xr[0]);
            bf[nt][1] = __float_as_uint(xr[4 * 136]);
        }
#pragma unroll
        for (int mt = 0; mt < 4; ++mt) {
            const float* wp = Wb + (cc * OC + m0 + mt * 16) * 8;
            float2 aA = *(const float2*)(wp + gr * 8 + tk * 2);
            float2 aB = *(const float2*)(wp + (gr + 8) * 8 + tk * 2);
            uint32_t af[4] = {__float_as_uint(aA.x), __float_as_uint(aB.x),
                              __float_as_uint(aA.y), __float_as_uint(aB.y)};
#pragma unroll
            for (int nt = 0; nt < 4; ++nt) mma_tf32(d[mt][nt], af, bf[nt]);
        }
    }
#pragma unroll
    for (int mt = 0; mt < 4; ++mt) {
#pragma unroll
        for (int h2 = 0; h2 < 2; ++h2) {
            int mr = m0 + mt * 16 + gr + h2 * 8;
            long rowo = (long)(b * OC + mr) * HW + pix0;
#pragma unroll
            for (int nt = 0; nt < 4; ++nt) {
                long o = rowo + n0 + nt * 8 + tk * 2;
                *(float2*)&out[o] = make_float2(d[mt][nt][h2 * 2], d[mt][nt][h2 * 2 + 1]);
            }
        }
    }
}

// ---- 1x1 conv OC=64, N=256 full row. LNORM: LN input. LNOUT: also emit ln(out) ----
template<bool LNORM, bool PBW, bool RES, bool LNOUT>
__global__ void __launch_bounds__(256, 2)
conv1x1r_mma(const float* __restrict__ in, const float* __restrict__ wsrc,
             const float* __restrict__ lnw, const float* __restrict__ lnb,
             const float* __restrict__ res, float* __restrict__ out,
             float* __restrict__ out2, int in_bstride, int ic_off)
{
    extern __shared__ float smem[];
    float* Xb = smem;            // 64 x 264
    float* Wb = smem + 16896;    // [cc][64][8k']
    uint32_t sbX = smaddr(Xb), sbW = smaddr(Wb);
    int tid = threadIdx.x, wid = tid >> 5, lane = tid & 31;
    int gr = lane >> 2, tk = lane & 3;
    int b = blockIdx.y, pix0 = blockIdx.x * 256;
    const float* inb = in + (long)b * in_bstride + (long)ic_off * HW + pix0;

    for (int idx = tid; idx < 4096; idx += 256) {
        int c4 = idx & 63, ic = idx >> 6;
        cpa16(sbX + (ic * 264 + c4 * 4) * 4, inb + (long)ic * HW + c4 * 4);
    }
    if (!PBW) {
        const float4* s_ = (const float4*)wsrc;
        for (int t_ = tid; t_ < 1024; t_ += 256) cpa16(sbW + t_ * 16, s_ + t_);
    }
    cpa_commit();
    if (PBW) {
        const float* wb = wsrc + b * 4096;
        for (int idx = tid; idx < 4096; idx += 256) {
            int kp = idx & 7, rest = idx >> 3;
            int m = rest & 63, cc = rest >> 6;
            int k = (kp >> 1) + ((kp & 1) << 2);
            Wb[idx] = tf32r(wb[m * 64 + cc * 8 + k]);
        }
    }
    cpa_wait0();
    __syncthreads();
    if (LNORM) {
        float s = 0.f, ss = 0.f;
#pragma unroll 8
        for (int c = 0; c < 64; ++c) { float v = Xb[c * 264 + tid]; s += v; ss += v * v; }
        float mu = s * (1.f / 64), var = ss * (1.f / 64) - mu * mu;
        float r = rsqrtf(var + 1e-5f);
#pragma unroll 8
        for (int c = 0; c < 64; ++c)
            Xb[c * 264 + tid] = tf32r((Xb[c * 264 + tid] - mu) * r * lnw[c] + lnb[c]);
    } else {
        for (int i = tid; i < 16384; i += 256) {
            int px = i & 255, ic = i >> 8;
            Xb[ic * 264 + px] = tf32r(Xb[ic * 264 + px]);
        }
    }
    __syncthreads();

    int mw = wid & 1, nw = wid >> 1;
    int m0 = mw * 32, n0 = nw * 64;
    float d[2][8][4];
#pragma unroll
    for (int mt = 0; mt < 2; ++mt)
#pragma unroll
        for (int nt = 0; nt < 8; ++nt)
#pragma unroll
            for (int q = 0; q < 4; ++q) d[mt][nt][q] = 0.f;

#pragma unroll
    for (int cc = 0; cc < 8; ++cc) {
        uint32_t bf[8][2];
#pragma unroll
        for (int nt = 0; nt < 8; ++nt) {
            const float* xr = Xb + (cc * 8 + tk) * 264 + n0 + nt * 8 + gr;
            bf[nt][0] = __float_as_uint(xr[0]);
            bf[nt][1] = __float_as_uint(xr[4 * 264]);
        }
#pragma unroll
        for (int mt = 0; mt < 2; ++mt) {
            const float* wp = Wb + (cc * 64 + m0 + mt * 16) * 8;
            float2 aA = *(const float2*)(wp + gr * 8 + tk * 2);
            float2 aB = *(const float2*)(wp + (gr + 8) * 8 + tk * 2);
            uint32_t af[4] = {__float_as_uint(aA.x), __float_as_uint(aB.x),
                              __float_as_uint(aA.y), __float_as_uint(aB.y)};
#pragma unroll
            for (int nt = 0; nt < 8; ++nt) mma_tf32(d[mt][nt], af, bf[nt]);
        }
    }
    if (LNOUT) __syncthreads();
#pragma unroll
    for (int mt = 0; mt < 2; ++mt) {
#pragma unroll
        for (int h2 = 0; h2 < 2; ++h2) {
            int mr = m0 + mt * 16 + gr + h2 * 8;
            long rowo = (long)(b * 64 + mr) * HW + pix0;
#pragma unroll
            for (int nt = 0; nt < 8; ++nt) {
                int px = n0 + nt * 8 + tk * 2;
                long o = rowo + px;
                float v0 = d[mt][nt][h2 * 2], v1 = d[mt][nt][h2 * 2 + 1];
                if (RES) {
                    float2 rv = *(const float2*)&res[o];
                    v0 += rv.x; v1 += rv.y;
                }
                *(float2*)&out[o] = make_float2(v0, v1);
                if (LNOUT) *(float2*)&Xb[mr * 264 + px] = make_float2(v0, v1);
            }
        }
    }
    if (LNOUT) {
        __syncthreads();
        float s = 0.f, ss = 0.f;
#pragma unroll 8
        for (int c = 0; c < 64; ++c) { float v = Xb[c * 264 + tid]; s += v; ss += v * v; }
        float mu = s * (1.f / 64), var = ss * (1.f / 64) - mu * mu;
        float r = rsqrtf(var + 1e-5f);
        long ob = (long)(b * 64) * HW + pix0 + tid;
#pragma unroll 8
        for (int c = 0; c < 64; ++c)
            out2[ob + (long)c * HW] = tf32r((Xb[c * 264 + tid] - mu) * r * lnw[c] + lnb[c]);
    }
}

// ---- depthwise 3x3: 4 rows x 8 px per thread, rolling row loads ----
template<int CH>
__device__ __forceinline__ void dw_body(const float* __restrict__ in, const float* __restrict__ w,
                                        float* __restrict__ out, int bid)
{
    int p = bid * 256 + threadIdx.x;
    int xg = p & 31, yq = (p >> 5) & 63, g = p >> 11;
    int c = g & (CH - 1);
    int x0 = xg * 8, y0 = yq * 4;
    const float* wp = w + c * 9;
    float wr[9];
#pragma unroll
    for (int t = 0; t < 9; ++t) wr[t] = wp[t];
    const float* ip = in + (long)g * HW;
    bool interior = (yq > 0) && (yq < 63) && (xg > 0) && (xg < 31);
    float acc[4][8];
#pragma unroll
    for (int rr = 0; rr < 4; ++rr)
#pragma unroll
        for (int q = 0; q < 8; ++q) acc[rr][q] = 0.f;
#pragma unroll
    for (int iy = 0; iy < 6; ++iy) {
        int gy = y0 - 1 + iy;
        float r[10];
        if (interior) {
            const float* base = ip + gy * 256 + x0;
            float4 a = *(const float4*)base;
            float4 bq = *(const float4*)(base + 4);
            r[0] = base[-1];
            r[1] = a.x; r[2] = a.y; r[3] = a.z; r[4] = a.w;
            r[5] = bq.x; r[6] = bq.y; r[7] = bq.z; r[8] = bq.w;
            r[9] = base[8];
        } else {
#pragma unroll
            for (int j = 0; j < 10; ++j) {
                int ix = x0 - 1 + j;
                r[j] = (gy >= 0 && gy < 256 && ix >= 0 && ix < 256) ? ip[gy * 256 + ix] : 0.f;
            }
        }
#pragma unroll
        for (int ky = 0; ky < 3; ++ky) {
            int rr = iy - ky;
            if (rr >= 0 && rr < 4) {
#pragma unroll
                for (int kx = 0; kx < 3; ++kx) {
                    float wv = wr[ky * 3 + kx];
#pragma unroll
                    for (int q = 0; q < 8; ++q) acc[rr][q] += wv * r[q + kx];
                }
            }
        }
    }
#pragma unroll
    for (int rr = 0; rr < 4; ++rr) {
        float* op = out + (long)g * HW + (y0 + rr) * 256 + x0;
        *(float4*)op = make_float4(acc[rr][0], acc[rr][1], acc[rr][2], acc[rr][3]);
        *(float4*)(op + 4) = make_float4(acc[rr][4], acc[rr][5], acc[rr][6], acc[rr][7]);
    }
}

__global__ void dw3x3_both(const float* __restrict__ inkv, const float* __restrict__ wkv,
                           float* __restrict__ outkv,
                           const float* __restrict__ inq, const float* __restrict__ wq,
                           float* __restrict__ outq)
{
    int bid = blockIdx.x;
    if (bid < 4096) dw_body<128>(inkv, wkv, outkv, bid);
    else dw_body<64>(inq, wq, outq, bid - 4096);
}

// ---- attention stats (float4 gram loops, pitch 132) ----
__global__ void attn_stats_kernel(const float* __restrict__ q, const float* __restrict__ k,
                                  float* __restrict__ part)
{
    __shared__ float sQ[16 * 132];
    __shared__ float sK[16 * 132];
    int g = blockIdx.y;
    int b = g >> 2, h = g & 3;
    const float* qb = q + (long)b * 64 * HW + (long)h * 16 * HW;
    const float* kb = k + (long)b * 128 * HW + (long)h * 16 * HW;
    int tid = threadIdx.x;
    int c = tid >> 4, d = tid & 15;
    float accG = 0.f, accQ = 0.f, accK = 0.f;
    int nbase = blockIdx.x * (HW / NCHUNK);
    for (int sub = 0; sub < (HW / NCHUNK) / 128; ++sub) {
        int n0 = nbase + sub * 128;
#pragma unroll
        for (int i = 0; i < 8; ++i) {
            int lin = tid + i * 256;
            int cc = lin >> 7, nn = lin & 127;
            sQ[cc * 132 + nn] = qb[(long)cc * HW + n0 + nn];
            sK[cc * 132 + nn] = kb[(long)cc * HW + n0 + nn];
        }
        __syncthreads();
        const float* qr = sQ + c * 132;
        const float* kr = sK + d * 132;
#pragma unroll 4
        for (int n4 = 0; n4 < 32; ++n4) {
            float4 qa = *(const float4*)(qr + n4 * 4);
            float4 ka = *(const float4*)(kr + n4 * 4);
            accG += qa.x * ka.x + qa.y * ka.y + qa.z * ka.z + qa.w * ka.w;
        }
        if (d == 0) {
#pragma unroll 4
            for (int n4 = 0; n4 < 32; ++n4) {
                float4 qa = *(const float4*)(qr + n4 * 4);
                accQ += qa.x * qa.x + qa.y * qa.y + qa.z * qa.z + qa.w * qa.w;
            }
        }
        if (c == 0) {
#pragma unroll 4
            for (int n4 = 0; n4 < 32; ++n4) {
                float4 ka = *(const float4*)(kr + n4 * 4);
                accK += ka.x * ka.x + ka.y * ka.y + ka.z * ka.z + ka.w * ka.w;
            }
        }
        __syncthreads();
    }
    float* pp = part + ((long)g * NCHUNK + blockIdx.x) * 288;
    pp[tid] = accG;
    if (d == 0) pp[256 + c] = accQ;
    if (c == 0) pp[272 + d] = accK;
}

// ---- softmax + fold W_proj -> M[b][64][64] ----
__global__ void attn_finish_kernel(const float* __restrict__ part, const float* __restrict__ wproj,
                                   const float* __restrict__ temp, float* __restrict__ Mout)
{
    int b = blockIdx.x, tid = threadIdx.x;
    __shared__ float sG[4][256];
    __shared__ float sq[4][16], sk[4][16];
    __shared__ float sA[4][16][16];
    for (int h = 0; h < 4; ++h) {
        const float* pp = part + ((long)(b * 4 + h)) * NCHUNK * 288;
        float s = 0.f;
        for (int ch = 0; ch < NCHUNK; ++ch) s += pp[ch * 288 + tid];
        sG[h][tid] = s;
        if (tid < 32) {
            float s2 = 0.f;
            for (int ch = 0; ch < NCHUNK; ++ch) s2 += pp[ch * 288 + 256 + tid];
            if (tid < 16) sq[h][tid] = s2; else sk[h][tid - 16] = s2;
        }
    }
    __syncthreads();
    if (tid < 64) {
        int h = tid >> 4, c = tid & 15;
        float qn = fmaxf(sqrtf(sq[h][c]), 1e-12f);
        float tp = temp[h];
        float lg[16];
        float mx = -1e30f;
#pragma unroll
        for (int d = 0; d < 16; ++d) {
            float kn = fmaxf(sqrtf(sk[h][d]), 1e-12f);
            lg[d] = tp * sG[h][c * 16 + d] / (qn * kn);
            mx = fmaxf(mx, lg[d]);
        }
        float ssum = 0.f;
#pragma unroll
        for (int d = 0; d < 16; ++d) { lg[d] = expf(lg[d] - mx); ssum += lg[d]; }
        float inv = 1.f / ssum;
#pragma unroll
        for (int d = 0; d < 16; ++d) sA[h][c][d] = lg[d] * inv;
    }
    __syncthreads();
    for (int e = tid; e < 4096; e += 256) {
        int oc = e >> 6, j = e & 63, h = j >> 4, d = j & 15;
        float s = 0.f;
#pragma unroll
        for (int r = 0; r < 16; ++r) s += wproj[oc * 64 + h * 16 + r] * sA[h][r][d];
        Mout[b * 4096 + e] = s;
    }
}

// ---- dual 3x3 conv (ga1+gm1): M=128 stacked, N=128, shared X, gelu epilogue ----
__global__ void __launch_bounds__(256, 2)
conv3x3_dual(const float* __restrict__ in, const float* __restrict__ wimg,
             float* __restrict__ outA, float* __restrict__ outB)
{
    extern __shared__ float smem[];
    float* Wb = smem;               // 2 x 9216
    float* Xb = smem + 18432;       // 2 x 3264
    uint32_t sbW = smaddr(Wb), sbX = smaddr(Xb);

    int tid = threadIdx.x, wid = tid >> 5, lane = tid & 31;
    int gr = lane >> 2, tk = lane & 3;
    int half = blockIdx.x & 1, y = blockIdx.x >> 1, b = blockIdx.y;
    int x0 = half * 128;
    const float* inb = in + (long)b * (64 * HW);

#define STAGE(C, BUF) do { \
        for (int idx = tid; idx < 816; idx += 256) { \
            int c4 = idx % 34; \
            int ri = idx / 34; \
            int ic = ri & 7, row = ri >> 3; \
            int gx = x0 - 4 + c4 * 4; \
            int gy = y + row - 1; \
            bool ok = (gx >= 0) && (gx <= 252) && (gy >= 0) && (gy < 256); \
            const float* g_ = inb + (long)((C) * 8 + ic) * HW + gy * 256 + gx; \
            cpa16z(sbX + ((BUF) * 3264 + ri * 136 + c4 * 4) * 4, ok ? g_ : inb, ok); \
        } \
        const float4* s_ = (const float4*)(wimg + (long)(C) * 9216); \
        uint32_t d_ = sbW + (BUF) * 36864; \
        for (int t_ = tid; t_ < 2304; t_ += 256) cpa16(d_ + t_ * 16, s_ + t_); \
    } while (0)

    STAGE(0, 0);
    cpa_commit();
    STAGE(1, 1);
    cpa_commit();

    int mw = wid & 1, nw = wid >> 1;
    int m0 = mw * 64, n0 = nw * 32;
    float d[4][4][4];
#pragma unroll
    for (int mt = 0; mt < 4; ++mt)
#pragma unroll
        for (int nt = 0; nt < 4; ++nt)
#pragma unroll
            for (int q = 0; q < 4; ++q) d[mt][nt][q] = 0.f;

    for (int cc = 0; cc < 8; ++cc) {
        if (cc < 7) cpa_wait1(); else cpa_wait0();
        __syncthreads();
        const float* wb = Wb + (cc & 1) * 9216;
        const float* xb = Xb + (cc & 1) * 3264;
#pragma unroll
        for (int tap = 0; tap < 9; ++tap) {
            int ky = tap / 3, kx = tap - ky * 3;
            const float* xr = xb + (ky * 8 + tk) * 136 + n0 + gr + kx + 3;
            uint32_t bf[4][2];
#pragma unroll
            for (int nt = 0; nt < 4; ++nt) {
                bf[nt][0] = __float_as_uint(xr[nt * 8]);
                bf[nt][1] = __float_as_uint(xr[nt * 8 + 4 * 136]);
            }
#pragma unroll
            for (int mt = 0; mt < 4; ++mt) {
                const float* wp = wb + (tap * 128 + m0 + mt * 16) * 8;
                float2 aA = *(const float2*)(wp + gr * 8 + tk * 2);
                float2 aB = *(const float2*)(wp + (gr + 8) * 8 + tk * 2);
                uint32_t af[4];
                af[0] = __float_as_uint(aA.x);
                af[1] = __float_as_uint(aB.x);
                af[2] = __float_as_uint(aA.y);
                af[3] = __float_as_uint(aB.y);
#pragma unroll
                for (int nt = 0; nt < 4; ++nt)
                    mma_tf32(d[mt][nt], af, bf[nt]);
            }
        }
        __syncthreads();
        if (cc + 2 < 8) { STAGE(cc + 2, cc & 1); cpa_commit(); }
    }
#undef STAGE

    long pxbase = (long)y * 256 + x0;
#pragma unroll
    for (int mt = 0; mt < 4; ++mt) {
#pragma unroll
        for (int h2 = 0; h2 < 2; ++h2) {
            int mr = m0 + mt * 16 + gr + h2 * 8;
            float* dst = (mr < 64) ? (outA + (long)(b * 64 + mr) * HW)
                                   : (outB + (long)(b * 64 + mr - 64) * HW);
#pragma unroll
            for (int nt = 0; nt < 4; ++nt) {
                long o = pxbase + n0 + nt * 8 + tk * 2;
                float v0 = tf32r(gelu_f(d[mt][nt][h2 * 2]));
                float v1 = tf32r(gelu_f(d[mt][nt][h2 * 2 + 1]));
                *(float2*)&dst[o] = make_float2(v0, v1);
            }
        }
    }
}

// ---- dense 3x3 conv via mma.sync tf32, M=64, N=256 (full row), direct STG ----
template<int EPI>
__global__ void __launch_bounds__(256, 2)
conv3x3_mma(const float* __restrict__ in, const float* __restrict__ wimg,
            const float* __restrict__ aux1, const float* __restrict__ aux2,
            float* __restrict__ out)
{
    extern __shared__ float smem[];
    float* Wb = smem;               // 2 x 4608
    float* Xb = smem + 9216;        // 2 x 6336
    uint32_t sbW = smaddr(Wb), sbX = smaddr(Xb);

    int tid = threadIdx.x, wid = tid >> 5, lane = tid & 31;
    int gr = lane >> 2, tk = lane & 3;
    int y = blockIdx.x, b = blockIdx.y;
    const float* inb = in + (long)b * (64 * HW);

#define STAGE(C, BUF) do { \
        for (int idx = tid; idx < 1584; idx += 256) { \
            int c4 = idx % 66; \
            int ri = idx / 66; \
            int ic = ri & 7, row = ri >> 3; \
            int gx = -4 + c4 * 4; \
            int gy = y + row - 1; \
            bool ok = (gx >= 0) && (gx <= 252) && (gy >= 0) && (gy < 256); \
            const float* g_ = inb + (long)((C) * 8 + ic) * HW + gy * 256 + gx; \
            cpa16z(sbX + ((BUF) * 6336 + ri * 264 + c4 * 4) * 4, ok ? g_ : inb, ok); \
        } \
        const float4* s_ = (const float4*)(wimg + (long)(C) * 4608); \
        uint32_t d_ = sbW + (BUF) * 18432; \
        for (int t_ = tid; t_ < 1152; t_ += 256) cpa16(d_ + t_ * 16, s_ + t_); \
    } while (0)

    STAGE(0, 0);
    cpa_commit();
    STAGE(1, 1);
    cpa_commit();

    int mw = wid & 1, nw = wid >> 1;
    int m0 = mw * 32, n0 = nw * 64;
    float d[2][8][4];
#pragma unroll
    for (int mt = 0; mt < 2; ++mt)
#pragma unroll
        for (int nt = 0; nt < 8; ++nt)
#pragma unroll
            for (int q = 0; q < 4; ++q) d[mt][nt][q] = 0.f;

    for (int cc = 0; cc < 8; ++cc) {
        if (cc < 7) cpa_wait1(); else cpa_wait0();
        __syncthreads();
        const float* wb = Wb + (cc & 1) * 4608;
        const float* xb = Xb + (cc & 1) * 6336;
#pragma unroll
        for (int tap = 0; tap < 9; ++tap) {
            int ky = tap / 3, kx = tap - ky * 3;
            const float* xr = xb + (ky * 8 + tk) * 264 + n0 + gr + kx + 3;
            uint32_t bf[8][2];
#pragma unroll
            for (int nt = 0; nt < 8; ++nt) {
                bf[nt][0] = __float_as_uint(xr[nt * 8]);
                bf[nt][1] = __float_as_uint(xr[nt * 8 + 4 * 264]);
            }
#pragma unroll
            for (int mt = 0; mt < 2; ++mt) {
                const float* wp = wb + (tap * 64 + m0 + mt * 16) * 8;
                float2 aA = *(const float2*)(wp + gr * 8 + tk * 2);
                float2 aB = *(const float2*)(wp + (gr + 8) * 8 + tk * 2);
                uint32_t af[4];
                af[0] = __float_as_uint(aA.x);
                af[1] = __float_as_uint(aB.x);
                af[2] = __float_as_uint(aA.y);
                af[3] = __float_as_uint(aB.y);
#pragma unroll
                for (int nt = 0; nt < 8; ++nt)
                    mma_tf32(d[mt][nt], af, bf[nt]);
            }
        }
        __syncthreads();
        if (cc + 2 < 8) { STAGE(cc + 2, cc & 1); cpa_commit(); }
    }
#undef STAGE

    long obase = (long)(b * 64) * HW + y * 256;
#pragma unroll
    for (int mt = 0; mt < 2; ++mt) {
#pragma unroll
        for (int h2 = 0; h2 < 2; ++h2) {
            int mr = m0 + mt * 16 + gr + h2 * 8;
            long rowo = obase + (long)mr * HW;
#pragma unroll
            for (int nt = 0; nt < 8; ++nt) {
                long o = rowo + n0 + nt * 8 + tk * 2;
                float v0 = d[mt][nt][h2 * 2], v1 = d[mt][nt][h2 * 2 + 1];
                if (EPI == 1) {
                    v0 = tf32r(gelu_f(v0));
                    v1 = tf32r(gelu_f(v1));
                } else if (EPI == 2) {
                    float2 a1v = *(const float2*)&aux1[o];
                    float2 a2v = *(const float2*)&aux2[o];
                    v0 = tf32r(a1v.x * (1.f / (1.f + expf(-v0))) + a2v.x);
                    v1 = tf32r(a1v.y * (1.f / (1.f + expf(-v1))) + a2v.y);
                } else if (EPI == 3) {
                    float2 rv = *(const float2*)&aux1[o];
                    v0 += rv.x; v1 += rv.y;
                }
                *(float2*)&out[o] = make_float2(v0, v1);
            }
        }
    }
}

extern "C" void kernel_launch(void* const* d_in, const int* in_sizes, int n_in,
                              void* d_out, int out_size)
{
    const float* x       = (const float*)d_in[0];
    const float* ref     = (const float*)d_in[1];
    const float* ln1w    = (const float*)d_in[2];
    const float* ln1b    = (const float*)d_in[3];
    const float* ln2w    = (const float*)d_in[4];
    const float* ln2b    = (const float*)d_in[5];
    const float* ln3w    = (const float*)d_in[6];
    const float* ln3b    = (const float*)d_in[7];
    const float* w_kv    = (const float*)d_in[8];
    const float* w_kv_dw = (const float*)d_in[9];
    const float* w_q     = (const float*)d_in[10];
    const float* w_q_dw  = (const float*)d_in[11];
    const float* w_proj  = (const float*)d_in[12];
    const float* temp    = (const float*)d_in[13];
    const float* w_add1  = (const float*)d_in[14];
    const float* w_add2  = (const float*)d_in[15];
    const float* w_mul1  = (const float*)d_in[16];
    const float* w_fuse  = (const float*)d_in[17];
    float* out = (float*)d_out;

    float* pool = nullptr;
    cudaGetSymbolAddress((void**)&pool, g_pool);
    const long SZ = 16777216L, SZ2 = 33554432L;
    float* kv0  = pool;
    float* kv1  = pool + SZ2;
    float* bufA = pool + 2 * SZ2;
    float* bufB = bufA + SZ;
    float* bufC = bufB + SZ;
    float* bufD = bufC + SZ;
    float* bufE = bufD + SZ;
    float* x1   = bufE + SZ;
    float* Mb   = x1 + SZ;
    float* part = Mb + 16384;
    float* wI1m = part + 294912;     // 73728
    float* wIa2 = wI1m + 73728;      // 36864
    float* wIm  = wIa2 + 36864;      // 36864
    float* wIf  = wIm + 36864;       // 36864
    float* wIkv = wIf + 36864;       // 8192
    float* wIq  = wIkv + 8192;       // 4096

    cudaFuncSetAttribute(conv3x3_mma<0>, cudaFuncAttributeMaxDynamicSharedMemorySize, CSM3);
    cudaFuncSetAttribute(conv3x3_mma<2>, cudaFuncAttributeMaxDynamicSharedMemorySize, CSM3);
    cudaFuncSetAttribute(conv3x3_mma<3>, cudaFuncAttributeMaxDynamicSharedMemorySize, CSM3);
    cudaFuncSetAttribute(conv3x3_dual, cudaFuncAttributeMaxDynamicSharedMemorySize, CSM3D);
    cudaFuncSetAttribute(conv1x1_kv, cudaFuncAttributeMaxDynamicSharedMemorySize, CSM1KV);
    cudaFuncSetAttribute((conv1x1r_mma<true, false, false, false>), cudaFuncAttributeMaxDynamicSharedMemorySize, CSM1R);
    cudaFuncSetAttribute((conv1x1r_mma<false, true, true, true>), cudaFuncAttributeMaxDynamicSharedMemorySize, CSM1R);

    wprep_all<<<768, 256>>>(w_add1, w_add2, w_mul1, w_fuse, w_kv, w_q,
                            wI1m, wIa2, wIm, wIf, wIkv, wIq);

    // ---- Attention branch ----
    conv1x1_kv<<<dim3(512, 4), 256, CSM1KV>>>(ref, wIkv, ln1w, ln1b, kv0);
    conv1x1r_mma<true, false, false, false><<<dim3(256, 4), 256, CSM1R>>>(x, wIq, ln3w, ln3b, nullptr, bufC, nullptr, 64 * HW, 0);
    dw3x3_both<<<6144, 256>>>(kv0, w_kv_dw, kv1, bufC, w_q_dw, bufD);
    attn_stats_kernel<<<dim3(NCHUNK, 16), 256>>>(bufD, kv1, part);
    attn_finish_kernel<<<4, 256>>>(part, w_proj, temp, Mb);
    // x1 = x + M_b @ v ; bufA = tf32(ln2(x1)) fused
    conv1x1r_mma<false, true, true, true><<<dim3(256, 4), 256, CSM1R>>>(kv1, Mb, ln2w, ln2b, x, x1, bufA, 128 * HW, 64);

    // ---- SFM branch ----
    conv3x3_dual<<<dim3(512, 4), 256, CSM3D>>>(bufA, wI1m, bufB, bufD);                 // ga1 + gm1
    conv3x3_mma<0><<<dim3(256, 4), 256, CSM3>>>(bufB, wIa2, nullptr, nullptr, bufC);    // x_add
    conv3x3_mma<2><<<dim3(256, 4), 256, CSM3>>>(bufD, wIm, bufA, bufC, bufE);           // z
    conv3x3_mma<3><<<dim3(256, 4), 256, CSM3>>>(bufE, wIf, x1, nullptr, out);           // out
}